// round 1
// baseline (speedup 1.0000x reference)
#include <cuda_runtime.h>
#include <math.h>

// Problem constants: B=1, C=32, H=W=256, WS=16, OWS=24, NH=2, d=16
#define HWP   65536      // H*W pixels
#define NKEY  576        // OWS*OWS
#define NQ    256        // WS*WS
#define NWIN  256        // (H/WS)*(W/WS)

// ---------------- scratch (device globals; no runtime allocation) ----------------
__device__ float g_xhwc [HWP * 32];
__device__ float g_f    [HWP * 32];
__device__ float g_t2   [HWP * 16];
__device__ float g_t4   [HWP * 32];
__device__ float g_q    [HWP * 32];
__device__ float g_kv   [HWP * 64];
__device__ float g_att  [HWP * 32];
__device__ float g_o1   [HWP * 32];
__device__ float g_o2   [HWP * 32];
__device__ float g_biasT[2 * NKEY * NQ];
__device__ float g_stats[64];

// ---------------- helpers ----------------
__device__ __forceinline__ float warp_sum(float v) {
#pragma unroll
    for (int o = 16; o; o >>= 1) v += __shfl_xor_sync(0xffffffffu, v, o);
    return v;
}

__device__ __forceinline__ float gelu_tanh(float x) {
    float x3 = x * x * x;
    return 0.5f * x * (1.f + tanhf(0.7978845608028654f * (x + 0.044715f * x3)));
}

// ---------------- K0: CHW -> HWC transpose of x ----------------
__global__ void chw2hwc_kernel(const float* __restrict__ x, float* __restrict__ xh) {
    __shared__ float sm[32][33];
    int p0 = blockIdx.x * 32;
    int tx = threadIdx.x, ty = threadIdx.y;
    for (int c = ty; c < 32; c += 8) sm[c][tx] = x[c * HWP + p0 + tx];
    __syncthreads();
    for (int r = ty; r < 32; r += 8) xh[(p0 + r) * 32 + tx] = sm[tx][r];
}

// ---------------- K1: conv1(1->8,k3)+relu + conv2(8->16,k1)+relu ----------------
__global__ __launch_bounds__(256) void stem12_kernel(
    const float* __restrict__ depth,
    const float* __restrict__ cw1, const float* __restrict__ cb1,
    const float* __restrict__ cw2, const float* __restrict__ cb2,
    float* __restrict__ t2) {
    __shared__ float w1[72], b1s[8], w2[128], b2s[16];
    int tid = threadIdx.x;
    if (tid < 72)  w1[tid]  = cw1[tid];
    if (tid < 8)   b1s[tid] = cb1[tid];
    if (tid < 128) w2[tid]  = cw2[tid];
    if (tid < 16)  b2s[tid] = cb2[tid];
    __syncthreads();
    int p = blockIdx.x * 256 + tid;
    int y = p >> 8, x = p & 255;
    float d[9];
#pragma unroll
    for (int tap = 0; tap < 9; tap++) {
        int yy = y + tap / 3 - 1, xx = x + tap % 3 - 1;
        d[tap] = ((unsigned)yy < 256u && (unsigned)xx < 256u) ? depth[(yy << 8) + xx] : 0.f;
    }
    float c1[8];
#pragma unroll
    for (int o = 0; o < 8; o++) {
        float a = b1s[o];
#pragma unroll
        for (int tap = 0; tap < 9; tap++) a += d[tap] * w1[o * 9 + tap];
        c1[o] = fmaxf(a, 0.f);
    }
    float* dst = t2 + p * 16;
#pragma unroll
    for (int o2 = 0; o2 < 16; o2++) {
        float a = b2s[o2];
#pragma unroll
        for (int o = 0; o < 8; o++) a += c1[o] * w2[o2 * 8 + o];
        dst[o2] = fmaxf(a, 0.f);
    }
}

// ---------------- K2: conv3(16->16,k3)+relu + conv4(16->32,k1) ----------------
__global__ __launch_bounds__(256) void stem34_kernel(
    const float* __restrict__ t2,
    const float* __restrict__ cw3, const float* __restrict__ cb3,
    const float* __restrict__ cw4, const float* __restrict__ cb4,
    float* __restrict__ t4) {
    __shared__ float w3[2304];   // [oc][tap][ic]
    __shared__ float w4[512];
    __shared__ float b3[16], b4[32];
    int tid = threadIdx.x;
    for (int i = tid; i < 2304; i += 256) {
        int oc = i / 144, r = i - oc * 144, tap = r >> 4, ic = r & 15;
        w3[i] = cw3[oc * 144 + ic * 9 + tap];
    }
    for (int i = tid; i < 512; i += 256) w4[i] = cw4[i];
    if (tid < 16) b3[tid] = cb3[tid];
    if (tid < 32) b4[tid] = cb4[tid];
    __syncthreads();
    int p = blockIdx.x * 256 + tid;
    int y = p >> 8, x = p & 255;
    float acc[16];
#pragma unroll
    for (int i = 0; i < 16; i++) acc[i] = b3[i];
#pragma unroll 1
    for (int tap = 0; tap < 9; tap++) {
        int yy = y + tap / 3 - 1, xx = x + tap % 3 - 1;
        if ((unsigned)yy < 256u && (unsigned)xx < 256u) {
            const float4* src = (const float4*)(t2 + (((yy << 8) + xx) << 4));
            float4 i0 = src[0], i1 = src[1], i2 = src[2], i3 = src[3];
            float in[16] = {i0.x, i0.y, i0.z, i0.w, i1.x, i1.y, i1.z, i1.w,
                            i2.x, i2.y, i2.z, i2.w, i3.x, i3.y, i3.z, i3.w};
            const float* wt = &w3[tap * 16];
#pragma unroll
            for (int oc = 0; oc < 16; oc++) {
                const float* wr = wt + oc * 144;
#pragma unroll
                for (int ic = 0; ic < 16; ic++) acc[oc] += in[ic] * wr[ic];
            }
        }
    }
#pragma unroll
    for (int i = 0; i < 16; i++) acc[i] = fmaxf(acc[i], 0.f);
    float* dst = t4 + p * 32;
#pragma unroll
    for (int c4 = 0; c4 < 32; c4++) {
        float a = b4[c4];
#pragma unroll
        for (int oc = 0; oc < 16; oc++) a += acc[oc] * w4[c4 * 16 + oc];
        dst[c4] = a;
    }
}

// ---------------- K3: instance-norm stats (deterministic 2-pass) ----------------
__global__ __launch_bounds__(256) void inorm_stats_kernel(const float* __restrict__ t4,
                                                          float* __restrict__ stats) {
    int c = blockIdx.x;
    __shared__ float red[256];
    float s = 0.f;
    for (int p = threadIdx.x; p < HWP; p += 256) s += t4[p * 32 + c];
    red[threadIdx.x] = s;
    __syncthreads();
    for (int o = 128; o; o >>= 1) {
        if (threadIdx.x < o) red[threadIdx.x] += red[threadIdx.x + o];
        __syncthreads();
    }
    float mean = red[0] * (1.f / HWP);
    __syncthreads();
    float s2 = 0.f;
    for (int p = threadIdx.x; p < HWP; p += 256) {
        float dd = t4[p * 32 + c] - mean;
        s2 += dd * dd;
    }
    red[threadIdx.x] = s2;
    __syncthreads();
    for (int o = 128; o; o >>= 1) {
        if (threadIdx.x < o) red[threadIdx.x] += red[threadIdx.x + o];
        __syncthreads();
    }
    if (threadIdx.x == 0) {
        stats[c] = mean;
        stats[32 + c] = rsqrtf(red[0] * (1.f / HWP) + 1e-5f);
    }
}

// ---------------- K4: apply instance norm -> f (HWC) ----------------
__global__ void inorm_apply_kernel(const float* __restrict__ t4, const float* __restrict__ stats,
                                   const float* __restrict__ in_g, const float* __restrict__ in_b,
                                   float* __restrict__ f) {
    int idx = blockIdx.x * 256 + threadIdx.x;
    int c = idx & 31;
    f[idx] = (t4[idx] - stats[c]) * stats[32 + c] * in_g[c] + in_b[c];
}

// ---------------- K5: rel-pos bias, transposed to [head][key][query] ----------------
__global__ void build_bias_kernel(const int* __restrict__ rpi, const float* __restrict__ rpb,
                                  float* __restrict__ biasT) {
    int idx = blockIdx.x * 256 + threadIdx.x;   // 576*256
    int j = idx >> 8, qq = idx & 255;
    int r = rpi[qq * NKEY + j];
    biasT[j * NQ + qq] = rpb[r * 2 + 0];
    biasT[NKEY * NQ + j * NQ + qq] = rpb[r * 2 + 1];
}

// ---------------- K6: LN + q/kv projections (warp per pixel) ----------------
__global__ __launch_bounds__(256) void ln_qkv_kernel(
    const float* __restrict__ srcq, const float* __restrict__ srckv,
    const float* __restrict__ n1g, const float* __restrict__ n1b,
    const float* __restrict__ wq, const float* __restrict__ bq,
    const float* __restrict__ wkv, const float* __restrict__ bkv,
    float* __restrict__ qo, float* __restrict__ kvo) {
    __shared__ float s_wq[1024], s_wkv[2048];
    __shared__ float s_bq[32], s_bkv[64], s_g[32], s_b[32];
    int tid = threadIdx.x;
    for (int i = tid; i < 1024; i += 256) s_wq[i] = wq[i];
    for (int i = tid; i < 2048; i += 256) s_wkv[i] = wkv[i];
    if (tid < 32) { s_bq[tid] = bq[tid]; s_g[tid] = n1g[tid]; s_b[tid] = n1b[tid]; }
    if (tid < 64) s_bkv[tid] = bkv[tid];
    __syncthreads();
    int lane = tid & 31;
    int p = blockIdx.x * 8 + (tid >> 5);
    {
        float xv = srcq[p * 32 + lane];
        float mean = warp_sum(xv) * (1.f / 32.f);
        float dv = xv - mean;
        float var = warp_sum(dv * dv) * (1.f / 32.f);
        float xn = dv * rsqrtf(var + 1e-5f) * s_g[lane] + s_b[lane];
        float acc = s_bq[lane];
#pragma unroll
        for (int i = 0; i < 32; i++)
            acc += __shfl_sync(0xffffffffu, xn, i) * s_wq[i * 32 + lane];
        qo[p * 32 + lane] = acc;
    }
    {
        float xv = srckv[p * 32 + lane];
        float mean = warp_sum(xv) * (1.f / 32.f);
        float dv = xv - mean;
        float var = warp_sum(dv * dv) * (1.f / 32.f);
        float xn = dv * rsqrtf(var + 1e-5f) * s_g[lane] + s_b[lane];
        float a0 = s_bkv[lane], a1 = s_bkv[lane + 32];
#pragma unroll
        for (int i = 0; i < 32; i++) {
            float xi = __shfl_sync(0xffffffffu, xn, i);
            a0 += xi * s_wkv[i * 64 + lane];
            a1 += xi * s_wkv[i * 64 + lane + 32];
        }
        kvo[p * 64 + lane] = a0;
        kvo[p * 64 + 32 + lane] = a1;
    }
}

// ---------------- K7: windowed cross-attention (one block per window*head) ----------------
__global__ __launch_bounds__(256) void attn_kernel(
    const float* __restrict__ q, const float* __restrict__ kv,
    const float* __restrict__ biasT, float* __restrict__ out) {
    extern __shared__ float sm[];
    float* ksm = sm;                 // [576][16]
    float* vsm = sm + NKEY * 16;     // [576][16]
    int win = blockIdx.x, head = blockIdx.y;
    int wy = win >> 4, wx = win & 15;
    int t = threadIdx.x;

    for (int j = t; j < NKEY; j += 256) {
        int jy = j / 24, jx = j - jy * 24;
        int yy = (wy << 4) - 4 + jy, xx = (wx << 4) - 4 + jx;
        float4 k0, k1, k2, k3, v0, v1, v2, v3;
        if ((unsigned)yy < 256u && (unsigned)xx < 256u) {
            const float* base = kv + ((size_t)((yy << 8) + xx) << 6);
            const float4* kp = (const float4*)(base + (head << 4));
            k0 = kp[0]; k1 = kp[1]; k2 = kp[2]; k3 = kp[3];
            const float4* vp = (const float4*)(base + 32 + (head << 4));
            v0 = vp[0]; v1 = vp[1]; v2 = vp[2]; v3 = vp[3];
        } else {
            k0 = k1 = k2 = k3 = make_float4(0.f, 0.f, 0.f, 0.f);
            v0 = v1 = v2 = v3 = k0;
        }
        float4* kd = (float4*)(ksm + j * 16);
        kd[0] = k0; kd[1] = k1; kd[2] = k2; kd[3] = k3;
        float4* vd = (float4*)(vsm + j * 16);
        vd[0] = v0; vd[1] = v1; vd[2] = v2; vd[3] = v3;
    }

    int qy = (wy << 4) + (t >> 4), qx = (wx << 4) + (t & 15);
    const float4* qp = (const float4*)(q + ((size_t)((qy << 8) + qx) << 5) + (head << 4));
    float4 q0 = qp[0], q1 = qp[1], q2 = qp[2], q3 = qp[3];
    float qr[16] = {q0.x * 0.25f, q0.y * 0.25f, q0.z * 0.25f, q0.w * 0.25f,
                    q1.x * 0.25f, q1.y * 0.25f, q1.z * 0.25f, q1.w * 0.25f,
                    q2.x * 0.25f, q2.y * 0.25f, q2.z * 0.25f, q2.w * 0.25f,
                    q3.x * 0.25f, q3.y * 0.25f, q3.z * 0.25f, q3.w * 0.25f};
    __syncthreads();

    const float* brow = biasT + head * (NKEY * NQ) + t;
    float m = -1e30f, l = 0.f;
    float o[16];
#pragma unroll
    for (int dd = 0; dd < 16; dd++) o[dd] = 0.f;

    for (int j = 0; j < NKEY; j++) {
        const float4* kk = (const float4*)(ksm + j * 16);
        float4 a = kk[0], b = kk[1], c = kk[2], d = kk[3];
        float s0 = qr[0] * a.x + qr[1] * a.y + qr[2] * a.z + qr[3] * a.w;
        float s1 = qr[4] * b.x + qr[5] * b.y + qr[6] * b.z + qr[7] * b.w;
        float s2 = qr[8] * c.x + qr[9] * c.y + qr[10] * c.z + qr[11] * c.w;
        float s3 = qr[12] * d.x + qr[13] * d.y + qr[14] * d.z + qr[15] * d.w;
        float s = brow[j << 8] + ((s0 + s1) + (s2 + s3));
        float pp;
        if (s > m) {
            float sc = __expf(m - s);
#pragma unroll
            for (int dd = 0; dd < 16; dd++) o[dd] *= sc;
            l *= sc;
            m = s;
            pp = 1.f;
        } else {
            pp = __expf(s - m);
        }
        l += pp;
        const float4* vv = (const float4*)(vsm + j * 16);
        float4 va = vv[0], vb = vv[1], vc = vv[2], vd = vv[3];
        o[0]  += pp * va.x; o[1]  += pp * va.y; o[2]  += pp * va.z; o[3]  += pp * va.w;
        o[4]  += pp * vb.x; o[5]  += pp * vb.y; o[6]  += pp * vb.z; o[7]  += pp * vb.w;
        o[8]  += pp * vc.x; o[9]  += pp * vc.y; o[10] += pp * vc.z; o[11] += pp * vc.w;
        o[12] += pp * vd.x; o[13] += pp * vd.y; o[14] += pp * vd.z; o[15] += pp * vd.w;
    }
    float inv = 1.f / l;
    float4* op = (float4*)(out + ((size_t)((qy << 8) + qx) << 5) + (head << 4));
    op[0] = make_float4(o[0] * inv, o[1] * inv, o[2] * inv, o[3] * inv);
    op[1] = make_float4(o[4] * inv, o[5] * inv, o[6] * inv, o[7] * inv);
    op[2] = make_float4(o[8] * inv, o[9] * inv, o[10] * inv, o[11] * inv);
    op[3] = make_float4(o[12] * inv, o[13] * inv, o[14] * inv, o[15] * inv);
}

// ---------------- K8: out-proj + shortcut + LN + MLP(gelu) residual ----------------
__global__ __launch_bounds__(256) void proj_mlp_kernel(
    const float* __restrict__ att, const float* __restrict__ sc,
    const float* __restrict__ wp, const float* __restrict__ bp,
    const float* __restrict__ n2g, const float* __restrict__ n2b,
    const float* __restrict__ mw1, const float* __restrict__ mb1,
    const float* __restrict__ mw2, const float* __restrict__ mb2,
    float* __restrict__ out) {
    __shared__ float s_wp[1024], s_mw1[2048], s_mw2[2048];
    __shared__ float s_bp[32], s_mb1[64], s_mb2[32], s_g[32], s_b[32];
    int tid = threadIdx.x;
    for (int i = tid; i < 1024; i += 256) s_wp[i] = wp[i];
    for (int i = tid; i < 2048; i += 256) { s_mw1[i] = mw1[i]; s_mw2[i] = mw2[i]; }
    if (tid < 32) { s_bp[tid] = bp[tid]; s_mb2[tid] = mb2[tid]; s_g[tid] = n2g[tid]; s_b[tid] = n2b[tid]; }
    if (tid < 64) s_mb1[tid] = mb1[tid];
    __syncthreads();
    int lane = tid & 31;
    int p = blockIdx.x * 8 + (tid >> 5);

    float a = att[p * 32 + lane];
    float y = s_bp[lane];
#pragma unroll
    for (int i = 0; i < 32; i++)
        y += __shfl_sync(0xffffffffu, a, i) * s_wp[i * 32 + lane];
    y += sc[p * 32 + lane];

    float mean = warp_sum(y) * (1.f / 32.f);
    float dv = y - mean;
    float var = warp_sum(dv * dv) * (1.f / 32.f);
    float yn = dv * rsqrtf(var + 1e-5f) * s_g[lane] + s_b[lane];

    float h0 = s_mb1[lane], h1 = s_mb1[lane + 32];
#pragma unroll
    for (int i = 0; i < 32; i++) {
        float xi = __shfl_sync(0xffffffffu, yn, i);
        h0 += xi * s_mw1[i * 64 + lane];
        h1 += xi * s_mw1[i * 64 + lane + 32];
    }
    h0 = gelu_tanh(h0);
    h1 = gelu_tanh(h1);
    float r = s_mb2[lane];
#pragma unroll
    for (int i = 0; i < 32; i++) {
        float g0 = __shfl_sync(0xffffffffu, h0, i);
        float g1 = __shfl_sync(0xffffffffu, h1, i);
        r += g0 * s_mw2[i * 32 + lane] + g1 * s_mw2[(i + 32) * 32 + lane];
    }
    out[p * 32 + lane] = y + r;
}

// ---------------- K9: final sum, HWC -> CHW ----------------
__global__ void final_kernel(const float* __restrict__ o1, const float* __restrict__ o2,
                             const float* __restrict__ x, float* __restrict__ out) {
    __shared__ float sm[32][33];
    int p0 = blockIdx.x * 32;
    int tx = threadIdx.x, ty = threadIdx.y;
    for (int r = ty; r < 32; r += 8) {
        int p = p0 + r;
        sm[r][tx] = o1[p * 32 + tx] + o2[p * 32 + tx];
    }
    __syncthreads();
    for (int c = ty; c < 32; c += 8)
        out[c * HWP + p0 + tx] = sm[tx][c] + x[c * HWP + p0 + tx];
}

// ---------------- launch ----------------
extern "C" void kernel_launch(void* const* d_in, const int* in_sizes, int n_in,
                              void* d_out, int out_size) {
    const float* x    = (const float*)d_in[0];
    const float* dep  = (const float*)d_in[1];
    const int*   rpi  = (const int*)  d_in[2];
    const float* cw1  = (const float*)d_in[3];
    const float* cb1  = (const float*)d_in[4];
    const float* cw2  = (const float*)d_in[5];
    const float* cb2  = (const float*)d_in[6];
    const float* cw3  = (const float*)d_in[7];
    const float* cb3  = (const float*)d_in[8];
    const float* cw4  = (const float*)d_in[9];
    const float* cb4  = (const float*)d_in[10];
    const float* in_g = (const float*)d_in[11];
    const float* in_b = (const float*)d_in[12];
    const float* n1g  = (const float*)d_in[13];
    const float* n1b  = (const float*)d_in[14];
    const float* wq   = (const float*)d_in[15];
    const float* bq   = (const float*)d_in[16];
    const float* wkv  = (const float*)d_in[17];
    const float* bkv  = (const float*)d_in[18];
    const float* rpb  = (const float*)d_in[19];
    const float* wp   = (const float*)d_in[20];
    const float* bp   = (const float*)d_in[21];
    const float* n2g  = (const float*)d_in[22];
    const float* n2b  = (const float*)d_in[23];
    const float* mw1  = (const float*)d_in[24];
    const float* mb1  = (const float*)d_in[25];
    const float* mw2  = (const float*)d_in[26];
    const float* mb2  = (const float*)d_in[27];
    float* out = (float*)d_out;

    void *p_xhwc, *p_f, *p_t2, *p_t4, *p_q, *p_kv, *p_att, *p_o1, *p_o2, *p_bias, *p_stats;
    cudaGetSymbolAddress(&p_xhwc, g_xhwc);
    cudaGetSymbolAddress(&p_f, g_f);
    cudaGetSymbolAddress(&p_t2, g_t2);
    cudaGetSymbolAddress(&p_t4, g_t4);
    cudaGetSymbolAddress(&p_q, g_q);
    cudaGetSymbolAddress(&p_kv, g_kv);
    cudaGetSymbolAddress(&p_att, g_att);
    cudaGetSymbolAddress(&p_o1, g_o1);
    cudaGetSymbolAddress(&p_o2, g_o2);
    cudaGetSymbolAddress(&p_bias, g_biasT);
    cudaGetSymbolAddress(&p_stats, g_stats);

    cudaFuncSetAttribute(attn_kernel, cudaFuncAttributeMaxDynamicSharedMemorySize,
                         NKEY * 16 * 2 * (int)sizeof(float));

    const int smem_attn = NKEY * 16 * 2 * (int)sizeof(float);  // 73728

    chw2hwc_kernel<<<2048, dim3(32, 8)>>>(x, (float*)p_xhwc);
    stem12_kernel<<<256, 256>>>(dep, cw1, cb1, cw2, cb2, (float*)p_t2);
    stem34_kernel<<<256, 256>>>((float*)p_t2, cw3, cb3, cw4, cb4, (float*)p_t4);
    inorm_stats_kernel<<<32, 256>>>((float*)p_t4, (float*)p_stats);
    inorm_apply_kernel<<<8192, 256>>>((float*)p_t4, (float*)p_stats, in_g, in_b, (float*)p_f);
    build_bias_kernel<<<576, 256>>>(rpi, rpb, (float*)p_bias);

    // OCAB 1: q from x, kv from f
    ln_qkv_kernel<<<8192, 256>>>((float*)p_xhwc, (float*)p_f, n1g, n1b, wq, bq, wkv, bkv,
                                 (float*)p_q, (float*)p_kv);
    attn_kernel<<<dim3(NWIN, 2), 256, smem_attn>>>((float*)p_q, (float*)p_kv,
                                                   (float*)p_bias, (float*)p_att);
    proj_mlp_kernel<<<8192, 256>>>((float*)p_att, (float*)p_xhwc, wp, bp, n2g, n2b,
                                   mw1, mb1, mw2, mb2, (float*)p_o1);

    // OCAB 2: q from f, kv from x
    ln_qkv_kernel<<<8192, 256>>>((float*)p_f, (float*)p_xhwc, n1g, n1b, wq, bq, wkv, bkv,
                                 (float*)p_q, (float*)p_kv);
    attn_kernel<<<dim3(NWIN, 2), 256, smem_attn>>>((float*)p_q, (float*)p_kv,
                                                   (float*)p_bias, (float*)p_att);
    proj_mlp_kernel<<<8192, 256>>>((float*)p_att, (float*)p_f, wp, bp, n2g, n2b,
                                   mw1, mb1, mw2, mb2, (float*)p_o2);

    final_kernel<<<2048, dim3(32, 8)>>>((float*)p_o1, (float*)p_o2, x, out);
}

// round 2
// speedup vs baseline: 1.1329x; 1.1329x over previous
#include <cuda_runtime.h>
#include <math.h>

// Problem constants: B=1, C=32, H=W=256, WS=16, OWS=24, NH=2, d=16
#define HWP   65536
#define NKEY  576
#define NQ    256
#define NWIN  256

typedef unsigned long long u64;

// ---------------- scratch (device globals; no runtime allocation) ----------------
__device__ float  g_xhwc [HWP * 32];
__device__ float  g_f    [HWP * 32];
__device__ float  g_t2   [HWP * 16];
__device__ float  g_t4   [HWP * 32];
__device__ float  g_q    [HWP * 32];
__device__ float  g_kv   [HWP * 64];
__device__ float  g_att  [HWP * 32];
__device__ float  g_o1   [HWP * 32];
__device__ float  g_o2   [HWP * 32];
__device__ float  g_biasT[2 * NKEY * NQ];
__device__ float  g_stats[64];
__device__ double g_part [1024 * 64];

// ---------------- packed f32x2 helpers ----------------
__device__ __forceinline__ u64 f2pack(float lo, float hi) {
    u64 r; asm("mov.b64 %0, {%1, %2};" : "=l"(r) : "f"(lo), "f"(hi)); return r;
}
__device__ __forceinline__ float2 f2unpack(u64 v) {
    float2 f; asm("mov.b64 {%0, %1}, %2;" : "=f"(f.x), "=f"(f.y) : "l"(v)); return f;
}
__device__ __forceinline__ u64 f2fma(u64 a, u64 b, u64 c) {
    u64 d; asm("fma.rn.f32x2 %0, %1, %2, %3;" : "=l"(d) : "l"(a), "l"(b), "l"(c)); return d;
}
__device__ __forceinline__ u64 f2mul(u64 a, u64 b) {
    u64 d; asm("mul.rn.f32x2 %0, %1, %2;" : "=l"(d) : "l"(a), "l"(b)); return d;
}
__device__ __forceinline__ u64 f2add(u64 a, u64 b) {
    u64 d; asm("add.rn.f32x2 %0, %1, %2;" : "=l"(d) : "l"(a), "l"(b)); return d;
}

__device__ __forceinline__ float warp_sum(float v) {
#pragma unroll
    for (int o = 16; o; o >>= 1) v += __shfl_xor_sync(0xffffffffu, v, o);
    return v;
}

__device__ __forceinline__ float gelu_tanh(float x) {
    float x3 = x * x * x;
    return 0.5f * x * (1.f + tanhf(0.7978845608028654f * (x + 0.044715f * x3)));
}

// ---------------- K0: CHW -> HWC transpose of x ----------------
__global__ void chw2hwc_kernel(const float* __restrict__ x, float* __restrict__ xh) {
    __shared__ float sm[32][33];
    int p0 = blockIdx.x * 32;
    int tx = threadIdx.x, ty = threadIdx.y;
    for (int c = ty; c < 32; c += 8) sm[c][tx] = x[c * HWP + p0 + tx];
    __syncthreads();
    for (int r = ty; r < 32; r += 8) xh[(p0 + r) * 32 + tx] = sm[tx][r];
}

// ---------------- K1: conv1(1->8,k3)+relu + conv2(8->16,k1)+relu ----------------
__global__ __launch_bounds__(256) void stem12_kernel(
    const float* __restrict__ depth,
    const float* __restrict__ cw1, const float* __restrict__ cb1,
    const float* __restrict__ cw2, const float* __restrict__ cb2,
    float* __restrict__ t2) {
    __shared__ float w1[72], b1s[8], w2[128], b2s[16];
    int tid = threadIdx.x;
    if (tid < 72)  w1[tid]  = cw1[tid];
    if (tid < 8)   b1s[tid] = cb1[tid];
    if (tid < 128) w2[tid]  = cw2[tid];
    if (tid < 16)  b2s[tid] = cb2[tid];
    __syncthreads();
    int p = blockIdx.x * 256 + tid;
    int y = p >> 8, x = p & 255;
    float d[9];
#pragma unroll
    for (int tap = 0; tap < 9; tap++) {
        int yy = y + tap / 3 - 1, xx = x + tap % 3 - 1;
        d[tap] = ((unsigned)yy < 256u && (unsigned)xx < 256u) ? depth[(yy << 8) + xx] : 0.f;
    }
    float c1[8];
#pragma unroll
    for (int o = 0; o < 8; o++) {
        float a = b1s[o];
#pragma unroll
        for (int tap = 0; tap < 9; tap++) a += d[tap] * w1[o * 9 + tap];
        c1[o] = fmaxf(a, 0.f);
    }
    float* dst = t2 + p * 16;
#pragma unroll
    for (int o2 = 0; o2 < 16; o2++) {
        float a = b2s[o2];
#pragma unroll
        for (int o = 0; o < 8; o++) a += c1[o] * w2[o2 * 8 + o];
        dst[o2] = fmaxf(a, 0.f);
    }
}

// ---------------- K2: conv3(16->16,k3)+relu + conv4(16->32,k1), packed f32x2 ----------------
__global__ __launch_bounds__(256) void stem34_kernel(
    const float* __restrict__ t2,
    const float* __restrict__ cw3, const float* __restrict__ cb3,
    const float* __restrict__ cw4, const float* __restrict__ cb4,
    float* __restrict__ t4) {
    __shared__ u64 w3p[1152];   // [oc][tap][ic2]
    __shared__ u64 w4p[256];    // [c4][oc2]
    __shared__ float b3[16], b4[32];
    int tid = threadIdx.x;
    for (int i = tid; i < 1152; i += 256) {
        int oc = i / 72, r = i - oc * 72, tap = r >> 3, ic2 = r & 7;
        w3p[i] = f2pack(cw3[oc * 144 + (2 * ic2) * 9 + tap],
                        cw3[oc * 144 + (2 * ic2 + 1) * 9 + tap]);
    }
    if (tid < 256) {
        int c4 = tid >> 3, o2 = tid & 7;
        w4p[tid] = f2pack(cw4[c4 * 16 + 2 * o2], cw4[c4 * 16 + 2 * o2 + 1]);
    }
    if (tid < 16) b3[tid] = cb3[tid];
    if (tid < 32) b4[tid] = cb4[tid];
    __syncthreads();
    int p = blockIdx.x * 256 + tid;
    int y = p >> 8, x = p & 255;
    u64 acc2[16];
#pragma unroll
    for (int i = 0; i < 16; i++) acc2[i] = 0ULL;
#pragma unroll 1
    for (int tap = 0; tap < 9; tap++) {
        int yy = y + tap / 3 - 1, xx = x + tap % 3 - 1;
        if ((unsigned)yy < 256u && (unsigned)xx < 256u) {
            const float4* src = (const float4*)(t2 + (((yy << 8) + xx) << 4));
            float4 i0 = src[0], i1 = src[1], i2v = src[2], i3 = src[3];
            u64 in2[8] = {f2pack(i0.x, i0.y), f2pack(i0.z, i0.w),
                          f2pack(i1.x, i1.y), f2pack(i1.z, i1.w),
                          f2pack(i2v.x, i2v.y), f2pack(i2v.z, i2v.w),
                          f2pack(i3.x, i3.y), f2pack(i3.z, i3.w)};
            const u64* wt = &w3p[tap * 8];
#pragma unroll
            for (int oc = 0; oc < 16; oc++) {
                const u64* wr = wt + oc * 72;
#pragma unroll
                for (int k = 0; k < 8; k++) acc2[oc] = f2fma(in2[k], wr[k], acc2[oc]);
            }
        }
    }
    float c3[16];
#pragma unroll
    for (int oc = 0; oc < 16; oc++) {
        float2 f = f2unpack(acc2[oc]);
        c3[oc] = fmaxf(f.x + f.y + b3[oc], 0.f);
    }
    u64 a2[8];
#pragma unroll
    for (int o2 = 0; o2 < 8; o2++) a2[o2] = f2pack(c3[2 * o2], c3[2 * o2 + 1]);
    float* dst = t4 + (size_t)p * 32;
#pragma unroll
    for (int c4 = 0; c4 < 32; c4++) {
        u64 r = 0ULL;
#pragma unroll
        for (int o2 = 0; o2 < 8; o2++) r = f2fma(a2[o2], w4p[c4 * 8 + o2], r);
        float2 f = f2unpack(r);
        dst[c4] = f.x + f.y + b4[c4];
    }
}

// ---------------- K3a: instance-norm partial sums (1024 blocks, fp64 accum) ----------------
__global__ __launch_bounds__(256) void inorm_part_kernel(const float* __restrict__ t4,
                                                         double* __restrict__ part) {
    int tid = threadIdx.x;
    size_t base = (size_t)blockIdx.x * 2048;   // 64 pixels * 32 ch
    double s = 0.0, s2 = 0.0;
#pragma unroll
    for (int it = 0; it < 8; it++) {
        float v = t4[base + it * 256 + tid];
        double dv = (double)v;
        s += dv; s2 += dv * dv;
    }
    __shared__ double sa[256], sb[256];
    sa[tid] = s; sb[tid] = s2;
    __syncthreads();
    if (tid < 32) {
        double a = 0.0, b = 0.0;
#pragma unroll
        for (int k = 0; k < 8; k++) { a += sa[k * 32 + tid]; b += sb[k * 32 + tid]; }
        part[blockIdx.x * 64 + tid] = a;
        part[blockIdx.x * 64 + 32 + tid] = b;
    }
}

// ---------------- K3b: instance-norm final reduce ----------------
__global__ __launch_bounds__(256) void inorm_final_kernel(const double* __restrict__ part,
                                                          float* __restrict__ stats) {
    int c = threadIdx.x & 31, g = threadIdx.x >> 5;
    double a = 0.0, b = 0.0;
    for (int blk = g; blk < 1024; blk += 8) {
        a += part[blk * 64 + c];
        b += part[blk * 64 + 32 + c];
    }
    __shared__ double sa[8][32], sb[8][32];
    sa[g][c] = a; sb[g][c] = b;
    __syncthreads();
    if (threadIdx.x < 32) {
        double s = 0.0, s2 = 0.0;
#pragma unroll
        for (int k = 0; k < 8; k++) { s += sa[k][threadIdx.x]; s2 += sb[k][threadIdx.x]; }
        double mean = s / (double)HWP;
        double var = s2 / (double)HWP - mean * mean;
        stats[threadIdx.x] = (float)mean;
        stats[32 + threadIdx.x] = rsqrtf((float)var + 1e-5f);
    }
}

// ---------------- K4: apply instance norm -> f (HWC) ----------------
__global__ void inorm_apply_kernel(const float* __restrict__ t4, const float* __restrict__ stats,
                                   const float* __restrict__ in_g, const float* __restrict__ in_b,
                                   float* __restrict__ f) {
    int idx = blockIdx.x * 256 + threadIdx.x;
    int c = idx & 31;
    f[idx] = (t4[idx] - stats[c]) * stats[32 + c] * in_g[c] + in_b[c];
}

// ---------------- K5: rel-pos bias, transposed to [head][key][query] ----------------
__global__ void build_bias_kernel(const int* __restrict__ rpi, const float* __restrict__ rpb,
                                  float* __restrict__ biasT) {
    int idx = blockIdx.x * 256 + threadIdx.x;   // 576*256
    int j = idx >> 8, qq = idx & 255;
    int r = rpi[qq * NKEY + j];
    biasT[j * NQ + qq] = rpb[r * 2 + 0];
    biasT[NKEY * NQ + j * NQ + qq] = rpb[r * 2 + 1];
}

// ---------------- K6: LN + q/kv projections (packed f32x2, smem broadcast) ----------------
__global__ __launch_bounds__(256) void ln_qkv_kernel(
    const float* __restrict__ srcq, const float* __restrict__ srckv,
    const float* __restrict__ n1g, const float* __restrict__ n1b,
    const float* __restrict__ wq, const float* __restrict__ bq,
    const float* __restrict__ wkv, const float* __restrict__ bkv,
    float* __restrict__ qo, float* __restrict__ kvo) {
    __shared__ u64 s_wq2[512], s_wk2[512], s_wv2[512];
    __shared__ float s_bq[32], s_bkv[64], s_g[32], s_b[32];
    __shared__ __align__(16) float s_act[8][32];
    int tid = threadIdx.x;
    for (int idx = tid; idx < 512; idx += 256) {
        int i2 = idx >> 5, l = idx & 31;
        s_wq2[idx] = f2pack(wq[(2 * i2) * 32 + l], wq[(2 * i2 + 1) * 32 + l]);
        s_wk2[idx] = f2pack(wkv[(2 * i2) * 64 + l], wkv[(2 * i2 + 1) * 64 + l]);
        s_wv2[idx] = f2pack(wkv[(2 * i2) * 64 + 32 + l], wkv[(2 * i2 + 1) * 64 + 32 + l]);
    }
    if (tid < 32) { s_bq[tid] = bq[tid]; s_g[tid] = n1g[tid]; s_b[tid] = n1b[tid]; }
    if (tid < 64) s_bkv[tid] = bkv[tid];
    __syncthreads();
    int lane = tid & 31, w = tid >> 5;
    int p = blockIdx.x * 8 + w;
    // q pass
    {
        float xv = srcq[p * 32 + lane];
        float mean = warp_sum(xv) * (1.f / 32.f);
        float dv = xv - mean;
        float var = warp_sum(dv * dv) * (1.f / 32.f);
        float xn = dv * rsqrtf(var + 1e-5f) * s_g[lane] + s_b[lane];
        s_act[w][lane] = xn;
        __syncwarp();
        u64 acc = 0ULL;
#pragma unroll
        for (int i2 = 0; i2 < 16; i2++) {
            u64 x2 = *(const u64*)&s_act[w][2 * i2];
            acc = f2fma(x2, s_wq2[i2 * 32 + lane], acc);
        }
        float2 ff = f2unpack(acc);
        qo[p * 32 + lane] = ff.x + ff.y + s_bq[lane];
        __syncwarp();
    }
    // kv pass
    {
        float xv = srckv[p * 32 + lane];
        float mean = warp_sum(xv) * (1.f / 32.f);
        float dv = xv - mean;
        float var = warp_sum(dv * dv) * (1.f / 32.f);
        float xn = dv * rsqrtf(var + 1e-5f) * s_g[lane] + s_b[lane];
        s_act[w][lane] = xn;
        __syncwarp();
        u64 ak = 0ULL, av = 0ULL;
#pragma unroll
        for (int i2 = 0; i2 < 16; i2++) {
            u64 x2 = *(const u64*)&s_act[w][2 * i2];
            ak = f2fma(x2, s_wk2[i2 * 32 + lane], ak);
            av = f2fma(x2, s_wv2[i2 * 32 + lane], av);
        }
        float2 fk = f2unpack(ak), fv = f2unpack(av);
        kvo[p * 64 + lane] = fk.x + fk.y + s_bkv[lane];
        kvo[p * 64 + 32 + lane] = fv.x + fv.y + s_bkv[lane + 32];
    }
}

// ---------------- K7: windowed cross-attention (packed f32x2, online softmax) ----------------
__global__ __launch_bounds__(256) void attn_kernel(
    const float* __restrict__ q, const float* __restrict__ kv,
    const float* __restrict__ biasT, float* __restrict__ out) {
    extern __shared__ float sm[];
    float* ksm = sm;                 // [576][16]
    float* vsm = sm + NKEY * 16;     // [576][16]
    int win = blockIdx.x, head = blockIdx.y;
    int wy = win >> 4, wx = win & 15;
    int t = threadIdx.x;

    for (int j = t; j < NKEY; j += 256) {
        int jy = j / 24, jx = j - jy * 24;
        int yy = (wy << 4) - 4 + jy, xx = (wx << 4) - 4 + jx;
        float4 k0, k1, k2, k3, v0, v1, v2, v3;
        if ((unsigned)yy < 256u && (unsigned)xx < 256u) {
            const float* base = kv + ((size_t)((yy << 8) + xx) << 6);
            const float4* kp = (const float4*)(base + (head << 4));
            k0 = kp[0]; k1 = kp[1]; k2 = kp[2]; k3 = kp[3];
            const float4* vp = (const float4*)(base + 32 + (head << 4));
            v0 = vp[0]; v1 = vp[1]; v2 = vp[2]; v3 = vp[3];
        } else {
            k0 = k1 = k2 = k3 = make_float4(0.f, 0.f, 0.f, 0.f);
            v0 = v1 = v2 = v3 = k0;
        }
        float4* kd = (float4*)(ksm + j * 16);
        kd[0] = k0; kd[1] = k1; kd[2] = k2; kd[3] = k3;
        float4* vd = (float4*)(vsm + j * 16);
        vd[0] = v0; vd[1] = v1; vd[2] = v2; vd[3] = v3;
    }

    int qy = (wy << 4) + (t >> 4), qx = (wx << 4) + (t & 15);
    const float4* qp = (const float4*)(q + ((size_t)((qy << 8) + qx) << 5) + (head << 4));
    float4 q0 = qp[0], q1 = qp[1], q2 = qp[2], q3 = qp[3];
    u64 qp8[8] = {f2pack(q0.x * 0.25f, q0.y * 0.25f), f2pack(q0.z * 0.25f, q0.w * 0.25f),
                  f2pack(q1.x * 0.25f, q1.y * 0.25f), f2pack(q1.z * 0.25f, q1.w * 0.25f),
                  f2pack(q2.x * 0.25f, q2.y * 0.25f), f2pack(q2.z * 0.25f, q2.w * 0.25f),
                  f2pack(q3.x * 0.25f, q3.y * 0.25f), f2pack(q3.z * 0.25f, q3.w * 0.25f)};
    __syncthreads();

    const float* brow = biasT + head * (NKEY * NQ) + t;
    float m = -1e30f, l = 0.f;
    u64 o2[8];
#pragma unroll
    for (int dd = 0; dd < 8; dd++) o2[dd] = 0ULL;

#pragma unroll 2
    for (int j = 0; j < NKEY; j++) {
        const ulonglong2* kk = (const ulonglong2*)(ksm + j * 16);
        ulonglong2 kA = kk[0], kB = kk[1], kC = kk[2], kD = kk[3];
        u64 a0 = f2mul(qp8[0], kA.x);
        u64 a1 = f2mul(qp8[1], kA.y);
        a0 = f2fma(qp8[2], kB.x, a0); a1 = f2fma(qp8[3], kB.y, a1);
        a0 = f2fma(qp8[4], kC.x, a0); a1 = f2fma(qp8[5], kC.y, a1);
        a0 = f2fma(qp8[6], kD.x, a0); a1 = f2fma(qp8[7], kD.y, a1);
        a0 = f2add(a0, a1);
        float2 fs = f2unpack(a0);
        float s = brow[j << 8] + fs.x + fs.y;
        float pp;
        if (s > m) {
            float sc = __expf(m - s);
            u64 sc2 = f2pack(sc, sc);
#pragma unroll
            for (int dd = 0; dd < 8; dd++) o2[dd] = f2mul(sc2, o2[dd]);
            l *= sc; m = s; pp = 1.f;
        } else {
            pp = __expf(s - m);
        }
        l += pp;
        const ulonglong2* vv = (const ulonglong2*)(vsm + j * 16);
        ulonglong2 vA = vv[0], vB = vv[1], vC = vv[2], vD = vv[3];
        u64 p2 = f2pack(pp, pp);
        o2[0] = f2fma(p2, vA.x, o2[0]); o2[1] = f2fma(p2, vA.y, o2[1]);
        o2[2] = f2fma(p2, vB.x, o2[2]); o2[3] = f2fma(p2, vB.y, o2[3]);
        o2[4] = f2fma(p2, vC.x, o2[4]); o2[5] = f2fma(p2, vC.y, o2[5]);
        o2[6] = f2fma(p2, vD.x, o2[6]); o2[7] = f2fma(p2, vD.y, o2[7]);
    }
    float inv = 1.f / l;
    float4* op = (float4*)(out + ((size_t)((qy << 8) + qx) << 5) + (head << 4));
#pragma unroll
    for (int g = 0; g < 4; g++) {
        float2 e0 = f2unpack(o2[2 * g]);
        float2 e1 = f2unpack(o2[2 * g + 1]);
        op[g] = make_float4(e0.x * inv, e0.y * inv, e1.x * inv, e1.y * inv);
    }
}

// ---------------- K8: out-proj + shortcut + LN + MLP(gelu) residual (packed) ----------------
__global__ __launch_bounds__(256) void proj_mlp_kernel(
    const float* __restrict__ att, const float* __restrict__ sc,
    const float* __restrict__ wp, const float* __restrict__ bp,
    const float* __restrict__ n2g, const float* __restrict__ n2b,
    const float* __restrict__ mw1, const float* __restrict__ mb1,
    const float* __restrict__ mw2, const float* __restrict__ mb2,
    float* __restrict__ out) {
    __shared__ u64 s_wp2[512], s_m1a[512], s_m1b[512], s_m2[1024];
    __shared__ float s_bp[32], s_mb1[64], s_mb2[32], s_g[32], s_b[32];
    __shared__ __align__(16) float s_act[8][32];
    __shared__ __align__(16) float s_h[8][64];
    int tid = threadIdx.x;
    for (int idx = tid; idx < 512; idx += 256) {
        int i2 = idx >> 5, l = idx & 31;
        s_wp2[idx] = f2pack(wp[(2 * i2) * 32 + l], wp[(2 * i2 + 1) * 32 + l]);
        s_m1a[idx] = f2pack(mw1[(2 * i2) * 64 + l], mw1[(2 * i2 + 1) * 64 + l]);
        s_m1b[idx] = f2pack(mw1[(2 * i2) * 64 + 32 + l], mw1[(2 * i2 + 1) * 64 + 32 + l]);
    }
    for (int idx = tid; idx < 1024; idx += 256) {
        int i2 = idx >> 5, l = idx & 31;
        s_m2[idx] = f2pack(mw2[(2 * i2) * 32 + l], mw2[(2 * i2 + 1) * 32 + l]);
    }
    if (tid < 32) { s_bp[tid] = bp[tid]; s_mb2[tid] = mb2[tid]; s_g[tid] = n2g[tid]; s_b[tid] = n2b[tid]; }
    if (tid < 64) s_mb1[tid] = mb1[tid];
    __syncthreads();
    int lane = tid & 31, w = tid >> 5;
    int p = blockIdx.x * 8 + w;

    float a = att[p * 32 + lane];
    s_act[w][lane] = a;
    __syncwarp();
    u64 acc = 0ULL;
#pragma unroll
    for (int i2 = 0; i2 < 16; i2++) {
        u64 x2 = *(const u64*)&s_act[w][2 * i2];
        acc = f2fma(x2, s_wp2[i2 * 32 + lane], acc);
    }
    float2 fy = f2unpack(acc);
    float y = fy.x + fy.y + s_bp[lane] + sc[p * 32 + lane];

    float mean = warp_sum(y) * (1.f / 32.f);
    float dv = y - mean;
    float var = warp_sum(dv * dv) * (1.f / 32.f);
    float yn = dv * rsqrtf(var + 1e-5f) * s_g[lane] + s_b[lane];

    __syncwarp();
    s_act[w][lane] = yn;
    __syncwarp();
    u64 h0a = 0ULL, h1a = 0ULL;
#pragma unroll
    for (int i2 = 0; i2 < 16; i2++) {
        u64 x2 = *(const u64*)&s_act[w][2 * i2];
        h0a = f2fma(x2, s_m1a[i2 * 32 + lane], h0a);
        h1a = f2fma(x2, s_m1b[i2 * 32 + lane], h1a);
    }
    float2 f0 = f2unpack(h0a), f1 = f2unpack(h1a);
    float h0 = gelu_tanh(f0.x + f0.y + s_mb1[lane]);
    float h1 = gelu_tanh(f1.x + f1.y + s_mb1[lane + 32]);
    s_h[w][lane] = h0;
    s_h[w][32 + lane] = h1;
    __syncwarp();
    u64 r2 = 0ULL;
#pragma unroll
    for (int i2 = 0; i2 < 32; i2++) {
        u64 g2 = *(const u64*)&s_h[w][2 * i2];
        r2 = f2fma(g2, s_m2[i2 * 32 + lane], r2);
    }
    float2 fr = f2unpack(r2);
    out[p * 32 + lane] = y + fr.x + fr.y + s_mb2[lane];
}

// ---------------- K9: final sum, HWC -> CHW ----------------
__global__ void final_kernel(const float* __restrict__ o1, const float* __restrict__ o2,
                             const float* __restrict__ x, float* __restrict__ out) {
    __shared__ float sm[32][33];
    int p0 = blockIdx.x * 32;
    int tx = threadIdx.x, ty = threadIdx.y;
    for (int r = ty; r < 32; r += 8) {
        int p = p0 + r;
        sm[r][tx] = o1[p * 32 + tx] + o2[p * 32 + tx];
    }
    __syncthreads();
    for (int c = ty; c < 32; c += 8)
        out[c * HWP + p0 + tx] = sm[tx][c] + x[c * HWP + p0 + tx];
}

// ---------------- launch ----------------
extern "C" void kernel_launch(void* const* d_in, const int* in_sizes, int n_in,
                              void* d_out, int out_size) {
    const float* x    = (const float*)d_in[0];
    const float* dep  = (const float*)d_in[1];
    const int*   rpi  = (const int*)  d_in[2];
    const float* cw1  = (const float*)d_in[3];
    const float* cb1  = (const float*)d_in[4];
    const float* cw2  = (const float*)d_in[5];
    const float* cb2  = (const float*)d_in[6];
    const float* cw3  = (const float*)d_in[7];
    const float* cb3  = (const float*)d_in[8];
    const float* cw4  = (const float*)d_in[9];
    const float* cb4  = (const float*)d_in[10];
    const float* in_g = (const float*)d_in[11];
    const float* in_b = (const float*)d_in[12];
    const float* n1g  = (const float*)d_in[13];
    const float* n1b  = (const float*)d_in[14];
    const float* wq   = (const float*)d_in[15];
    const float* bq   = (const float*)d_in[16];
    const float* wkv  = (const float*)d_in[17];
    const float* bkv  = (const float*)d_in[18];
    const float* rpb  = (const float*)d_in[19];
    const float* wp   = (const float*)d_in[20];
    const float* bp   = (const float*)d_in[21];
    const float* n2g  = (const float*)d_in[22];
    const float* n2b  = (const float*)d_in[23];
    const float* mw1  = (const float*)d_in[24];
    const float* mb1  = (const float*)d_in[25];
    const float* mw2  = (const float*)d_in[26];
    const float* mb2  = (const float*)d_in[27];
    float* out = (float*)d_out;

    void *p_xhwc, *p_f, *p_t2, *p_t4, *p_q, *p_kv, *p_att, *p_o1, *p_o2, *p_bias, *p_stats, *p_part;
    cudaGetSymbolAddress(&p_xhwc, g_xhwc);
    cudaGetSymbolAddress(&p_f, g_f);
    cudaGetSymbolAddress(&p_t2, g_t2);
    cudaGetSymbolAddress(&p_t4, g_t4);
    cudaGetSymbolAddress(&p_q, g_q);
    cudaGetSymbolAddress(&p_kv, g_kv);
    cudaGetSymbolAddress(&p_att, g_att);
    cudaGetSymbolAddress(&p_o1, g_o1);
    cudaGetSymbolAddress(&p_o2, g_o2);
    cudaGetSymbolAddress(&p_bias, g_biasT);
    cudaGetSymbolAddress(&p_stats, g_stats);
    cudaGetSymbolAddress(&p_part, g_part);

    cudaFuncSetAttribute(attn_kernel, cudaFuncAttributeMaxDynamicSharedMemorySize,
                         NKEY * 16 * 2 * (int)sizeof(float));
    const int smem_attn = NKEY * 16 * 2 * (int)sizeof(float);  // 73728

    chw2hwc_kernel<<<2048, dim3(32, 8)>>>(x, (float*)p_xhwc);
    stem12_kernel<<<256, 256>>>(dep, cw1, cb1, cw2, cb2, (float*)p_t2);
    stem34_kernel<<<256, 256>>>((float*)p_t2, cw3, cb3, cw4, cb4, (float*)p_t4);
    inorm_part_kernel<<<1024, 256>>>((float*)p_t4, (double*)p_part);
    inorm_final_kernel<<<1, 256>>>((double*)p_part, (float*)p_stats);
    inorm_apply_kernel<<<8192, 256>>>((float*)p_t4, (float*)p_stats, in_g, in_b, (float*)p_f);
    build_bias_kernel<<<576, 256>>>(rpi, rpb, (float*)p_bias);

    // OCAB 1: q from x, kv from f
    ln_qkv_kernel<<<8192, 256>>>((float*)p_xhwc, (float*)p_f, n1g, n1b, wq, bq, wkv, bkv,
                                 (float*)p_q, (float*)p_kv);
    attn_kernel<<<dim3(NWIN, 2), 256, smem_attn>>>((float*)p_q, (float*)p_kv,
                                                   (float*)p_bias, (float*)p_att);
    proj_mlp_kernel<<<8192, 256>>>((float*)p_att, (float*)p_xhwc, wp, bp, n2g, n2b,
                                   mw1, mb1, mw2, mb2, (float*)p_o1);

    // OCAB 2: q from f, kv from x
    ln_qkv_kernel<<<8192, 256>>>((float*)p_f, (float*)p_xhwc, n1g, n1b, wq, bq, wkv, bkv,
                                 (float*)p_q, (float*)p_kv);
    attn_kernel<<<dim3(NWIN, 2), 256, smem_attn>>>((float*)p_q, (float*)p_kv,
                                                   (float*)p_bias, (float*)p_att);
    proj_mlp_kernel<<<8192, 256>>>((float*)p_att, (float*)p_f, wp, bp, n2g, n2b,
                                   mw1, mb1, mw2, mb2, (float*)p_o2);

    final_kernel<<<2048, dim3(32, 8)>>>((float*)p_o1, (float*)p_o2, x, out);
}

// round 3
// speedup vs baseline: 1.7127x; 1.5117x over previous
#include <cuda_runtime.h>
#include <math.h>

// Problem constants: B=1, C=32, H=W=256, WS=16, OWS=24, NH=2, d=16
#define HWP   65536
#define NKEY  576
#define NQ    256
#define NWIN  256

typedef unsigned long long u64;

// ---------------- scratch (device globals; no runtime allocation) ----------------
__device__ float  g_xhwc [HWP * 32];
__device__ float  g_f    [HWP * 32];
__device__ float  g_t2   [HWP * 16];
__device__ float  g_t4   [HWP * 32];
__device__ float  g_q    [2 * HWP * 32];
__device__ float  g_kv   [2 * HWP * 64];
__device__ float  g_att  [2 * HWP * 32];
__device__ float  g_o    [2 * HWP * 32];
__device__ float  g_biasT[2 * NKEY * NQ];
__device__ float  g_stats[64];
__device__ float  g_part [512 * 64];

// ---------------- packed f32x2 helpers ----------------
__device__ __forceinline__ u64 f2pack(float lo, float hi) {
    u64 r; asm("mov.b64 %0, {%1, %2};" : "=l"(r) : "f"(lo), "f"(hi)); return r;
}
__device__ __forceinline__ float2 f2unpack(u64 v) {
    float2 f; asm("mov.b64 {%0, %1}, %2;" : "=f"(f.x), "=f"(f.y) : "l"(v)); return f;
}
__device__ __forceinline__ u64 f2fma(u64 a, u64 b, u64 c) {
    u64 d; asm("fma.rn.f32x2 %0, %1, %2, %3;" : "=l"(d) : "l"(a), "l"(b), "l"(c)); return d;
}
__device__ __forceinline__ u64 f2mul(u64 a, u64 b) {
    u64 d; asm("mul.rn.f32x2 %0, %1, %2;" : "=l"(d) : "l"(a), "l"(b)); return d;
}
__device__ __forceinline__ u64 f2add(u64 a, u64 b) {
    u64 d; asm("add.rn.f32x2 %0, %1, %2;" : "=l"(d) : "l"(a), "l"(b)); return d;
}
__device__ __forceinline__ float ex2f(float x) {
    float y; asm("ex2.approx.f32 %0, %1;" : "=f"(y) : "f"(x)); return y;
}

__device__ __forceinline__ float warp_sum(float v) {
#pragma unroll
    for (int o = 16; o; o >>= 1) v += __shfl_xor_sync(0xffffffffu, v, o);
    return v;
}

__device__ __forceinline__ float gelu_tanh(float x) {
    float x3 = x * x * x;
    return 0.5f * x * (1.f + tanhf(0.7978845608028654f * (x + 0.044715f * x3)));
}

#define LOG2E 1.4426950408889634f

// ---------------- K0: CHW -> HWC transpose of x ----------------
__global__ void chw2hwc_kernel(const float* __restrict__ x, float* __restrict__ xh) {
    __shared__ float sm[32][33];
    int p0 = blockIdx.x * 32;
    int tx = threadIdx.x, ty = threadIdx.y;
    for (int c = ty; c < 32; c += 8) sm[c][tx] = x[c * HWP + p0 + tx];
    __syncthreads();
    for (int r = ty; r < 32; r += 8) xh[(p0 + r) * 32 + tx] = sm[tx][r];
}

// ---------------- K1: conv1(1->8,k3)+relu + conv2(8->16,k1)+relu ----------------
__global__ __launch_bounds__(256) void stem12_kernel(
    const float* __restrict__ depth,
    const float* __restrict__ cw1, const float* __restrict__ cb1,
    const float* __restrict__ cw2, const float* __restrict__ cb2,
    float* __restrict__ t2) {
    __shared__ float w1[72], b1s[8], w2[128], b2s[16];
    int tid = threadIdx.x;
    if (tid < 72)  w1[tid]  = cw1[tid];
    if (tid < 8)   b1s[tid] = cb1[tid];
    if (tid < 128) w2[tid]  = cw2[tid];
    if (tid < 16)  b2s[tid] = cb2[tid];
    __syncthreads();
    int p = blockIdx.x * 256 + tid;
    int y = p >> 8, x = p & 255;
    float d[9];
#pragma unroll
    for (int tap = 0; tap < 9; tap++) {
        int yy = y + tap / 3 - 1, xx = x + tap % 3 - 1;
        d[tap] = ((unsigned)yy < 256u && (unsigned)xx < 256u) ? depth[(yy << 8) + xx] : 0.f;
    }
    float c1[8];
#pragma unroll
    for (int o = 0; o < 8; o++) {
        float a = b1s[o];
#pragma unroll
        for (int tap = 0; tap < 9; tap++) a += d[tap] * w1[o * 9 + tap];
        c1[o] = fmaxf(a, 0.f);
    }
    float* dst = t2 + p * 16;
#pragma unroll
    for (int o2 = 0; o2 < 16; o2++) {
        float a = b2s[o2];
#pragma unroll
        for (int o = 0; o < 8; o++) a += c1[o] * w2[o2 * 8 + o];
        dst[o2] = fmaxf(a, 0.f);
    }
}

// ---------------- K2: conv3(16->16,k3)+relu + conv4(16->32,k1), packed f32x2 ----------------
__global__ __launch_bounds__(256) void stem34_kernel(
    const float* __restrict__ t2,
    const float* __restrict__ cw3, const float* __restrict__ cb3,
    const float* __restrict__ cw4, const float* __restrict__ cb4,
    float* __restrict__ t4) {
    __shared__ u64 w3p[1152];   // [oc][tap][ic2]
    __shared__ u64 w4p[256];    // [c4][oc2]
    __shared__ float b3[16], b4[32];
    int tid = threadIdx.x;
    for (int i = tid; i < 1152; i += 256) {
        int oc = i / 72, r = i - oc * 72, tap = r >> 3, ic2 = r & 7;
        w3p[i] = f2pack(cw3[oc * 144 + (2 * ic2) * 9 + tap],
                        cw3[oc * 144 + (2 * ic2 + 1) * 9 + tap]);
    }
    if (tid < 256) {
        int c4 = tid >> 3, o2 = tid & 7;
        w4p[tid] = f2pack(cw4[c4 * 16 + 2 * o2], cw4[c4 * 16 + 2 * o2 + 1]);
    }
    if (tid < 16) b3[tid] = cb3[tid];
    if (tid < 32) b4[tid] = cb4[tid];
    __syncthreads();
    int p = blockIdx.x * 256 + tid;
    int y = p >> 8, x = p & 255;
    u64 acc2[16];
#pragma unroll
    for (int i = 0; i < 16; i++) acc2[i] = 0ULL;
#pragma unroll 1
    for (int tap = 0; tap < 9; tap++) {
        int yy = y + tap / 3 - 1, xx = x + tap % 3 - 1;
        if ((unsigned)yy < 256u && (unsigned)xx < 256u) {
            const float4* src = (const float4*)(t2 + (((yy << 8) + xx) << 4));
            float4 i0 = src[0], i1 = src[1], i2v = src[2], i3 = src[3];
            u64 in2[8] = {f2pack(i0.x, i0.y), f2pack(i0.z, i0.w),
                          f2pack(i1.x, i1.y), f2pack(i1.z, i1.w),
                          f2pack(i2v.x, i2v.y), f2pack(i2v.z, i2v.w),
                          f2pack(i3.x, i3.y), f2pack(i3.z, i3.w)};
            const u64* wt = &w3p[tap * 8];
#pragma unroll
            for (int oc = 0; oc < 16; oc++) {
                const u64* wr = wt + oc * 72;
#pragma unroll
                for (int k = 0; k < 8; k++) acc2[oc] = f2fma(in2[k], wr[k], acc2[oc]);
            }
        }
    }
    float c3[16];
#pragma unroll
    for (int oc = 0; oc < 16; oc++) {
        float2 f = f2unpack(acc2[oc]);
        c3[oc] = fmaxf(f.x + f.y + b3[oc], 0.f);
    }
    u64 a2[8];
#pragma unroll
    for (int o2 = 0; o2 < 8; o2++) a2[o2] = f2pack(c3[2 * o2], c3[2 * o2 + 1]);
    float* dst = t4 + (size_t)p * 32;
#pragma unroll
    for (int c4 = 0; c4 < 32; c4++) {
        u64 r = 0ULL;
#pragma unroll
        for (int o2 = 0; o2 < 8; o2++) r = f2fma(a2[o2], w4p[c4 * 8 + o2], r);
        float2 f = f2unpack(r);
        dst[c4] = f.x + f.y + b4[c4];
    }
}

// ---------------- K3a: instance-norm partial sums (fp32, float4, 512 blocks) ----------------
__global__ __launch_bounds__(256) void inorm_part_kernel(const float* __restrict__ t4,
                                                         float* __restrict__ part) {
    int tid = threadIdx.x;
    // block handles 128 pixels = 4096 floats; thread loads 4 float4 = 16 floats
    size_t base = (size_t)blockIdx.x * 4096;
    float s[4] = {0, 0, 0, 0}, s2[4] = {0, 0, 0, 0};
    const float4* src = (const float4*)(t4 + base);
#pragma unroll
    for (int it = 0; it < 4; it++) {
        float4 v = src[it * 256 + tid];
        s[0] += v.x; s2[0] += v.x * v.x;
        s[1] += v.y; s2[1] += v.y * v.y;
        s[2] += v.z; s2[2] += v.z * v.z;
        s[3] += v.w; s2[3] += v.w * v.w;
    }
    // thread covers channels c0 = (tid&7)*4 .. +3
    __shared__ float sa[256][4], sb[256][4];
#pragma unroll
    for (int k = 0; k < 4; k++) { sa[tid][k] = s[k]; sb[tid][k] = s2[k]; }
    __syncthreads();
    // 32 accumulators (channels); threads 0..31: channel c = tid; gather from threads with (t&7)*4<=c<(t&7)*4+4
    if (tid < 32) {
        int grp = tid >> 2, k = tid & 3;   // source thread group (t&7)==grp, slot k
        float a = 0.f, b = 0.f;
#pragma unroll
        for (int t8 = 0; t8 < 32; t8++) {  // threads t = t8*8 + grp
            a += sa[t8 * 8 + grp][k];
            b += sb[t8 * 8 + grp][k];
        }
        part[blockIdx.x * 64 + tid] = a;
        part[blockIdx.x * 64 + 32 + tid] = b;
    }
}

// ---------------- K3b: instance-norm final reduce (fp64 accumulate of partials) ----------------
__global__ __launch_bounds__(256) void inorm_final_kernel(const float* __restrict__ part,
                                                          float* __restrict__ stats) {
    int c = threadIdx.x & 31, g = threadIdx.x >> 5;
    double a = 0.0, b = 0.0;
    for (int blk = g; blk < 512; blk += 8) {
        a += (double)part[blk * 64 + c];
        b += (double)part[blk * 64 + 32 + c];
    }
    __shared__ double sa[8][32], sb[8][32];
    sa[g][c] = a; sb[g][c] = b;
    __syncthreads();
    if (threadIdx.x < 32) {
        double s = 0.0, s2 = 0.0;
#pragma unroll
        for (int k = 0; k < 8; k++) { s += sa[k][threadIdx.x]; s2 += sb[k][threadIdx.x]; }
        double mean = s / (double)HWP;
        double var = s2 / (double)HWP - mean * mean;
        stats[threadIdx.x] = (float)mean;
        stats[32 + threadIdx.x] = rsqrtf((float)var + 1e-5f);
    }
}

// ---------------- K4: apply instance norm -> f (HWC) ----------------
__global__ void inorm_apply_kernel(const float* __restrict__ t4, const float* __restrict__ stats,
                                   const float* __restrict__ in_g, const float* __restrict__ in_b,
                                   float* __restrict__ f) {
    int idx = blockIdx.x * 256 + threadIdx.x;
    int c = idx & 31;
    f[idx] = (t4[idx] - stats[c]) * stats[32 + c] * in_g[c] + in_b[c];
}

// ---------------- K5: rel-pos bias, transposed, pre-scaled by log2(e) ----------------
__global__ void build_bias_kernel(const int* __restrict__ rpi, const float* __restrict__ rpb,
                                  float* __restrict__ biasT) {
    int idx = blockIdx.x * 256 + threadIdx.x;   // 576*256
    int j = idx >> 8, qq = idx & 255;
    int r = rpi[qq * NKEY + j];
    biasT[j * NQ + qq] = rpb[r * 2 + 0] * LOG2E;
    biasT[NKEY * NQ + j * NQ + qq] = rpb[r * 2 + 1] * LOG2E;
}

// ---------------- K6: LN + q/kv projections, both OCABs via blockIdx.y ----------------
__global__ __launch_bounds__(256) void ln_qkv_kernel(
    const float* __restrict__ xhwc, const float* __restrict__ f,
    const float* __restrict__ n1g, const float* __restrict__ n1b,
    const float* __restrict__ wq, const float* __restrict__ bq,
    const float* __restrict__ wkv, const float* __restrict__ bkv,
    float* __restrict__ qbase, float* __restrict__ kvbase) {
    __shared__ u64 s_wq2[512], s_wk2[512], s_wv2[512];
    __shared__ float s_bq[32], s_bkv[64], s_g[32], s_b[32];
    __shared__ __align__(16) float s_act[8][32];
    int tid = threadIdx.x;
    for (int idx = tid; idx < 512; idx += 256) {
        int i2 = idx >> 5, l = idx & 31;
        s_wq2[idx] = f2pack(wq[(2 * i2) * 32 + l], wq[(2 * i2 + 1) * 32 + l]);
        s_wk2[idx] = f2pack(wkv[(2 * i2) * 64 + l], wkv[(2 * i2 + 1) * 64 + l]);
        s_wv2[idx] = f2pack(wkv[(2 * i2) * 64 + 32 + l], wkv[(2 * i2 + 1) * 64 + 32 + l]);
    }
    if (tid < 32) { s_bq[tid] = bq[tid]; s_g[tid] = n1g[tid]; s_b[tid] = n1b[tid]; }
    if (tid < 64) s_bkv[tid] = bkv[tid];
    __syncthreads();
    int z = blockIdx.y;
    const float* srcq  = z ? f : xhwc;
    const float* srckv = z ? xhwc : f;
    float* qo  = qbase  + (size_t)z * HWP * 32;
    float* kvo = kvbase + (size_t)z * HWP * 64;
    int lane = tid & 31, w = tid >> 5;
    int p = blockIdx.x * 8 + w;
    {
        float xv = srcq[p * 32 + lane];
        float mean = warp_sum(xv) * (1.f / 32.f);
        float dv = xv - mean;
        float var = warp_sum(dv * dv) * (1.f / 32.f);
        float xn = dv * rsqrtf(var + 1e-5f) * s_g[lane] + s_b[lane];
        s_act[w][lane] = xn;
        __syncwarp();
        u64 acc = 0ULL;
#pragma unroll
        for (int i2 = 0; i2 < 16; i2++) {
            u64 x2 = *(const u64*)&s_act[w][2 * i2];
            acc = f2fma(x2, s_wq2[i2 * 32 + lane], acc);
        }
        float2 ff = f2unpack(acc);
        qo[p * 32 + lane] = ff.x + ff.y + s_bq[lane];
        __syncwarp();
    }
    {
        float xv = srckv[p * 32 + lane];
        float mean = warp_sum(xv) * (1.f / 32.f);
        float dv = xv - mean;
        float var = warp_sum(dv * dv) * (1.f / 32.f);
        float xn = dv * rsqrtf(var + 1e-5f) * s_g[lane] + s_b[lane];
        s_act[w][lane] = xn;
        __syncwarp();
        u64 ak = 0ULL, av = 0ULL;
#pragma unroll
        for (int i2 = 0; i2 < 16; i2++) {
            u64 x2 = *(const u64*)&s_act[w][2 * i2];
            ak = f2fma(x2, s_wk2[i2 * 32 + lane], ak);
            av = f2fma(x2, s_wv2[i2 * 32 + lane], av);
        }
        float2 fk = f2unpack(ak), fv = f2unpack(av);
        kvo[p * 64 + lane] = fk.x + fk.y + s_bkv[lane];
        kvo[p * 64 + 32 + lane] = fv.x + fv.y + s_bkv[lane + 32];
    }
}

// ---------------- K7: windowed cross-attention, branchless max-free softmax ----------------
__global__ __launch_bounds__(256) void attn_kernel(
    const float* __restrict__ qbase, const float* __restrict__ kvbase,
    const float* __restrict__ biasT, float* __restrict__ outbase) {
    extern __shared__ float sm[];
    float* ksm = sm;                 // [576][16]
    float* vsm = sm + NKEY * 16;     // [576][16]
    int win = blockIdx.x, head = blockIdx.y, z = blockIdx.z;
    const float* q   = qbase   + (size_t)z * HWP * 32;
    const float* kv  = kvbase  + (size_t)z * HWP * 64;
    float*       out = outbase + (size_t)z * HWP * 32;
    int wy = win >> 4, wx = win & 15;
    int t = threadIdx.x;

    for (int j = t; j < NKEY; j += 256) {
        int jy = j / 24, jx = j - jy * 24;
        int yy = (wy << 4) - 4 + jy, xx = (wx << 4) - 4 + jx;
        float4 k0, k1, k2, k3, v0, v1, v2, v3;
        if ((unsigned)yy < 256u && (unsigned)xx < 256u) {
            const float* base = kv + ((size_t)((yy << 8) + xx) << 6);
            const float4* kp = (const float4*)(base + (head << 4));
            k0 = kp[0]; k1 = kp[1]; k2 = kp[2]; k3 = kp[3];
            const float4* vp = (const float4*)(base + 32 + (head << 4));
            v0 = vp[0]; v1 = vp[1]; v2 = vp[2]; v3 = vp[3];
        } else {
            k0 = k1 = k2 = k3 = make_float4(0.f, 0.f, 0.f, 0.f);
            v0 = v1 = v2 = v3 = k0;
        }
        float4* kd = (float4*)(ksm + j * 16);
        kd[0] = k0; kd[1] = k1; kd[2] = k2; kd[3] = k3;
        float4* vd = (float4*)(vsm + j * 16);
        vd[0] = v0; vd[1] = v1; vd[2] = v2; vd[3] = v3;
    }

    int qy = (wy << 4) + (t >> 4), qx = (wx << 4) + (t & 15);
    const float4* qp = (const float4*)(q + ((size_t)((qy << 8) + qx) << 5) + (head << 4));
    float4 q0 = qp[0], q1 = qp[1], q2 = qp[2], q3 = qp[3];
    const float QS = 0.25f * LOG2E;   // fold 1/sqrt(d) and log2(e) into q
    u64 qp8[8] = {f2pack(q0.x * QS, q0.y * QS), f2pack(q0.z * QS, q0.w * QS),
                  f2pack(q1.x * QS, q1.y * QS), f2pack(q1.z * QS, q1.w * QS),
                  f2pack(q2.x * QS, q2.y * QS), f2pack(q2.z * QS, q2.w * QS),
                  f2pack(q3.x * QS, q3.y * QS), f2pack(q3.z * QS, q3.w * QS)};
    __syncthreads();

    const float* brow = biasT + head * (NKEY * NQ) + t;
    float l = 0.f;
    u64 o2[8];
#pragma unroll
    for (int dd = 0; dd < 8; dd++) o2[dd] = 0ULL;

#pragma unroll 4
    for (int j = 0; j < NKEY; j++) {
        const ulonglong2* kk = (const ulonglong2*)(ksm + j * 16);
        ulonglong2 kA = kk[0], kB = kk[1], kC = kk[2], kD = kk[3];
        u64 a0 = f2mul(qp8[0], kA.x);
        u64 a1 = f2mul(qp8[1], kA.y);
        a0 = f2fma(qp8[2], kB.x, a0); a1 = f2fma(qp8[3], kB.y, a1);
        a0 = f2fma(qp8[4], kC.x, a0); a1 = f2fma(qp8[5], kC.y, a1);
        a0 = f2fma(qp8[6], kD.x, a0); a1 = f2fma(qp8[7], kD.y, a1);
        a0 = f2add(a0, a1);
        float2 fs = f2unpack(a0);
        float s = brow[j << 8] + fs.x + fs.y;          // log2-domain score
        float pp = ex2f(fminf(s, 100.f));              // branchless, overflow-safe
        l += pp;
        const ulonglong2* vv = (const ulonglong2*)(vsm + j * 16);
        ulonglong2 vA = vv[0], vB = vv[1], vC = vv[2], vD = vv[3];
        u64 p2 = f2pack(pp, pp);
        o2[0] = f2fma(p2, vA.x, o2[0]); o2[1] = f2fma(p2, vA.y, o2[1]);
        o2[2] = f2fma(p2, vB.x, o2[2]); o2[3] = f2fma(p2, vB.y, o2[3]);
        o2[4] = f2fma(p2, vC.x, o2[4]); o2[5] = f2fma(p2, vC.y, o2[5]);
        o2[6] = f2fma(p2, vD.x, o2[6]); o2[7] = f2fma(p2, vD.y, o2[7]);
    }
    float inv = 1.f / l;
    float4* op = (float4*)(out + ((size_t)((qy << 8) + qx) << 5) + (head << 4));
#pragma unroll
    for (int g = 0; g < 4; g++) {
        float2 e0 = f2unpack(o2[2 * g]);
        float2 e1 = f2unpack(o2[2 * g + 1]);
        op[g] = make_float4(e0.x * inv, e0.y * inv, e1.x * inv, e1.y * inv);
    }
}

// ---------------- K8: out-proj + shortcut + LN + MLP(gelu), both OCABs ----------------
__global__ __launch_bounds__(256) void proj_mlp_kernel(
    const float* __restrict__ attbase,
    const float* __restrict__ xhwc, const float* __restrict__ f,
    const float* __restrict__ wp, const float* __restrict__ bp,
    const float* __restrict__ n2g, const float* __restrict__ n2b,
    const float* __restrict__ mw1, const float* __restrict__ mb1,
    const float* __restrict__ mw2, const float* __restrict__ mb2,
    float* __restrict__ outbase) {
    __shared__ u64 s_wp2[512], s_m1a[512], s_m1b[512], s_m2[1024];
    __shared__ float s_bp[32], s_mb1[64], s_mb2[32], s_g[32], s_b[32];
    __shared__ __align__(16) float s_act[8][32];
    __shared__ __align__(16) float s_h[8][64];
    int tid = threadIdx.x;
    for (int idx = tid; idx < 512; idx += 256) {
        int i2 = idx >> 5, l = idx & 31;
        s_wp2[idx] = f2pack(wp[(2 * i2) * 32 + l], wp[(2 * i2 + 1) * 32 + l]);
        s_m1a[idx] = f2pack(mw1[(2 * i2) * 64 + l], mw1[(2 * i2 + 1) * 64 + l]);
        s_m1b[idx] = f2pack(mw1[(2 * i2) * 64 + 32 + l], mw1[(2 * i2 + 1) * 64 + 32 + l]);
    }
    for (int idx = tid; idx < 1024; idx += 256) {
        int i2 = idx >> 5, l = idx & 31;
        s_m2[idx] = f2pack(mw2[(2 * i2) * 32 + l], mw2[(2 * i2 + 1) * 32 + l]);
    }
    if (tid < 32) { s_bp[tid] = bp[tid]; s_mb2[tid] = mb2[tid]; s_g[tid] = n2g[tid]; s_b[tid] = n2b[tid]; }
    if (tid < 64) s_mb1[tid] = mb1[tid];
    __syncthreads();
    int z = blockIdx.y;
    const float* att = attbase + (size_t)z * HWP * 32;
    const float* sc  = z ? f : xhwc;
    float* out = outbase + (size_t)z * HWP * 32;
    int lane = tid & 31, w = tid >> 5;
    int p = blockIdx.x * 8 + w;

    float a = att[p * 32 + lane];
    s_act[w][lane] = a;
    __syncwarp();
    u64 acc = 0ULL;
#pragma unroll
    for (int i2 = 0; i2 < 16; i2++) {
        u64 x2 = *(const u64*)&s_act[w][2 * i2];
        acc = f2fma(x2, s_wp2[i2 * 32 + lane], acc);
    }
    float2 fy = f2unpack(acc);
    float y = fy.x + fy.y + s_bp[lane] + sc[p * 32 + lane];

    float mean = warp_sum(y) * (1.f / 32.f);
    float dv = y - mean;
    float var = warp_sum(dv * dv) * (1.f / 32.f);
    float yn = dv * rsqrtf(var + 1e-5f) * s_g[lane] + s_b[lane];

    __syncwarp();
    s_act[w][lane] = yn;
    __syncwarp();
    u64 h0a = 0ULL, h1a = 0ULL;
#pragma unroll
    for (int i2 = 0; i2 < 16; i2++) {
        u64 x2 = *(const u64*)&s_act[w][2 * i2];
        h0a = f2fma(x2, s_m1a[i2 * 32 + lane], h0a);
        h1a = f2fma(x2, s_m1b[i2 * 32 + lane], h1a);
    }
    float2 f0 = f2unpack(h0a), f1 = f2unpack(h1a);
    float h0 = gelu_tanh(f0.x + f0.y + s_mb1[lane]);
    float h1 = gelu_tanh(f1.x + f1.y + s_mb1[lane + 32]);
    s_h[w][lane] = h0;
    s_h[w][32 + lane] = h1;
    __syncwarp();
    u64 r2 = 0ULL;
#pragma unroll
    for (int i2 = 0; i2 < 32; i2++) {
        u64 g2 = *(const u64*)&s_h[w][2 * i2];
        r2 = f2fma(g2, s_m2[i2 * 32 + lane], r2);
    }
    float2 fr = f2unpack(r2);
    out[p * 32 + lane] = y + fr.x + fr.y + s_mb2[lane];
}

// ---------------- K9: final sum, HWC -> CHW ----------------
__global__ void final_kernel(const float* __restrict__ obase,
                             const float* __restrict__ x, float* __restrict__ out) {
    __shared__ float sm[32][33];
    int p0 = blockIdx.x * 32;
    int tx = threadIdx.x, ty = threadIdx.y;
    const float* o1 = obase;
    const float* o2 = obase + (size_t)HWP * 32;
    for (int r = ty; r < 32; r += 8) {
        int p = p0 + r;
        sm[r][tx] = o1[p * 32 + tx] + o2[p * 32 + tx];
    }
    __syncthreads();
    for (int c = ty; c < 32; c += 8)
        out[c * HWP + p0 + tx] = sm[tx][c] + x[c * HWP + p0 + tx];
}

// ---------------- launch ----------------
extern "C" void kernel_launch(void* const* d_in, const int* in_sizes, int n_in,
                              void* d_out, int out_size) {
    const float* x    = (const float*)d_in[0];
    const float* dep  = (const float*)d_in[1];
    const int*   rpi  = (const int*)  d_in[2];
    const float* cw1  = (const float*)d_in[3];
    const float* cb1  = (const float*)d_in[4];
    const float* cw2  = (const float*)d_in[5];
    const float* cb2  = (const float*)d_in[6];
    const float* cw3  = (const float*)d_in[7];
    const float* cb3  = (const float*)d_in[8];
    const float* cw4  = (const float*)d_in[9];
    const float* cb4  = (const float*)d_in[10];
    const float* in_g = (const float*)d_in[11];
    const float* in_b = (const float*)d_in[12];
    const float* n1g  = (const float*)d_in[13];
    const float* n1b  = (const float*)d_in[14];
    const float* wq   = (const float*)d_in[15];
    const float* bq   = (const float*)d_in[16];
    const float* wkv  = (const float*)d_in[17];
    const float* bkv  = (const float*)d_in[18];
    const float* rpb  = (const float*)d_in[19];
    const float* wp   = (const float*)d_in[20];
    const float* bp   = (const float*)d_in[21];
    const float* n2g  = (const float*)d_in[22];
    const float* n2b  = (const float*)d_in[23];
    const float* mw1  = (const float*)d_in[24];
    const float* mb1  = (const float*)d_in[25];
    const float* mw2  = (const float*)d_in[26];
    const float* mb2  = (const float*)d_in[27];
    float* out = (float*)d_out;

    void *p_xhwc, *p_f, *p_t2, *p_t4, *p_q, *p_kv, *p_att, *p_o, *p_bias, *p_stats, *p_part;
    cudaGetSymbolAddress(&p_xhwc, g_xhwc);
    cudaGetSymbolAddress(&p_f, g_f);
    cudaGetSymbolAddress(&p_t2, g_t2);
    cudaGetSymbolAddress(&p_t4, g_t4);
    cudaGetSymbolAddress(&p_q, g_q);
    cudaGetSymbolAddress(&p_kv, g_kv);
    cudaGetSymbolAddress(&p_att, g_att);
    cudaGetSymbolAddress(&p_o, g_o);
    cudaGetSymbolAddress(&p_bias, g_biasT);
    cudaGetSymbolAddress(&p_stats, g_stats);
    cudaGetSymbolAddress(&p_part, g_part);

    cudaFuncSetAttribute(attn_kernel, cudaFuncAttributeMaxDynamicSharedMemorySize,
                         NKEY * 16 * 2 * (int)sizeof(float));
    const int smem_attn = NKEY * 16 * 2 * (int)sizeof(float);  // 73728

    chw2hwc_kernel<<<2048, dim3(32, 8)>>>(x, (float*)p_xhwc);
    stem12_kernel<<<256, 256>>>(dep, cw1, cb1, cw2, cb2, (float*)p_t2);
    stem34_kernel<<<256, 256>>>((float*)p_t2, cw3, cb3, cw4, cb4, (float*)p_t4);
    inorm_part_kernel<<<512, 256>>>((float*)p_t4, (float*)p_part);
    inorm_final_kernel<<<1, 256>>>((float*)p_part, (float*)p_stats);
    inorm_apply_kernel<<<8192, 256>>>((float*)p_t4, (float*)p_stats, in_g, in_b, (float*)p_f);
    build_bias_kernel<<<576, 256>>>(rpi, rpb, (float*)p_bias);

    ln_qkv_kernel<<<dim3(8192, 2), 256>>>((float*)p_xhwc, (float*)p_f, n1g, n1b,
                                          wq, bq, wkv, bkv, (float*)p_q, (float*)p_kv);
    attn_kernel<<<dim3(NWIN, 2, 2), 256, smem_attn>>>((float*)p_q, (float*)p_kv,
                                                      (float*)p_bias, (float*)p_att);
    proj_mlp_kernel<<<dim3(8192, 2), 256>>>((float*)p_att, (float*)p_xhwc, (float*)p_f,
                                            wp, bp, n2g, n2b, mw1, mb1, mw2, mb2,
                                            (float*)p_o);

    final_kernel<<<2048, dim3(32, 8)>>>((float*)p_o, x, out);
}

// round 4
// speedup vs baseline: 2.7316x; 1.5950x over previous
#include <cuda_runtime.h>
#include <cuda_bf16.h>
#include <math.h>

// Problem constants: B=1, C=32, H=W=256, WS=16, OWS=24, NH=2, d=16
#define HWP   65536
#define NKEY  576
#define NQ    256
#define NWIN  256

typedef unsigned long long u64;
typedef unsigned int u32;

#define LOG2E 1.4426950408889634f

// attn smem layout
#define KSTRIDE 24      // bf16 elems per K row (conflict-free B-frag loads)
#define VSTRIDE 584     // bf16 elems per Vt row (conflict-free B-frag loads)
#define SMEM_K_BYTES (NKEY * KSTRIDE * 2)            // 27648
#define SMEM_ATTN    (SMEM_K_BYTES + 16 * VSTRIDE * 2) // 27648 + 18688 = 46336

// ---------------- scratch (device globals; no runtime allocation) ----------------
__device__ float  g_xhwc [HWP * 32];
__device__ float  g_f    [HWP * 32];
__device__ float  g_t2   [HWP * 16];
__device__ float  g_t4   [HWP * 32];
__device__ float  g_q    [2 * HWP * 32];
__device__ float  g_kv   [2 * HWP * 64];
__device__ float  g_att  [2 * HWP * 32];
__device__ float  g_o    [2 * HWP * 32];
__device__ u64    g_biasF[2 * NQ * 36 * 4];   // [head][q][chunk][tig] packed bf16 x4
__device__ float  g_stats[64];
__device__ float  g_part [512 * 64];

// ---------------- packed f32x2 helpers ----------------
__device__ __forceinline__ u64 f2pack(float lo, float hi) {
    u64 r; asm("mov.b64 %0, {%1, %2};" : "=l"(r) : "f"(lo), "f"(hi)); return r;
}
__device__ __forceinline__ float2 f2unpack(u64 v) {
    float2 f; asm("mov.b64 {%0, %1}, %2;" : "=f"(f.x), "=f"(f.y) : "l"(v)); return f;
}
__device__ __forceinline__ u64 f2fma(u64 a, u64 b, u64 c) {
    u64 d; asm("fma.rn.f32x2 %0, %1, %2, %3;" : "=l"(d) : "l"(a), "l"(b), "l"(c)); return d;
}
__device__ __forceinline__ float ex2f(float x) {
    float y; asm("ex2.approx.f32 %0, %1;" : "=f"(y) : "f"(x)); return y;
}
// pack two f32 into bf16x2 (lo = first arg)
__device__ __forceinline__ u32 bfpack(float lo, float hi) {
    u32 d; asm("cvt.rn.bf16x2.f32 %0, %1, %2;" : "=r"(d) : "f"(hi), "f"(lo)); return d;
}

__device__ __forceinline__ float warp_sum(float v) {
#pragma unroll
    for (int o = 16; o; o >>= 1) v += __shfl_xor_sync(0xffffffffu, v, o);
    return v;
}

__device__ __forceinline__ float gelu_tanh(float x) {
    float z = 0.7978845608028654f * (x + 0.044715f * x * x * x);
    float e = ex2f(2.8853900817779268f * z);     // exp(2z)
    float t = 1.f - __fdividef(2.f, e + 1.f);    // tanh(z), branchless, saturates correctly
    return 0.5f * x * (1.f + t);
}

// mma.sync m16n8k16 bf16 -> f32
__device__ __forceinline__ void mma_bf16(float* d, const u32* a, const u32* b, const float* c) {
    asm("mma.sync.aligned.m16n8k16.row.col.f32.bf16.bf16.f32 "
        "{%0,%1,%2,%3}, {%4,%5,%6,%7}, {%8,%9}, {%10,%11,%12,%13};"
        : "=f"(d[0]), "=f"(d[1]), "=f"(d[2]), "=f"(d[3])
        : "r"(a[0]), "r"(a[1]), "r"(a[2]), "r"(a[3]),
          "r"(b[0]), "r"(b[1]),
          "f"(c[0]), "f"(c[1]), "f"(c[2]), "f"(c[3]));
}

// ---------------- K0: CHW -> HWC transpose of x ----------------
__global__ void chw2hwc_kernel(const float* __restrict__ x, float* __restrict__ xh) {
    __shared__ float sm[32][33];
    int p0 = blockIdx.x * 32;
    int tx = threadIdx.x, ty = threadIdx.y;
    for (int c = ty; c < 32; c += 8) sm[c][tx] = x[c * HWP + p0 + tx];
    __syncthreads();
    for (int r = ty; r < 32; r += 8) xh[(p0 + r) * 32 + tx] = sm[tx][r];
}

// ---------------- K1: conv1(1->8,k3)+relu + conv2(8->16,k1)+relu ----------------
__global__ __launch_bounds__(256) void stem12_kernel(
    const float* __restrict__ depth,
    const float* __restrict__ cw1, const float* __restrict__ cb1,
    const float* __restrict__ cw2, const float* __restrict__ cb2,
    float* __restrict__ t2) {
    __shared__ float w1[72], b1s[8], w2[128], b2s[16];
    int tid = threadIdx.x;
    if (tid < 72)  w1[tid]  = cw1[tid];
    if (tid < 8)   b1s[tid] = cb1[tid];
    if (tid < 128) w2[tid]  = cw2[tid];
    if (tid < 16)  b2s[tid] = cb2[tid];
    __syncthreads();
    int p = blockIdx.x * 256 + tid;
    int y = p >> 8, x = p & 255;
    float d[9];
#pragma unroll
    for (int tap = 0; tap < 9; tap++) {
        int yy = y + tap / 3 - 1, xx = x + tap % 3 - 1;
        d[tap] = ((unsigned)yy < 256u && (unsigned)xx < 256u) ? depth[(yy << 8) + xx] : 0.f;
    }
    float c1[8];
#pragma unroll
    for (int o = 0; o < 8; o++) {
        float a = b1s[o];
#pragma unroll
        for (int tap = 0; tap < 9; tap++) a += d[tap] * w1[o * 9 + tap];
        c1[o] = fmaxf(a, 0.f);
    }
    float* dst = t2 + p * 16;
#pragma unroll
    for (int o2 = 0; o2 < 16; o2++) {
        float a = b2s[o2];
#pragma unroll
        for (int o = 0; o < 8; o++) a += c1[o] * w2[o2 * 8 + o];
        dst[o2] = fmaxf(a, 0.f);
    }
}

// ---------------- K2: conv3(16->16,k3)+relu + conv4(16->32,k1), packed f32x2 ----------------
__global__ __launch_bounds__(256) void stem34_kernel(
    const float* __restrict__ t2,
    const float* __restrict__ cw3, const float* __restrict__ cb3,
    const float* __restrict__ cw4, const float* __restrict__ cb4,
    float* __restrict__ t4) {
    __shared__ u64 w3p[1152];
    __shared__ u64 w4p[256];
    __shared__ float b3[16], b4[32];
    int tid = threadIdx.x;
    for (int i = tid; i < 1152; i += 256) {
        int oc = i / 72, r = i - oc * 72, tap = r >> 3, ic2 = r & 7;
        w3p[i] = f2pack(cw3[oc * 144 + (2 * ic2) * 9 + tap],
                        cw3[oc * 144 + (2 * ic2 + 1) * 9 + tap]);
    }
    if (tid < 256) {
        int c4 = tid >> 3, o2 = tid & 7;
        w4p[tid] = f2pack(cw4[c4 * 16 + 2 * o2], cw4[c4 * 16 + 2 * o2 + 1]);
    }
    if (tid < 16) b3[tid] = cb3[tid];
    if (tid < 32) b4[tid] = cb4[tid];
    __syncthreads();
    int p = blockIdx.x * 256 + tid;
    int y = p >> 8, x = p & 255;
    u64 acc2[16];
#pragma unroll
    for (int i = 0; i < 16; i++) acc2[i] = 0ULL;
#pragma unroll 1
    for (int tap = 0; tap < 9; tap++) {
        int yy = y + tap / 3 - 1, xx = x + tap % 3 - 1;
        if ((unsigned)yy < 256u && (unsigned)xx < 256u) {
            const float4* src = (const float4*)(t2 + (((yy << 8) + xx) << 4));
            float4 i0 = src[0], i1 = src[1], i2v = src[2], i3 = src[3];
            u64 in2[8] = {f2pack(i0.x, i0.y), f2pack(i0.z, i0.w),
                          f2pack(i1.x, i1.y), f2pack(i1.z, i1.w),
                          f2pack(i2v.x, i2v.y), f2pack(i2v.z, i2v.w),
                          f2pack(i3.x, i3.y), f2pack(i3.z, i3.w)};
            const u64* wt = &w3p[tap * 8];
#pragma unroll
            for (int oc = 0; oc < 16; oc++) {
                const u64* wr = wt + oc * 72;
#pragma unroll
                for (int k = 0; k < 8; k++) acc2[oc] = f2fma(in2[k], wr[k], acc2[oc]);
            }
        }
    }
    float c3[16];
#pragma unroll
    for (int oc = 0; oc < 16; oc++) {
        float2 f = f2unpack(acc2[oc]);
        c3[oc] = fmaxf(f.x + f.y + b3[oc], 0.f);
    }
    u64 a2[8];
#pragma unroll
    for (int o2 = 0; o2 < 8; o2++) a2[o2] = f2pack(c3[2 * o2], c3[2 * o2 + 1]);
    float* dst = t4 + (size_t)p * 32;
#pragma unroll
    for (int c4 = 0; c4 < 32; c4++) {
        u64 r = 0ULL;
#pragma unroll
        for (int o2 = 0; o2 < 8; o2++) r = f2fma(a2[o2], w4p[c4 * 8 + o2], r);
        float2 f = f2unpack(r);
        dst[c4] = f.x + f.y + b4[c4];
    }
}

// ---------------- K3a: instance-norm partial sums ----------------
__global__ __launch_bounds__(256) void inorm_part_kernel(const float* __restrict__ t4,
                                                         float* __restrict__ part) {
    int tid = threadIdx.x;
    size_t base = (size_t)blockIdx.x * 4096;
    float s[4] = {0, 0, 0, 0}, s2[4] = {0, 0, 0, 0};
    const float4* src = (const float4*)(t4 + base);
#pragma unroll
    for (int it = 0; it < 4; it++) {
        float4 v = src[it * 256 + tid];
        s[0] += v.x; s2[0] += v.x * v.x;
        s[1] += v.y; s2[1] += v.y * v.y;
        s[2] += v.z; s2[2] += v.z * v.z;
        s[3] += v.w; s2[3] += v.w * v.w;
    }
    __shared__ float sa[256][4], sb[256][4];
#pragma unroll
    for (int k = 0; k < 4; k++) { sa[tid][k] = s[k]; sb[tid][k] = s2[k]; }
    __syncthreads();
    if (tid < 32) {
        int grp = tid >> 2, k = tid & 3;
        float a = 0.f, b = 0.f;
#pragma unroll
        for (int t8 = 0; t8 < 32; t8++) {
            a += sa[t8 * 8 + grp][k];
            b += sb[t8 * 8 + grp][k];
        }
        part[blockIdx.x * 64 + tid] = a;
        part[blockIdx.x * 64 + 32 + tid] = b;
    }
}

// ---------------- K3b: instance-norm final reduce ----------------
__global__ __launch_bounds__(256) void inorm_final_kernel(const float* __restrict__ part,
                                                          float* __restrict__ stats) {
    int c = threadIdx.x & 31, g = threadIdx.x >> 5;
    double a = 0.0, b = 0.0;
    for (int blk = g; blk < 512; blk += 8) {
        a += (double)part[blk * 64 + c];
        b += (double)part[blk * 64 + 32 + c];
    }
    __shared__ double sa[8][32], sb[8][32];
    sa[g][c] = a; sb[g][c] = b;
    __syncthreads();
    if (threadIdx.x < 32) {
        double s = 0.0, s2 = 0.0;
#pragma unroll
        for (int k = 0; k < 8; k++) { s += sa[k][threadIdx.x]; s2 += sb[k][threadIdx.x]; }
        double mean = s / (double)HWP;
        double var = s2 / (double)HWP - mean * mean;
        stats[threadIdx.x] = (float)mean;
        stats[32 + threadIdx.x] = rsqrtf((float)var + 1e-5f);
    }
}

// ---------------- K4: apply instance norm -> f (HWC) ----------------
__global__ void inorm_apply_kernel(const float* __restrict__ t4, const float* __restrict__ stats,
                                   const float* __restrict__ in_g, const float* __restrict__ in_b,
                                   float* __restrict__ f) {
    int idx = blockIdx.x * 256 + threadIdx.x;
    int c = idx & 31;
    f[idx] = (t4[idx] - stats[c]) * stats[32 + c] * in_g[c] + in_b[c];
}

// ---------------- K5: bias fragments [head][q][chunk][tig], bf16 x4, log2-scaled ----------------
__global__ void build_biasF_kernel(const int* __restrict__ rpi, const float* __restrict__ rpb,
                                   u64* __restrict__ biasF) {
    int idx = blockIdx.x * 256 + threadIdx.x;    // 2*256*36*4 = 73728
    int tig = idx & 3;
    int t2 = idx >> 2;
    int ch = t2 % 36;
    int t3 = t2 / 36;
    int q = t3 & 255;
    int h = t3 >> 8;
    int k0 = ch * 16 + 2 * tig;
    u64 r = 0;
#pragma unroll
    for (int e = 0; e < 4; e++) {
        int k = k0 + (e >> 1) * 8 + (e & 1);     // k0, k0+1, k0+8, k0+9
        float v = rpb[rpi[q * NKEY + k] * 2 + h] * LOG2E;
        unsigned short us = __bfloat16_as_ushort(__float2bfloat16(v));
        r |= (u64)us << (16 * e);
    }
    biasF[idx] = r;
}

// ---------------- K6: LN + q/kv projections, both OCABs via blockIdx.y ----------------
__global__ __launch_bounds__(256) void ln_qkv_kernel(
    const float* __restrict__ xhwc, const float* __restrict__ f,
    const float* __restrict__ n1g, const float* __restrict__ n1b,
    const float* __restrict__ wq, const float* __restrict__ bq,
    const float* __restrict__ wkv, const float* __restrict__ bkv,
    float* __restrict__ qbase, float* __restrict__ kvbase) {
    __shared__ u64 s_wq2[512], s_wk2[512], s_wv2[512];
    __shared__ float s_bq[32], s_bkv[64], s_g[32], s_b[32];
    __shared__ __align__(16) float s_act[8][32];
    int tid = threadIdx.x;
    for (int idx = tid; idx < 512; idx += 256) {
        int i2 = idx >> 5, l = idx & 31;
        s_wq2[idx] = f2pack(wq[(2 * i2) * 32 + l], wq[(2 * i2 + 1) * 32 + l]);
        s_wk2[idx] = f2pack(wkv[(2 * i2) * 64 + l], wkv[(2 * i2 + 1) * 64 + l]);
        s_wv2[idx] = f2pack(wkv[(2 * i2) * 64 + 32 + l], wkv[(2 * i2 + 1) * 64 + 32 + l]);
    }
    if (tid < 32) { s_bq[tid] = bq[tid]; s_g[tid] = n1g[tid]; s_b[tid] = n1b[tid]; }
    if (tid < 64) s_bkv[tid] = bkv[tid];
    __syncthreads();
    int z = blockIdx.y;
    const float* srcq  = z ? f : xhwc;
    const float* srckv = z ? xhwc : f;
    float* qo  = qbase  + (size_t)z * HWP * 32;
    float* kvo = kvbase + (size_t)z * HWP * 64;
    int lane = tid & 31, w = tid >> 5;
    int p = blockIdx.x * 8 + w;
    {
        float xv = srcq[p * 32 + lane];
        float mean = warp_sum(xv) * (1.f / 32.f);
        float dv = xv - mean;
        float var = warp_sum(dv * dv) * (1.f / 32.f);
        float xn = dv * rsqrtf(var + 1e-5f) * s_g[lane] + s_b[lane];
        s_act[w][lane] = xn;
        __syncwarp();
        u64 acc = 0ULL;
#pragma unroll
        for (int i2 = 0; i2 < 16; i2++) {
            u64 x2 = *(const u64*)&s_act[w][2 * i2];
            acc = f2fma(x2, s_wq2[i2 * 32 + lane], acc);
        }
        float2 ff = f2unpack(acc);
        qo[p * 32 + lane] = ff.x + ff.y + s_bq[lane];
        __syncwarp();
    }
    {
        float xv = srckv[p * 32 + lane];
        float mean = warp_sum(xv) * (1.f / 32.f);
        float dv = xv - mean;
        float var = warp_sum(dv * dv) * (1.f / 32.f);
        float xn = dv * rsqrtf(var + 1e-5f) * s_g[lane] + s_b[lane];
        s_act[w][lane] = xn;
        __syncwarp();
        u64 ak = 0ULL, av = 0ULL;
#pragma unroll
        for (int i2 = 0; i2 < 16; i2++) {
            u64 x2 = *(const u64*)&s_act[w][2 * i2];
            ak = f2fma(x2, s_wk2[i2 * 32 + lane], ak);
            av = f2fma(x2, s_wv2[i2 * 32 + lane], av);
        }
        float2 fk = f2unpack(ak), fv = f2unpack(av);
        kvo[p * 64 + lane] = fk.x + fk.y + s_bkv[lane];
        kvo[p * 64 + 32 + lane] = fv.x + fv.y + s_bkv[lane + 32];
    }
}

// ---------------- K7: flash attention via mma.sync bf16 ----------------
__global__ __launch_bounds__(256) void attn_kernel(
    const float* __restrict__ qbase, const float* __restrict__ kvbase,
    const u64* __restrict__ biasF, float* __restrict__ outbase) {
    extern __shared__ __align__(16) char smraw[];
    __nv_bfloat16* ksm = (__nv_bfloat16*)smraw;                    // [576][KSTRIDE]
    __nv_bfloat16* vsm = (__nv_bfloat16*)(smraw + SMEM_K_BYTES);   // [16][VSTRIDE] (dim-major)
    int win = blockIdx.x, head = blockIdx.y, z = blockIdx.z;
    const float* q   = qbase   + (size_t)z * HWP * 32;
    const float* kv  = kvbase  + (size_t)z * HWP * 64;
    float*       out = outbase + (size_t)z * HWP * 32;
    int wy = win >> 4, wx = win & 15;
    int t = threadIdx.x;
    int warp = t >> 5, lane = t & 31;
    int gid = lane >> 2, tig = lane & 3;

    // ---- fill K (bf16, row per key) and Vt (bf16, dim-major) ----
    for (int j = t; j < NKEY; j += 256) {
        int jy = j / 24, jx = j - jy * 24;
        int yy = (wy << 4) - 4 + jy, xx = (wx << 4) - 4 + jx;
        float4 k0, k1, k2, k3, v0, v1, v2, v3;
        if ((unsigned)yy < 256u && (unsigned)xx < 256u) {
            const float* base = kv + ((size_t)((yy << 8) + xx) << 6);
            const float4* kp = (const float4*)(base + (head << 4));
            k0 = kp[0]; k1 = kp[1]; k2 = kp[2]; k3 = kp[3];
            const float4* vp = (const float4*)(base + 32 + (head << 4));
            v0 = vp[0]; v1 = vp[1]; v2 = vp[2]; v3 = vp[3];
        } else {
            k0 = k1 = k2 = k3 = make_float4(0.f, 0.f, 0.f, 0.f);
            v0 = v1 = v2 = v3 = k0;
        }
        u32* kd = (u32*)(ksm + j * KSTRIDE);
        kd[0] = bfpack(k0.x, k0.y); kd[1] = bfpack(k0.z, k0.w);
        kd[2] = bfpack(k1.x, k1.y); kd[3] = bfpack(k1.z, k1.w);
        kd[4] = bfpack(k2.x, k2.y); kd[5] = bfpack(k2.z, k2.w);
        kd[6] = bfpack(k3.x, k3.y); kd[7] = bfpack(k3.z, k3.w);
        float vv[16] = {v0.x, v0.y, v0.z, v0.w, v1.x, v1.y, v1.z, v1.w,
                        v2.x, v2.y, v2.z, v2.w, v3.x, v3.y, v3.z, v3.w};
#pragma unroll
        for (int d = 0; d < 16; d++) vsm[d * VSTRIDE + j] = __float2bfloat16(vv[d]);
    }

    // ---- Q fragments (2 m-tiles x a0..a3), pre-scaled by 0.25*log2(e) ----
    const float QS = 0.25f * LOG2E;
    u32 qa[2][4];
    int qwb = warp * 32;
#pragma unroll
    for (int m = 0; m < 2; m++) {
        int r0 = qwb + m * 16 + gid;      // row gid
        int r1 = r0 + 8;                  // row gid+8
        int px0 = ((wy << 4) + (r0 >> 4)) * 256 + (wx << 4) + (r0 & 15);
        int px1 = ((wy << 4) + (r1 >> 4)) * 256 + (wx << 4) + (r1 & 15);
        const float* q0p = q + (size_t)px0 * 32 + (head << 4);
        const float* q1p = q + (size_t)px1 * 32 + (head << 4);
        float2 x0 = *(const float2*)(q0p + 2 * tig);
        float2 x2 = *(const float2*)(q0p + 2 * tig + 8);
        float2 x1 = *(const float2*)(q1p + 2 * tig);
        float2 x3 = *(const float2*)(q1p + 2 * tig + 8);
        qa[m][0] = bfpack(x0.x * QS, x0.y * QS);
        qa[m][1] = bfpack(x1.x * QS, x1.y * QS);
        qa[m][2] = bfpack(x2.x * QS, x2.y * QS);
        qa[m][3] = bfpack(x3.x * QS, x3.y * QS);
    }
    __syncthreads();

    float o[2][2][4];
#pragma unroll
    for (int m = 0; m < 2; m++)
#pragma unroll
        for (int d = 0; d < 2; d++)
#pragma unroll
            for (int i = 0; i < 4; i++) o[m][d][i] = 0.f;
    float l4[4] = {0.f, 0.f, 0.f, 0.f};   // rows: [m*2 + half] = qwb + m*16 + gid + 8*half

    const u64* bF = biasF + ((size_t)head << 8) * 144;   // head*256*36*4

#pragma unroll 2
    for (int ch = 0; ch < 36; ch++) {
        int kb = ch * 16;
        // K B-fragments (2 n-tiles), conflict-free
        u32 kf[2][2];
#pragma unroll
        for (int nt = 0; nt < 2; nt++) {
            const __nv_bfloat16* kr = ksm + (kb + nt * 8 + gid) * KSTRIDE + 2 * tig;
            kf[nt][0] = *(const u32*)kr;
            kf[nt][1] = *(const u32*)(kr + 8);
        }
        // V B-fragments (2 d-tiles), conflict-free
        u32 vb[2][2];
#pragma unroll
        for (int dt = 0; dt < 2; dt++) {
            const __nv_bfloat16* vr = vsm + (dt * 8 + gid) * VSTRIDE + kb + 2 * tig;
            vb[dt][0] = *(const u32*)vr;
            vb[dt][1] = *(const u32*)(vr + 8);
        }
        // bias fragments: one u64 per accumulator row
        u64 bw[4];
#pragma unroll
        for (int r4 = 0; r4 < 4; r4++) {
            int qrow = qwb + ((r4 >> 1) << 4) + ((r4 & 1) << 3) + gid;
            bw[r4] = bF[(qrow * 36 + ch) * 4 + tig];
        }
#pragma unroll
        for (int m = 0; m < 2; m++) {
            float c0[4] = {0.f, 0.f, 0.f, 0.f}, c1[4] = {0.f, 0.f, 0.f, 0.f};
            mma_bf16(c0, qa[m], kf[0], c0);
            mma_bf16(c1, qa[m], kf[1], c1);
            u32 bAlo = (u32)bw[m * 2],     bAhi = (u32)(bw[m * 2] >> 32);
            u32 bBlo = (u32)bw[m * 2 + 1], bBhi = (u32)(bw[m * 2 + 1] >> 32);
            float p00 = ex2f(fminf(c0[0] + __int_as_float(bAlo << 16), 80.f));
            float p01 = ex2f(fminf(c0[1] + __int_as_float((int)(bAlo & 0xffff0000u)), 80.f));
            float p02 = ex2f(fminf(c0[2] + __int_as_float(bBlo << 16), 80.f));
            float p03 = ex2f(fminf(c0[3] + __int_as_float((int)(bBlo & 0xffff0000u)), 80.f));
            float p10 = ex2f(fminf(c1[0] + __int_as_float(bAhi << 16), 80.f));
            float p11 = ex2f(fminf(c1[1] + __int_as_float((int)(bAhi & 0xffff0000u)), 80.f));
            float p12 = ex2f(fminf(c1[2] + __int_as_float(bBhi << 16), 80.f));
            float p13 = ex2f(fminf(c1[3] + __int_as_float((int)(bBhi & 0xffff0000u)), 80.f));
            l4[m * 2]     += (p00 + p01) + (p10 + p11);
            l4[m * 2 + 1] += (p02 + p03) + (p12 + p13);
            u32 pa[4];
            pa[0] = bfpack(p00, p01);   // (row gid,   keys 2tig/2tig+1)   ntile0
            pa[1] = bfpack(p02, p03);   // (row gid+8, keys 2tig/2tig+1)   ntile0
            pa[2] = bfpack(p10, p11);   // (row gid,   keys 8+2tig/+1)     ntile1
            pa[3] = bfpack(p12, p13);   // (row gid+8, keys 8+2tig/+1)     ntile1
            mma_bf16(o[m][0], pa, vb[0], o[m][0]);
            mma_bf16(o[m][1], pa, vb[1], o[m][1]);
        }
    }

    // reduce l across the 4 tig lanes of each gid group
#pragma unroll
    for (int r4 = 0; r4 < 4; r4++) {
        l4[r4] += __shfl_xor_sync(0xffffffffu, l4[r4], 1);
        l4[r4] += __shfl_xor_sync(0xffffffffu, l4[r4], 2);
        l4[r4] = 1.f / l4[r4];
    }

#pragma unroll
    for (int m = 0; m < 2; m++) {
        int r0 = qwb + m * 16 + gid;
        int r1 = r0 + 8;
        int px0 = ((wy << 4) + (r0 >> 4)) * 256 + (wx << 4) + (r0 & 15);
        int px1 = ((wy << 4) + (r1 >> 4)) * 256 + (wx << 4) + (r1 & 15);
        float* o0p = out + (size_t)px0 * 32 + (head << 4);
        float* o1p = out + (size_t)px1 * 32 + (head << 4);
        float i0 = l4[m * 2], i1 = l4[m * 2 + 1];
#pragma unroll
        for (int dt = 0; dt < 2; dt++) {
            *(float2*)(o0p + dt * 8 + 2 * tig) = make_float2(o[m][dt][0] * i0, o[m][dt][1] * i0);
            *(float2*)(o1p + dt * 8 + 2 * tig) = make_float2(o[m][dt][2] * i1, o[m][dt][3] * i1);
        }
    }
}

// ---------------- K8: out-proj + shortcut + LN + MLP(gelu), both OCABs ----------------
__global__ __launch_bounds__(256) void proj_mlp_kernel(
    const float* __restrict__ attbase,
    const float* __restrict__ xhwc, const float* __restrict__ f,
    const float* __restrict__ wp, const float* __restrict__ bp,
    const float* __restrict__ n2g, const float* __restrict__ n2b,
    const float* __restrict__ mw1, const float* __restrict__ mb1,
    const float* __restrict__ mw2, const float* __restrict__ mb2,
    float* __restrict__ outbase) {
    __shared__ u64 s_wp2[512], s_m1a[512], s_m1b[512], s_m2[1024];
    __shared__ float s_bp[32], s_mb1[64], s_mb2[32], s_g[32], s_b[32];
    __shared__ __align__(16) float s_act[8][32];
    __shared__ __align__(16) float s_h[8][64];
    int tid = threadIdx.x;
    for (int idx = tid; idx < 512; idx += 256) {
        int i2 = idx >> 5, l = idx & 31;
        s_wp2[idx] = f2pack(wp[(2 * i2) * 32 + l], wp[(2 * i2 + 1) * 32 + l]);
        s_m1a[idx] = f2pack(mw1[(2 * i2) * 64 + l], mw1[(2 * i2 + 1) * 64 + l]);
        s_m1b[idx] = f2pack(mw1[(2 * i2) * 64 + 32 + l], mw1[(2 * i2 + 1) * 64 + 32 + l]);
    }
    for (int idx = tid; idx < 1024; idx += 256) {
        int i2 = idx >> 5, l = idx & 31;
        s_m2[idx] = f2pack(mw2[(2 * i2) * 32 + l], mw2[(2 * i2 + 1) * 32 + l]);
    }
    if (tid < 32) { s_bp[tid] = bp[tid]; s_mb2[tid] = mb2[tid]; s_g[tid] = n2g[tid]; s_b[tid] = n2b[tid]; }
    if (tid < 64) s_mb1[tid] = mb1[tid];
    __syncthreads();
    int z = blockIdx.y;
    const float* att = attbase + (size_t)z * HWP * 32;
    const float* sc  = z ? f : xhwc;
    float* out = outbase + (size_t)z * HWP * 32;
    int lane = tid & 31, w = tid >> 5;
    int p = blockIdx.x * 8 + w;

    float a = att[p * 32 + lane];
    s_act[w][lane] = a;
    __syncwarp();
    u64 acc = 0ULL;
#pragma unroll
    for (int i2 = 0; i2 < 16; i2++) {
        u64 x2 = *(const u64*)&s_act[w][2 * i2];
        acc = f2fma(x2, s_wp2[i2 * 32 + lane], acc);
    }
    float2 fy = f2unpack(acc);
    float y = fy.x + fy.y + s_bp[lane] + sc[p * 32 + lane];

    float mean = warp_sum(y) * (1.f / 32.f);
    float dv = y - mean;
    float var = warp_sum(dv * dv) * (1.f / 32.f);
    float yn = dv * rsqrtf(var + 1e-5f) * s_g[lane] + s_b[lane];

    __syncwarp();
    s_act[w][lane] = yn;
    __syncwarp();
    u64 h0a = 0ULL, h1a = 0ULL;
#pragma unroll
    for (int i2 = 0; i2 < 16; i2++) {
        u64 x2 = *(const u64*)&s_act[w][2 * i2];
        h0a = f2fma(x2, s_m1a[i2 * 32 + lane], h0a);
        h1a = f2fma(x2, s_m1b[i2 * 32 + lane], h1a);
    }
    float2 f0 = f2unpack(h0a), f1 = f2unpack(h1a);
    float h0 = gelu_tanh(f0.x + f0.y + s_mb1[lane]);
    float h1 = gelu_tanh(f1.x + f1.y + s_mb1[lane + 32]);
    s_h[w][lane] = h0;
    s_h[w][32 + lane] = h1;
    __syncwarp();
    u64 r2 = 0ULL;
#pragma unroll
    for (int i2 = 0; i2 < 32; i2++) {
        u64 g2 = *(const u64*)&s_h[w][2 * i2];
        r2 = f2fma(g2, s_m2[i2 * 32 + lane], r2);
    }
    float2 fr = f2unpack(r2);
    out[p * 32 + lane] = y + fr.x + fr.y + s_mb2[lane];
}

// ---------------- K9: final sum, HWC -> CHW ----------------
__global__ void final_kernel(const float* __restrict__ obase,
                             const float* __restrict__ x, float* __restrict__ out) {
    __shared__ float sm[32][33];
    int p0 = blockIdx.x * 32;
    int tx = threadIdx.x, ty = threadIdx.y;
    const float* o1 = obase;
    const float* o2 = obase + (size_t)HWP * 32;
    for (int r = ty; r < 32; r += 8) {
        int p = p0 + r;
        sm[r][tx] = o1[p * 32 + tx] + o2[p * 32 + tx];
    }
    __syncthreads();
    for (int c = ty; c < 32; c += 8)
        out[c * HWP + p0 + tx] = sm[tx][c] + x[c * HWP + p0 + tx];
}

// ---------------- launch ----------------
extern "C" void kernel_launch(void* const* d_in, const int* in_sizes, int n_in,
                              void* d_out, int out_size) {
    const float* x    = (const float*)d_in[0];
    const float* dep  = (const float*)d_in[1];
    const int*   rpi  = (const int*)  d_in[2];
    const float* cw1  = (const float*)d_in[3];
    const float* cb1  = (const float*)d_in[4];
    const float* cw2  = (const float*)d_in[5];
    const float* cb2  = (const float*)d_in[6];
    const float* cw3  = (const float*)d_in[7];
    const float* cb3  = (const float*)d_in[8];
    const float* cw4  = (const float*)d_in[9];
    const float* cb4  = (const float*)d_in[10];
    const float* in_g = (const float*)d_in[11];
    const float* in_b = (const float*)d_in[12];
    const float* n1g  = (const float*)d_in[13];
    const float* n1b  = (const float*)d_in[14];
    const float* wq   = (const float*)d_in[15];
    const float* bq   = (const float*)d_in[16];
    const float* wkv  = (const float*)d_in[17];
    const float* bkv  = (const float*)d_in[18];
    const float* rpb  = (const float*)d_in[19];
    const float* wp   = (const float*)d_in[20];
    const float* bp   = (const float*)d_in[21];
    const float* n2g  = (const float*)d_in[22];
    const float* n2b  = (const float*)d_in[23];
    const float* mw1  = (const float*)d_in[24];
    const float* mb1  = (const float*)d_in[25];
    const float* mw2  = (const float*)d_in[26];
    const float* mb2  = (const float*)d_in[27];
    float* out = (float*)d_out;

    void *p_xhwc, *p_f, *p_t2, *p_t4, *p_q, *p_kv, *p_att, *p_o, *p_bias, *p_stats, *p_part;
    cudaGetSymbolAddress(&p_xhwc, g_xhwc);
    cudaGetSymbolAddress(&p_f, g_f);
    cudaGetSymbolAddress(&p_t2, g_t2);
    cudaGetSymbolAddress(&p_t4, g_t4);
    cudaGetSymbolAddress(&p_q, g_q);
    cudaGetSymbolAddress(&p_kv, g_kv);
    cudaGetSymbolAddress(&p_att, g_att);
    cudaGetSymbolAddress(&p_o, g_o);
    cudaGetSymbolAddress(&p_bias, g_biasF);
    cudaGetSymbolAddress(&p_stats, g_stats);
    cudaGetSymbolAddress(&p_part, g_part);

    cudaFuncSetAttribute(attn_kernel, cudaFuncAttributeMaxDynamicSharedMemorySize, SMEM_ATTN);

    chw2hwc_kernel<<<2048, dim3(32, 8)>>>(x, (float*)p_xhwc);
    stem12_kernel<<<256, 256>>>(dep, cw1, cb1, cw2, cb2, (float*)p_t2);
    stem34_kernel<<<256, 256>>>((float*)p_t2, cw3, cb3, cw4, cb4, (float*)p_t4);
    inorm_part_kernel<<<512, 256>>>((float*)p_t4, (float*)p_part);
    inorm_final_kernel<<<1, 256>>>((float*)p_part, (float*)p_stats);
    inorm_apply_kernel<<<8192, 256>>>((float*)p_t4, (float*)p_stats, in_g, in_b, (float*)p_f);
    build_biasF_kernel<<<288, 256>>>(rpi, rpb, (u64*)p_bias);

    ln_qkv_kernel<<<dim3(8192, 2), 256>>>((float*)p_xhwc, (float*)p_f, n1g, n1b,
                                          wq, bq, wkv, bkv, (float*)p_q, (float*)p_kv);
    attn_kernel<<<dim3(NWIN, 2, 2), 256, SMEM_ATTN>>>((float*)p_q, (float*)p_kv,
                                                      (u64*)p_bias, (float*)p_att);
    proj_mlp_kernel<<<dim3(8192, 2), 256>>>((float*)p_att, (float*)p_xhwc, (float*)p_f,
                                            wp, bp, n2g, n2b, mw1, mb1, mw2, mb2,
                                            (float*)p_o);

    final_kernel<<<2048, dim3(32, 8)>>>((float*)p_o, x, out);
}

// round 6
// speedup vs baseline: 2.8719x; 1.0513x over previous
#include <cuda_runtime.h>
#include <cuda_bf16.h>
#include <math.h>

// Problem constants: B=1, C=32, H=W=256, WS=16, OWS=24, NH=2, d=16
#define HWP   65536
#define NKEY  576
#define NQ    256
#define NWIN  256

typedef unsigned long long u64;
typedef unsigned int u32;

#define LOG2E 1.4426950408889634f

// attn smem layout
#define KSTRIDE 24      // bf16 elems per K row (conflict-free B-frag loads)
#define VSTRIDE 584     // bf16 elems per Vt row (conflict-free B-frag loads)
#define SMEM_K_BYTES (NKEY * KSTRIDE * 2)              // 27648
#define SMEM_ATTN    (SMEM_K_BYTES + 16 * VSTRIDE * 2) // 46336

// ---------------- scratch (device globals; no runtime allocation) ----------------
__device__ float          g_xhwc [HWP * 32];
__device__ float          g_t2   [HWP * 16];
__device__ float          g_t4   [HWP * 32];
__device__ __nv_bfloat16  g_qbf  [2 * HWP * 32];
__device__ __nv_bfloat16  g_kvbf [2 * HWP * 64];
__device__ __nv_bfloat16  g_attbf[2 * HWP * 32];
__device__ float          g_o    [2 * HWP * 32];
__device__ u64            g_biasF[2 * NQ * 36 * 4];   // [head][q][chunk][tig] bf16 x4
__device__ float          g_stats[64];
__device__ float          g_part [512 * 64];

// ---------------- packed f32x2 helpers ----------------
__device__ __forceinline__ u64 f2pack(float lo, float hi) {
    u64 r; asm("mov.b64 %0, {%1, %2};" : "=l"(r) : "f"(lo), "f"(hi)); return r;
}
__device__ __forceinline__ float2 f2unpack(u64 v) {
    float2 f; asm("mov.b64 {%0, %1}, %2;" : "=f"(f.x), "=f"(f.y) : "l"(v)); return f;
}
__device__ __forceinline__ u64 f2fma(u64 a, u64 b, u64 c) {
    u64 d; asm("fma.rn.f32x2 %0, %1, %2, %3;" : "=l"(d) : "l"(a), "l"(b), "l"(c)); return d;
}
__device__ __forceinline__ float ex2f(float x) {
    float y; asm("ex2.approx.f32 %0, %1;" : "=f"(y) : "f"(x)); return y;
}
// pack two f32 into bf16x2 (lo = first arg)
__device__ __forceinline__ u32 bfpack(float lo, float hi) {
    u32 d; asm("cvt.rn.bf16x2.f32 %0, %1, %2;" : "=r"(d) : "f"(hi), "f"(lo)); return d;
}

__device__ __forceinline__ float warp_sum(float v) {
#pragma unroll
    for (int o = 16; o; o >>= 1) v += __shfl_xor_sync(0xffffffffu, v, o);
    return v;
}

__device__ __forceinline__ float gelu_tanh(float x) {
    float z = 0.7978845608028654f * (x + 0.044715f * x * x * x);
    float e = ex2f(2.8853900817779268f * z);     // exp(2z)
    float t = 1.f - __fdividef(2.f, e + 1.f);    // tanh(z)
    return 0.5f * x * (1.f + t);
}

// mma.sync m16n8k16 bf16 -> f32
__device__ __forceinline__ void mma_bf16(float* d, const u32* a, const u32* b, const float* c) {
    asm("mma.sync.aligned.m16n8k16.row.col.f32.bf16.bf16.f32 "
        "{%0,%1,%2,%3}, {%4,%5,%6,%7}, {%8,%9}, {%10,%11,%12,%13};"
        : "=f"(d[0]), "=f"(d[1]), "=f"(d[2]), "=f"(d[3])
        : "r"(a[0]), "r"(a[1]), "r"(a[2]), "r"(a[3]),
          "r"(b[0]), "r"(b[1]),
          "f"(c[0]), "f"(c[1]), "f"(c[2]), "f"(c[3]));
}

// ---------------- K0: CHW -> HWC transpose of x ----------------
__global__ void chw2hwc_kernel(const float* __restrict__ x, float* __restrict__ xh) {
    __shared__ float sm[32][33];
    int p0 = blockIdx.x * 32;
    int tx = threadIdx.x, ty = threadIdx.y;
    for (int c = ty; c < 32; c += 8) sm[c][tx] = x[c * HWP + p0 + tx];
    __syncthreads();
    for (int r = ty; r < 32; r += 8) xh[(p0 + r) * 32 + tx] = sm[tx][r];
}

// ---------------- K1: conv1(1->8,k3)+relu + conv2(8->16,k1)+relu ----------------
__global__ __launch_bounds__(256) void stem12_kernel(
    const float* __restrict__ depth,
    const float* __restrict__ cw1, const float* __restrict__ cb1,
    const float* __restrict__ cw2, const float* __restrict__ cb2,
    float* __restrict__ t2) {
    __shared__ float w1[72], b1s[8], w2[128], b2s[16];
    int tid = threadIdx.x;
    if (tid < 72)  w1[tid]  = cw1[tid];
    if (tid < 8)   b1s[tid] = cb1[tid];
    if (tid < 128) w2[tid]  = cw2[tid];
    if (tid < 16)  b2s[tid] = cb2[tid];
    __syncthreads();
    int p = blockIdx.x * 256 + tid;
    int y = p >> 8, x = p & 255;
    float d[9];
#pragma unroll
    for (int tap = 0; tap < 9; tap++) {
        int yy = y + tap / 3 - 1, xx = x + tap % 3 - 1;
        d[tap] = ((unsigned)yy < 256u && (unsigned)xx < 256u) ? depth[(yy << 8) + xx] : 0.f;
    }
    float c1[8];
#pragma unroll
    for (int o = 0; o < 8; o++) {
        float a = b1s[o];
#pragma unroll
        for (int tap = 0; tap < 9; tap++) a += d[tap] * w1[o * 9 + tap];
        c1[o] = fmaxf(a, 0.f);
    }
    float* dst = t2 + p * 16;
#pragma unroll
    for (int o2 = 0; o2 < 16; o2++) {
        float a = b2s[o2];
#pragma unroll
        for (int o = 0; o < 8; o++) a += c1[o] * w2[o2 * 8 + o];
        dst[o2] = fmaxf(a, 0.f);
    }
}

// ---------------- K2: conv3(16->16,k3)+relu + conv4(16->32,k1), packed f32x2 ----------------
__global__ __launch_bounds__(256) void stem34_kernel(
    const float* __restrict__ t2,
    const float* __restrict__ cw3, const float* __restrict__ cb3,
    const float* __restrict__ cw4, const float* __restrict__ cb4,
    float* __restrict__ t4) {
    __shared__ u64 w3p[1152];
    __shared__ u64 w4p[256];
    __shared__ float b3[16], b4[32];
    int tid = threadIdx.x;
    for (int i = tid; i < 1152; i += 256) {
        int oc = i / 72, r = i - oc * 72, tap = r >> 3, ic2 = r & 7;
        w3p[i] = f2pack(cw3[oc * 144 + (2 * ic2) * 9 + tap],
                        cw3[oc * 144 + (2 * ic2 + 1) * 9 + tap]);
    }
    if (tid < 256) {
        int c4 = tid >> 3, o2 = tid & 7;
        w4p[tid] = f2pack(cw4[c4 * 16 + 2 * o2], cw4[c4 * 16 + 2 * o2 + 1]);
    }
    if (tid < 16) b3[tid] = cb3[tid];
    if (tid < 32) b4[tid] = cb4[tid];
    __syncthreads();
    int p = blockIdx.x * 256 + tid;
    int y = p >> 8, x = p & 255;
    u64 acc2[16];
#pragma unroll
    for (int i = 0; i < 16; i++) acc2[i] = 0ULL;
#pragma unroll 1
    for (int tap = 0; tap < 9; tap++) {
        int yy = y + tap / 3 - 1, xx = x + tap % 3 - 1;
        if ((unsigned)yy < 256u && (unsigned)xx < 256u) {
            const float4* src = (const float4*)(t2 + (((yy << 8) + xx) << 4));
            float4 i0 = src[0], i1 = src[1], i2v = src[2], i3 = src[3];
            u64 in2[8] = {f2pack(i0.x, i0.y), f2pack(i0.z, i0.w),
                          f2pack(i1.x, i1.y), f2pack(i1.z, i1.w),
                          f2pack(i2v.x, i2v.y), f2pack(i2v.z, i2v.w),
                          f2pack(i3.x, i3.y), f2pack(i3.z, i3.w)};
            const u64* wt = &w3p[tap * 8];
#pragma unroll
            for (int oc = 0; oc < 16; oc++) {
                const u64* wr = wt + oc * 72;
#pragma unroll
                for (int k = 0; k < 8; k++) acc2[oc] = f2fma(in2[k], wr[k], acc2[oc]);
            }
        }
    }
    float c3[16];
#pragma unroll
    for (int oc = 0; oc < 16; oc++) {
        float2 f = f2unpack(acc2[oc]);
        c3[oc] = fmaxf(f.x + f.y + b3[oc], 0.f);
    }
    u64 a2[8];
#pragma unroll
    for (int o2 = 0; o2 < 8; o2++) a2[o2] = f2pack(c3[2 * o2], c3[2 * o2 + 1]);
    float* dst = t4 + (size_t)p * 32;
#pragma unroll
    for (int c4 = 0; c4 < 32; c4++) {
        u64 r = 0ULL;
#pragma unroll
        for (int o2 = 0; o2 < 8; o2++) r = f2fma(a2[o2], w4p[c4 * 8 + o2], r);
        float2 f = f2unpack(r);
        dst[c4] = f.x + f.y + b4[c4];
    }
}

// ---------------- K3a: instance-norm partial sums ----------------
__global__ __launch_bounds__(256) void inorm_part_kernel(const float* __restrict__ t4,
                                                         float* __restrict__ part) {
    int tid = threadIdx.x;
    size_t base = (size_t)blockIdx.x * 4096;
    float s[4] = {0, 0, 0, 0}, s2[4] = {0, 0, 0, 0};
    const float4* src = (const float4*)(t4 + base);
#pragma unroll
    for (int it = 0; it < 4; it++) {
        float4 v = src[it * 256 + tid];
        s[0] += v.x; s2[0] += v.x * v.x;
        s[1] += v.y; s2[1] += v.y * v.y;
        s[2] += v.z; s2[2] += v.z * v.z;
        s[3] += v.w; s2[3] += v.w * v.w;
    }
    __shared__ float sa[256][4], sb[256][4];
#pragma unroll
    for (int k = 0; k < 4; k++) { sa[tid][k] = s[k]; sb[tid][k] = s2[k]; }
    __syncthreads();
    if (tid < 32) {
        int grp = tid >> 2, k = tid & 3;
        float a = 0.f, b = 0.f;
#pragma unroll
        for (int t8 = 0; t8 < 32; t8++) {
            a += sa[t8 * 8 + grp][k];
            b += sb[t8 * 8 + grp][k];
        }
        part[blockIdx.x * 64 + tid] = a;
        part[blockIdx.x * 64 + 32 + tid] = b;
    }
}

// ---------------- K3b: instance-norm final reduce ----------------
__global__ __launch_bounds__(256) void inorm_final_kernel(const float* __restrict__ part,
                                                          float* __restrict__ stats) {
    int c = threadIdx.x & 31, g = threadIdx.x >> 5;
    double a = 0.0, b = 0.0;
    for (int blk = g; blk < 512; blk += 8) {
        a += (double)part[blk * 64 + c];
        b += (double)part[blk * 64 + 32 + c];
    }
    __shared__ double sa[8][32], sb[8][32];
    sa[g][c] = a; sb[g][c] = b;
    __syncthreads();
    if (threadIdx.x < 32) {
        double s = 0.0, s2 = 0.0;
#pragma unroll
        for (int k = 0; k < 8; k++) { s += sa[k][threadIdx.x]; s2 += sb[k][threadIdx.x]; }
        double mean = s / (double)HWP;
        double var = s2 / (double)HWP - mean * mean;
        stats[threadIdx.x] = (float)mean;
        stats[32 + threadIdx.x] = rsqrtf((float)var + 1e-5f);
    }
}

// ---------------- K5: bias fragments [head][q][chunk][tig], bf16 x4, log2-scaled ----------------
__global__ void build_biasF_kernel(const int* __restrict__ rpi, const float* __restrict__ rpb,
                                   u64* __restrict__ biasF) {
    int idx = blockIdx.x * 256 + threadIdx.x;    // 2*256*36*4 = 73728
    int tig = idx & 3;
    int t2 = idx >> 2;
    int ch = t2 % 36;
    int t3 = t2 / 36;
    int q = t3 & 255;
    int h = t3 >> 8;
    int k0 = ch * 16 + 2 * tig;
    u64 r = 0;
#pragma unroll
    for (int e = 0; e < 4; e++) {
        int k = k0 + (e >> 1) * 8 + (e & 1);     // k0, k0+1, k0+8, k0+9
        float v = rpb[rpi[q * NKEY + k] * 2 + h] * LOG2E;
        unsigned short us = __bfloat16_as_ushort(__float2bfloat16(v));
        r |= (u64)us << (16 * e);
    }
    biasF[idx] = r;
}

// ---------------- K6: LN + q/kv projections; f computed on-the-fly; bf16 out ----------------
__global__ __launch_bounds__(256) void ln_qkv_kernel(
    const float* __restrict__ xhwc, const float* __restrict__ t4,
    const float* __restrict__ stats,
    const float* __restrict__ in_g, const float* __restrict__ in_b,
    const float* __restrict__ n1g, const float* __restrict__ n1b,
    const float* __restrict__ wq, const float* __restrict__ bq,
    const float* __restrict__ wkv, const float* __restrict__ bkv,
    __nv_bfloat16* __restrict__ qbase, __nv_bfloat16* __restrict__ kvbase) {
    __shared__ u64 s_wq2[512], s_wk2[512], s_wv2[512];
    __shared__ float s_bq[32], s_bkv[64], s_g[32], s_b[32], s_A[32], s_C[32];
    __shared__ __align__(16) float s_act[8][32];
    int tid = threadIdx.x;
    for (int idx = tid; idx < 512; idx += 256) {
        int i2 = idx >> 5, l = idx & 31;
        s_wq2[idx] = f2pack(wq[(2 * i2) * 32 + l], wq[(2 * i2 + 1) * 32 + l]);
        s_wk2[idx] = f2pack(wkv[(2 * i2) * 64 + l], wkv[(2 * i2 + 1) * 64 + l]);
        s_wv2[idx] = f2pack(wkv[(2 * i2) * 64 + 32 + l], wkv[(2 * i2 + 1) * 64 + 32 + l]);
    }
    if (tid < 32) {
        s_bq[tid] = bq[tid]; s_g[tid] = n1g[tid]; s_b[tid] = n1b[tid];
        float A = stats[32 + tid] * in_g[tid];
        s_A[tid] = A;
        s_C[tid] = in_b[tid] - stats[tid] * A;
    }
    if (tid < 64) s_bkv[tid] = bkv[tid];
    __syncthreads();
    int z = blockIdx.y;
    __nv_bfloat16* qo  = qbase  + (size_t)z * HWP * 32;
    __nv_bfloat16* kvo = kvbase + (size_t)z * HWP * 64;
    int lane = tid & 31, w = tid >> 5;
    int p = blockIdx.x * 8 + w;
    float xv_x = xhwc[p * 32 + lane];
    float fv   = t4[p * 32 + lane] * s_A[lane] + s_C[lane];   // f on the fly
    const float QS = 0.25f * LOG2E;
    {
        float xv = z ? fv : xv_x;
        float mean = warp_sum(xv) * (1.f / 32.f);
        float dv = xv - mean;
        float var = warp_sum(dv * dv) * (1.f / 32.f);
        float xn = dv * rsqrtf(var + 1e-5f) * s_g[lane] + s_b[lane];
        s_act[w][lane] = xn;
        __syncwarp();
        u64 acc = 0ULL;
#pragma unroll
        for (int i2 = 0; i2 < 16; i2++) {
            u64 x2 = *(const u64*)&s_act[w][2 * i2];
            acc = f2fma(x2, s_wq2[i2 * 32 + lane], acc);
        }
        float2 ff = f2unpack(acc);
        qo[p * 32 + lane] = __float2bfloat16((ff.x + ff.y + s_bq[lane]) * QS);
        __syncwarp();
    }
    {
        float xv = z ? xv_x : fv;
        float mean = warp_sum(xv) * (1.f / 32.f);
        float dv = xv - mean;
        float var = warp_sum(dv * dv) * (1.f / 32.f);
        float xn = dv * rsqrtf(var + 1e-5f) * s_g[lane] + s_b[lane];
        s_act[w][lane] = xn;
        __syncwarp();
        u64 ak = 0ULL, av = 0ULL;
#pragma unroll
        for (int i2 = 0; i2 < 16; i2++) {
            u64 x2 = *(const u64*)&s_act[w][2 * i2];
            ak = f2fma(x2, s_wk2[i2 * 32 + lane], ak);
            av = f2fma(x2, s_wv2[i2 * 32 + lane], av);
        }
        float2 fk = f2unpack(ak), fv2 = f2unpack(av);
        kvo[p * 64 + lane]      = __float2bfloat16(fk.x + fk.y + s_bkv[lane]);
        kvo[p * 64 + 32 + lane] = __float2bfloat16(fv2.x + fv2.y + s_bkv[lane + 32]);
    }
}

// ---------------- K7: flash attention via mma.sync bf16, bf16 I/O ----------------
__global__ __launch_bounds__(256) void attn_kernel(
    const __nv_bfloat16* __restrict__ qbase, const __nv_bfloat16* __restrict__ kvbase,
    const u64* __restrict__ biasF, __nv_bfloat16* __restrict__ outbase) {
    extern __shared__ __align__(16) char smraw[];
    __nv_bfloat16* ksm = (__nv_bfloat16*)smraw;                    // [576][KSTRIDE]
    __nv_bfloat16* vsm = (__nv_bfloat16*)(smraw + SMEM_K_BYTES);   // [16][VSTRIDE]
    int win = blockIdx.x, head = blockIdx.y, z = blockIdx.z;
    const __nv_bfloat16* q   = qbase   + (size_t)z * HWP * 32;
    const __nv_bfloat16* kv  = kvbase  + (size_t)z * HWP * 64;
    __nv_bfloat16*       out = outbase + (size_t)z * HWP * 32;
    int wy = win >> 4, wx = win & 15;
    int t = threadIdx.x;
    int warp = t >> 5, lane = t & 31;
    int gid = lane >> 2, tig = lane & 3;

    // ---- fill K (2x uint4 = 16 bf16 per row) and Vt (16 dims, dim-major) ----
    for (int j = t; j < NKEY; j += 256) {
        int jy = j / 24, jx = j - jy * 24;
        int yy = (wy << 4) - 4 + jy, xx = (wx << 4) - 4 + jx;
        uint4 k0 = make_uint4(0, 0, 0, 0), k1 = k0, v0 = k0, v1 = k0;
        if ((unsigned)yy < 256u && (unsigned)xx < 256u) {
            const __nv_bfloat16* base = kv + ((size_t)((yy << 8) + xx) << 6) + (head << 4);
            k0 = *(const uint4*)base;           // k dims 0..7
            k1 = *(const uint4*)(base + 8);     // k dims 8..15
            v0 = *(const uint4*)(base + 32);    // v dims 0..7
            v1 = *(const uint4*)(base + 40);    // v dims 8..15
        }
        *(uint4*)(ksm + j * KSTRIDE)     = k0;
        *(uint4*)(ksm + j * KSTRIDE + 8) = k1;
        u32 vw[8] = {v0.x, v0.y, v0.z, v0.w, v1.x, v1.y, v1.z, v1.w};
#pragma unroll
        for (int i = 0; i < 8; i++) {
            __nv_bfloat162 pr = *(const __nv_bfloat162*)&vw[i];
            vsm[(2 * i) * VSTRIDE + j]     = pr.x;
            vsm[(2 * i + 1) * VSTRIDE + j] = pr.y;
        }
    }

    // ---- Q fragments: direct u32 loads (q pre-scaled at projection) ----
    u32 qa[2][4];
    int qwb = warp * 32;
#pragma unroll
    for (int m = 0; m < 2; m++) {
        int r0 = qwb + m * 16 + gid;
        int r1 = r0 + 8;
        int px0 = ((wy << 4) + (r0 >> 4)) * 256 + (wx << 4) + (r0 & 15);
        int px1 = ((wy << 4) + (r1 >> 4)) * 256 + (wx << 4) + (r1 & 15);
        const __nv_bfloat16* q0p = q + (size_t)px0 * 32 + (head << 4);
        const __nv_bfloat16* q1p = q + (size_t)px1 * 32 + (head << 4);
        qa[m][0] = *(const u32*)(q0p + 2 * tig);
        qa[m][1] = *(const u32*)(q1p + 2 * tig);
        qa[m][2] = *(const u32*)(q0p + 8 + 2 * tig);
        qa[m][3] = *(const u32*)(q1p + 8 + 2 * tig);
    }
    __syncthreads();

    float o[2][2][4];
#pragma unroll
    for (int m = 0; m < 2; m++)
#pragma unroll
        for (int d = 0; d < 2; d++)
#pragma unroll
            for (int i = 0; i < 4; i++) o[m][d][i] = 0.f;
    float l4[4] = {0.f, 0.f, 0.f, 0.f};

    const u64* bF = biasF + ((size_t)head << 8) * 144;

#pragma unroll 2
    for (int ch = 0; ch < 36; ch++) {
        int kb = ch * 16;
        u32 kf[2][2];
#pragma unroll
        for (int nt = 0; nt < 2; nt++) {
            const __nv_bfloat16* kr = ksm + (kb + nt * 8 + gid) * KSTRIDE + 2 * tig;
            kf[nt][0] = *(const u32*)kr;
            kf[nt][1] = *(const u32*)(kr + 8);
        }
        u32 vb[2][2];
#pragma unroll
        for (int dt = 0; dt < 2; dt++) {
            const __nv_bfloat16* vr = vsm + (dt * 8 + gid) * VSTRIDE + kb + 2 * tig;
            vb[dt][0] = *(const u32*)vr;
            vb[dt][1] = *(const u32*)(vr + 8);
        }
        u64 bw[4];
#pragma unroll
        for (int r4 = 0; r4 < 4; r4++) {
            int qrow = qwb + ((r4 >> 1) << 4) + ((r4 & 1) << 3) + gid;
            bw[r4] = bF[(qrow * 36 + ch) * 4 + tig];
        }
#pragma unroll
        for (int m = 0; m < 2; m++) {
            float c0[4] = {0.f, 0.f, 0.f, 0.f}, c1[4] = {0.f, 0.f, 0.f, 0.f};
            mma_bf16(c0, qa[m], kf[0], c0);
            mma_bf16(c1, qa[m], kf[1], c1);
            u32 bAlo = (u32)bw[m * 2],     bAhi = (u32)(bw[m * 2] >> 32);
            u32 bBlo = (u32)bw[m * 2 + 1], bBhi = (u32)(bw[m * 2 + 1] >> 32);
            float p00 = ex2f(fminf(c0[0] + __int_as_float(bAlo << 16), 80.f));
            float p01 = ex2f(fminf(c0[1] + __int_as_float((int)(bAlo & 0xffff0000u)), 80.f));
            float p02 = ex2f(fminf(c0[2] + __int_as_float(bBlo << 16), 80.f));
            float p03 = ex2f(fminf(c0[3] + __int_as_float((int)(bBlo & 0xffff0000u)), 80.f));
            float p10 = ex2f(fminf(c1[0] + __int_as_float(bAhi << 16), 80.f));
            float p11 = ex2f(fminf(c1[1] + __int_as_float((int)(bAhi & 0xffff0000u)), 80.f));
            float p12 = ex2f(fminf(c1[2] + __int_as_float(bBhi << 16), 80.f));
            float p13 = ex2f(fminf(c1[3] + __int_as_float((int)(bBhi & 0xffff0000u)), 80.f));
            l4[m * 2]     += (p00 + p01) + (p10 + p11);
            l4[m * 2 + 1] += (p02 + p03) + (p12 + p13);
            u32 pa[4];
            pa[0] = bfpack(p00, p01);
            pa[1] = bfpack(p02, p03);
            pa[2] = bfpack(p10, p11);
            pa[3] = bfpack(p12, p13);
            mma_bf16(o[m][0], pa, vb[0], o[m][0]);
            mma_bf16(o[m][1], pa, vb[1], o[m][1]);
        }
    }

#pragma unroll
    for (int r4 = 0; r4 < 4; r4++) {
        l4[r4] += __shfl_xor_sync(0xffffffffu, l4[r4], 1);
        l4[r4] += __shfl_xor_sync(0xffffffffu, l4[r4], 2);
        l4[r4] = 1.f / l4[r4];
    }

#pragma unroll
    for (int m = 0; m < 2; m++) {
        int r0 = qwb + m * 16 + gid;
        int r1 = r0 + 8;
        int px0 = ((wy << 4) + (r0 >> 4)) * 256 + (wx << 4) + (r0 & 15);
        int px1 = ((wy << 4) + (r1 >> 4)) * 256 + (wx << 4) + (r1 & 15);
        __nv_bfloat16* o0p = out + (size_t)px0 * 32 + (head << 4);
        __nv_bfloat16* o1p = out + (size_t)px1 * 32 + (head << 4);
        float i0 = l4[m * 2], i1 = l4[m * 2 + 1];
#pragma unroll
        for (int dt = 0; dt < 2; dt++) {
            *(u32*)(o0p + dt * 8 + 2 * tig) = bfpack(o[m][dt][0] * i0, o[m][dt][1] * i0);
            *(u32*)(o1p + dt * 8 + 2 * tig) = bfpack(o[m][dt][2] * i1, o[m][dt][3] * i1);
        }
    }
}

// ---------------- K8: out-proj + shortcut + LN + MLP(gelu); f on the fly ----------------
__global__ __launch_bounds__(256) void proj_mlp_kernel(
    const __nv_bfloat16* __restrict__ attbase,
    const float* __restrict__ xhwc, const float* __restrict__ t4,
    const float* __restrict__ stats,
    const float* __restrict__ in_g, const float* __restrict__ in_b,
    const float* __restrict__ wp, const float* __restrict__ bp,
    const float* __restrict__ n2g, const float* __restrict__ n2b,
    const float* __restrict__ mw1, const float* __restrict__ mb1,
    const float* __restrict__ mw2, const float* __restrict__ mb2,
    float* __restrict__ outbase) {
    __shared__ u64 s_wp2[512], s_m1a[512], s_m1b[512], s_m2[1024];
    __shared__ float s_bp[32], s_mb1[64], s_mb2[32], s_g[32], s_b[32], s_A[32], s_C[32];
    __shared__ __align__(16) float s_act[8][32];
    __shared__ __align__(16) float s_h[8][64];
    int tid = threadIdx.x;
    for (int idx = tid; idx < 512; idx += 256) {
        int i2 = idx >> 5, l = idx & 31;
        s_wp2[idx] = f2pack(wp[(2 * i2) * 32 + l], wp[(2 * i2 + 1) * 32 + l]);
        s_m1a[idx] = f2pack(mw1[(2 * i2) * 64 + l], mw1[(2 * i2 + 1) * 64 + l]);
        s_m1b[idx] = f2pack(mw1[(2 * i2) * 64 + 32 + l], mw1[(2 * i2 + 1) * 64 + 32 + l]);
    }
    for (int idx = tid; idx < 1024; idx += 256) {
        int i2 = idx >> 5, l = idx & 31;
        s_m2[idx] = f2pack(mw2[(2 * i2) * 32 + l], mw2[(2 * i2 + 1) * 32 + l]);
    }
    if (tid < 32) {
        s_bp[tid] = bp[tid]; s_mb2[tid] = mb2[tid]; s_g[tid] = n2g[tid]; s_b[tid] = n2b[tid];
        float A = stats[32 + tid] * in_g[tid];
        s_A[tid] = A;
        s_C[tid] = in_b[tid] - stats[tid] * A;
    }
    if (tid < 64) s_mb1[tid] = mb1[tid];
    __syncthreads();
    int z = blockIdx.y;
    const __nv_bfloat16* att = attbase + (size_t)z * HWP * 32;
    float* out = outbase + (size_t)z * HWP * 32;
    int lane = tid & 31, w = tid >> 5;
    int p = blockIdx.x * 8 + w;

    float scv = z ? (t4[p * 32 + lane] * s_A[lane] + s_C[lane]) : xhwc[p * 32 + lane];

    float a = __bfloat162float(att[p * 32 + lane]);
    s_act[w][lane] = a;
    __syncwarp();
    u64 acc = 0ULL;
#pragma unroll
    for (int i2 = 0; i2 < 16; i2++) {
        u64 x2 = *(const u64*)&s_act[w][2 * i2];
        acc = f2fma(x2, s_wp2[i2 * 32 + lane], acc);
    }
    float2 fy = f2unpack(acc);
    float y = fy.x + fy.y + s_bp[lane] + scv;

    float mean = warp_sum(y) * (1.f / 32.f);
    float dv = y - mean;
    float var = warp_sum(dv * dv) * (1.f / 32.f);
    float yn = dv * rsqrtf(var + 1e-5f) * s_g[lane] + s_b[lane];

    __syncwarp();
    s_act[w][lane] = yn;
    __syncwarp();
    u64 h0a = 0ULL, h1a = 0ULL;
#pragma unroll
    for (int i2 = 0; i2 < 16; i2++) {
        u64 x2 = *(const u64*)&s_act[w][2 * i2];
        h0a = f2fma(x2, s_m1a[i2 * 32 + lane], h0a);
        h1a = f2fma(x2, s_m1b[i2 * 32 + lane], h1a);
    }
    float2 f0 = f2unpack(h0a), f1 = f2unpack(h1a);
    float h0 = gelu_tanh(f0.x + f0.y + s_mb1[lane]);
    float h1 = gelu_tanh(f1.x + f1.y + s_mb1[lane + 32]);
    s_h[w][lane] = h0;
    s_h[w][32 + lane] = h1;
    __syncwarp();
    u64 r2 = 0ULL;
#pragma unroll
    for (int i2 = 0; i2 < 32; i2++) {
        u64 g2 = *(const u64*)&s_h[w][2 * i2];
        r2 = f2fma(g2, s_m2[i2 * 32 + lane], r2);
    }
    float2 fr = f2unpack(r2);
    out[p * 32 + lane] = y + fr.x + fr.y + s_mb2[lane];
}

// ---------------- K9: final sum, HWC -> CHW ----------------
__global__ void final_kernel(const float* __restrict__ obase,
                             const float* __restrict__ x, float* __restrict__ out) {
    __shared__ float sm[32][33];
    int p0 = blockIdx.x * 32;
    int tx = threadIdx.x, ty = threadIdx.y;
    const float* o1 = obase;
    const float* o2 = obase + (size_t)HWP * 32;
    for (int r = ty; r < 32; r += 8) {
        int p = p0 + r;
        sm[r][tx] = o1[p * 32 + tx] + o2[p * 32 + tx];
    }
    __syncthreads();
    for (int c = ty; c < 32; c += 8)
        out[c * HWP + p0 + tx] = sm[tx][c] + x[c * HWP + p0 + tx];
}

// ---------------- launch ----------------
extern "C" void kernel_launch(void* const* d_in, const int* in_sizes, int n_in,
                              void* d_out, int out_size) {
    const float* x    = (const float*)d_in[0];
    const float* dep  = (const float*)d_in[1];
    const int*   rpi  = (const int*)  d_in[2];
    const float* cw1  = (const float*)d_in[3];
    const float* cb1  = (const float*)d_in[4];
    const float* cw2  = (const float*)d_in[5];
    const float* cb2  = (const float*)d_in[6];
    const float* cw3  = (const float*)d_in[7];
    const float* cb3  = (const float*)d_in[8];
    const float* cw4  = (const float*)d_in[9];
    const float* cb4  = (const float*)d_in[10];
    const float* in_g = (const float*)d_in[11];
    const float* in_b = (const float*)d_in[12];
    const float* n1g  = (const float*)d_in[13];
    const float* n1b  = (const float*)d_in[14];
    const float* wq   = (const float*)d_in[15];
    const float* bq   = (const float*)d_in[16];
    const float* wkv  = (const float*)d_in[17];
    const float* bkv  = (const float*)d_in[18];
    const float* rpb  = (const float*)d_in[19];
    const float* wp   = (const float*)d_in[20];
    const float* bp   = (const float*)d_in[21];
    const float* n2g  = (const float*)d_in[22];
    const float* n2b  = (const float*)d_in[23];
    const float* mw1  = (const float*)d_in[24];
    const float* mb1  = (const float*)d_in[25];
    const float* mw2  = (const float*)d_in[26];
    const float* mb2  = (const float*)d_in[27];
    float* out = (float*)d_out;

    void *p_xhwc, *p_t2, *p_t4, *p_q, *p_kv, *p_att, *p_o, *p_bias, *p_stats, *p_part;
    cudaGetSymbolAddress(&p_xhwc, g_xhwc);
    cudaGetSymbolAddress(&p_t2, g_t2);
    cudaGetSymbolAddress(&p_t4, g_t4);
    cudaGetSymbolAddress(&p_q, g_qbf);
    cudaGetSymbolAddress(&p_kv, g_kvbf);
    cudaGetSymbolAddress(&p_att, g_attbf);
    cudaGetSymbolAddress(&p_o, g_o);
    cudaGetSymbolAddress(&p_bias, g_biasF);
    cudaGetSymbolAddress(&p_stats, g_stats);
    cudaGetSymbolAddress(&p_part, g_part);

    cudaFuncSetAttribute(attn_kernel, cudaFuncAttributeMaxDynamicSharedMemorySize, SMEM_ATTN);

    chw2hwc_kernel<<<2048, dim3(32, 8)>>>(x, (float*)p_xhwc);
    stem12_kernel<<<256, 256>>>(dep, cw1, cb1, cw2, cb2, (float*)p_t2);
    stem34_kernel<<<256, 256>>>((float*)p_t2, cw3, cb3, cw4, cb4, (float*)p_t4);
    inorm_part_kernel<<<512, 256>>>((float*)p_t4, (float*)p_part);
    inorm_final_kernel<<<1, 256>>>((float*)p_part, (float*)p_stats);
    build_biasF_kernel<<<288, 256>>>(rpi, rpb, (u64*)p_bias);

    ln_qkv_kernel<<<dim3(8192, 2), 256>>>((float*)p_xhwc, (float*)p_t4, (float*)p_stats,
                                          in_g, in_b, n1g, n1b, wq, bq, wkv, bkv,
                                          (__nv_bfloat16*)p_q, (__nv_bfloat16*)p_kv);
    attn_kernel<<<dim3(NWIN, 2, 2), 256, SMEM_ATTN>>>((__nv_bfloat16*)p_q,
                                                      (__nv_bfloat16*)p_kv,
                                                      (u64*)p_bias,
                                                      (__nv_bfloat16*)p_att);
    proj_mlp_kernel<<<dim3(8192, 2), 256>>>((__nv_bfloat16*)p_att, (float*)p_xhwc,
                                            (float*)p_t4, (float*)p_stats, in_g, in_b,
                                            wp, bp, n2g, n2b, mw1, mb1, mw2, mb2,
                                            (float*)p_o);

    final_kernel<<<2048, dim3(32, 8)>>>((float*)p_o, x, out);
}

// round 7
// speedup vs baseline: 3.0169x; 1.0505x over previous
#include <cuda_runtime.h>
#include <cuda_bf16.h>
#include <math.h>

// Problem constants: B=1, C=32, H=W=256, WS=16, OWS=24, NH=2, d=16
#define HWP   65536
#define NKEY  576
#define NQ    256
#define NWIN  256

typedef unsigned long long u64;
typedef unsigned int u32;

#define LOG2E 1.4426950408889634f

// attn smem layout
#define KSTRIDE 24
#define VSTRIDE 584
#define SMEM_K_BYTES (NKEY * KSTRIDE * 2)              // 27648
#define SMEM_ATTN    (SMEM_K_BYTES + 16 * VSTRIDE * 2) // 46336

// pixels per warp in ln_qkv / proj_mlp (weight-staging amortization)
#define PPW 8

// ---------------- scratch ----------------
__device__ float          g_xhwc [HWP * 32];
__device__ float          g_t2   [HWP * 16];
__device__ float          g_t4   [HWP * 32];
__device__ __nv_bfloat16  g_qbf  [2 * HWP * 32];
__device__ __nv_bfloat16  g_kvbf [2 * HWP * 64];
__device__ __nv_bfloat16  g_attbf[2 * HWP * 32];
__device__ float          g_o    [2 * HWP * 32];
__device__ u64            g_biasF[2 * NQ * 36 * 4];
__device__ float          g_stats[64];
__device__ float          g_part [512 * 64];

// ---------------- helpers ----------------
__device__ __forceinline__ u64 f2pack(float lo, float hi) {
    u64 r; asm("mov.b64 %0, {%1, %2};" : "=l"(r) : "f"(lo), "f"(hi)); return r;
}
__device__ __forceinline__ float2 f2unpack(u64 v) {
    float2 f; asm("mov.b64 {%0, %1}, %2;" : "=f"(f.x), "=f"(f.y) : "l"(v)); return f;
}
__device__ __forceinline__ u64 f2fma(u64 a, u64 b, u64 c) {
    u64 d; asm("fma.rn.f32x2 %0, %1, %2, %3;" : "=l"(d) : "l"(a), "l"(b), "l"(c)); return d;
}
__device__ __forceinline__ float ex2f(float x) {
    float y; asm("ex2.approx.f32 %0, %1;" : "=f"(y) : "f"(x)); return y;
}
__device__ __forceinline__ u32 bfpack(float lo, float hi) {
    u32 d; asm("cvt.rn.bf16x2.f32 %0, %1, %2;" : "=r"(d) : "f"(hi), "f"(lo)); return d;
}
__device__ __forceinline__ float warp_sum(float v) {
#pragma unroll
    for (int o = 16; o; o >>= 1) v += __shfl_xor_sync(0xffffffffu, v, o);
    return v;
}
__device__ __forceinline__ float gelu_tanh(float x) {
    float z = 0.7978845608028654f * (x + 0.044715f * x * x * x);
    float e = ex2f(2.8853900817779268f * z);
    float t = 1.f - __fdividef(2.f, e + 1.f);
    return 0.5f * x * (1.f + t);
}
__device__ __forceinline__ void mma_bf16(float* d, const u32* a, const u32* b, const float* c) {
    asm("mma.sync.aligned.m16n8k16.row.col.f32.bf16.bf16.f32 "
        "{%0,%1,%2,%3}, {%4,%5,%6,%7}, {%8,%9}, {%10,%11,%12,%13};"
        : "=f"(d[0]), "=f"(d[1]), "=f"(d[2]), "=f"(d[3])
        : "r"(a[0]), "r"(a[1]), "r"(a[2]), "r"(a[3]),
          "r"(b[0]), "r"(b[1]),
          "f"(c[0]), "f"(c[1]), "f"(c[2]), "f"(c[3]));
}

// ---------------- K0: CHW -> HWC transpose of x ----------------
__global__ void chw2hwc_kernel(const float* __restrict__ x, float* __restrict__ xh) {
    __shared__ float sm[32][33];
    int p0 = blockIdx.x * 32;
    int tx = threadIdx.x, ty = threadIdx.y;
    for (int c = ty; c < 32; c += 8) sm[c][tx] = x[c * HWP + p0 + tx];
    __syncthreads();
    for (int r = ty; r < 32; r += 8) xh[(p0 + r) * 32 + tx] = sm[tx][r];
}

// ---------------- K1: conv1+conv2 ----------------
__global__ __launch_bounds__(256) void stem12_kernel(
    const float* __restrict__ depth,
    const float* __restrict__ cw1, const float* __restrict__ cb1,
    const float* __restrict__ cw2, const float* __restrict__ cb2,
    float* __restrict__ t2) {
    __shared__ float w1[72], b1s[8], w2[128], b2s[16];
    int tid = threadIdx.x;
    if (tid < 72)  w1[tid]  = cw1[tid];
    if (tid < 8)   b1s[tid] = cb1[tid];
    if (tid < 128) w2[tid]  = cw2[tid];
    if (tid < 16)  b2s[tid] = cb2[tid];
    __syncthreads();
    int p = blockIdx.x * 256 + tid;
    int y = p >> 8, x = p & 255;
    float d[9];
#pragma unroll
    for (int tap = 0; tap < 9; tap++) {
        int yy = y + tap / 3 - 1, xx = x + tap % 3 - 1;
        d[tap] = ((unsigned)yy < 256u && (unsigned)xx < 256u) ? depth[(yy << 8) + xx] : 0.f;
    }
    float c1[8];
#pragma unroll
    for (int o = 0; o < 8; o++) {
        float a = b1s[o];
#pragma unroll
        for (int tap = 0; tap < 9; tap++) a += d[tap] * w1[o * 9 + tap];
        c1[o] = fmaxf(a, 0.f);
    }
    float* dst = t2 + p * 16;
#pragma unroll
    for (int o2 = 0; o2 < 16; o2++) {
        float a = b2s[o2];
#pragma unroll
        for (int o = 0; o < 8; o++) a += c1[o] * w2[o2 * 8 + o];
        dst[o2] = fmaxf(a, 0.f);
    }
}

// ---------------- K2: conv3+conv4, packed f32x2 ----------------
__global__ __launch_bounds__(256) void stem34_kernel(
    const float* __restrict__ t2,
    const float* __restrict__ cw3, const float* __restrict__ cb3,
    const float* __restrict__ cw4, const float* __restrict__ cb4,
    float* __restrict__ t4) {
    __shared__ u64 w3p[1152];
    __shared__ u64 w4p[256];
    __shared__ float b3[16], b4[32];
    int tid = threadIdx.x;
    for (int i = tid; i < 1152; i += 256) {
        int oc = i / 72, r = i - oc * 72, tap = r >> 3, ic2 = r & 7;
        w3p[i] = f2pack(cw3[oc * 144 + (2 * ic2) * 9 + tap],
                        cw3[oc * 144 + (2 * ic2 + 1) * 9 + tap]);
    }
    if (tid < 256) {
        int c4 = tid >> 3, o2 = tid & 7;
        w4p[tid] = f2pack(cw4[c4 * 16 + 2 * o2], cw4[c4 * 16 + 2 * o2 + 1]);
    }
    if (tid < 16) b3[tid] = cb3[tid];
    if (tid < 32) b4[tid] = cb4[tid];
    __syncthreads();
    int p = blockIdx.x * 256 + tid;
    int y = p >> 8, x = p & 255;
    u64 acc2[16];
#pragma unroll
    for (int i = 0; i < 16; i++) acc2[i] = 0ULL;
#pragma unroll 1
    for (int tap = 0; tap < 9; tap++) {
        int yy = y + tap / 3 - 1, xx = x + tap % 3 - 1;
        if ((unsigned)yy < 256u && (unsigned)xx < 256u) {
            const float4* src = (const float4*)(t2 + (((yy << 8) + xx) << 4));
            float4 i0 = src[0], i1 = src[1], i2v = src[2], i3 = src[3];
            u64 in2[8] = {f2pack(i0.x, i0.y), f2pack(i0.z, i0.w),
                          f2pack(i1.x, i1.y), f2pack(i1.z, i1.w),
                          f2pack(i2v.x, i2v.y), f2pack(i2v.z, i2v.w),
                          f2pack(i3.x, i3.y), f2pack(i3.z, i3.w)};
            const u64* wt = &w3p[tap * 8];
#pragma unroll
            for (int oc = 0; oc < 16; oc++) {
                const u64* wr = wt + oc * 72;
#pragma unroll
                for (int k = 0; k < 8; k++) acc2[oc] = f2fma(in2[k], wr[k], acc2[oc]);
            }
        }
    }
    float c3[16];
#pragma unroll
    for (int oc = 0; oc < 16; oc++) {
        float2 f = f2unpack(acc2[oc]);
        c3[oc] = fmaxf(f.x + f.y + b3[oc], 0.f);
    }
    u64 a2[8];
#pragma unroll
    for (int o2 = 0; o2 < 8; o2++) a2[o2] = f2pack(c3[2 * o2], c3[2 * o2 + 1]);
    float* dst = t4 + (size_t)p * 32;
#pragma unroll
    for (int c4 = 0; c4 < 32; c4++) {
        u64 r = 0ULL;
#pragma unroll
        for (int o2 = 0; o2 < 8; o2++) r = f2fma(a2[o2], w4p[c4 * 8 + o2], r);
        float2 f = f2unpack(r);
        dst[c4] = f.x + f.y + b4[c4];
    }
}

// ---------------- K3a: instance-norm partial sums ----------------
__global__ __launch_bounds__(256) void inorm_part_kernel(const float* __restrict__ t4,
                                                         float* __restrict__ part) {
    int tid = threadIdx.x;
    size_t base = (size_t)blockIdx.x * 4096;
    float s[4] = {0, 0, 0, 0}, s2[4] = {0, 0, 0, 0};
    const float4* src = (const float4*)(t4 + base);
#pragma unroll
    for (int it = 0; it < 4; it++) {
        float4 v = src[it * 256 + tid];
        s[0] += v.x; s2[0] += v.x * v.x;
        s[1] += v.y; s2[1] += v.y * v.y;
        s[2] += v.z; s2[2] += v.z * v.z;
        s[3] += v.w; s2[3] += v.w * v.w;
    }
    __shared__ float sa[256][4], sb[256][4];
#pragma unroll
    for (int k = 0; k < 4; k++) { sa[tid][k] = s[k]; sb[tid][k] = s2[k]; }
    __syncthreads();
    if (tid < 32) {
        int grp = tid >> 2, k = tid & 3;
        float a = 0.f, b = 0.f;
#pragma unroll
        for (int t8 = 0; t8 < 32; t8++) {
            a += sa[t8 * 8 + grp][k];
            b += sb[t8 * 8 + grp][k];
        }
        part[blockIdx.x * 64 + tid] = a;
        part[blockIdx.x * 64 + 32 + tid] = b;
    }
}

// ---------------- K3b: instance-norm final reduce ----------------
__global__ __launch_bounds__(256) void inorm_final_kernel(const float* __restrict__ part,
                                                          float* __restrict__ stats) {
    int c = threadIdx.x & 31, g = threadIdx.x >> 5;
    double a = 0.0, b = 0.0;
    for (int blk = g; blk < 512; blk += 8) {
        a += (double)part[blk * 64 + c];
        b += (double)part[blk * 64 + 32 + c];
    }
    __shared__ double sa[8][32], sb[8][32];
    sa[g][c] = a; sb[g][c] = b;
    __syncthreads();
    if (threadIdx.x < 32) {
        double s = 0.0, s2 = 0.0;
#pragma unroll
        for (int k = 0; k < 8; k++) { s += sa[k][threadIdx.x]; s2 += sb[k][threadIdx.x]; }
        double mean = s / (double)HWP;
        double var = s2 / (double)HWP - mean * mean;
        stats[threadIdx.x] = (float)mean;
        stats[32 + threadIdx.x] = rsqrtf((float)var + 1e-5f);
    }
}

// ---------------- K5: bias fragments ----------------
__global__ void build_biasF_kernel(const int* __restrict__ rpi, const float* __restrict__ rpb,
                                   u64* __restrict__ biasF) {
    int idx = blockIdx.x * 256 + threadIdx.x;
    int tig = idx & 3;
    int t2 = idx >> 2;
    int ch = t2 % 36;
    int t3 = t2 / 36;
    int q = t3 & 255;
    int h = t3 >> 8;
    int k0 = ch * 16 + 2 * tig;
    u64 r = 0;
#pragma unroll
    for (int e = 0; e < 4; e++) {
        int k = k0 + (e >> 1) * 8 + (e & 1);
        float v = rpb[rpi[q * NKEY + k] * 2 + h] * LOG2E;
        unsigned short us = __bfloat16_as_ushort(__float2bfloat16(v));
        r |= (u64)us << (16 * e);
    }
    biasF[idx] = r;
}

// ---------------- K6: LN + q/kv projections; warp loops over PPW pixels ----------------
__global__ __launch_bounds__(256) void ln_qkv_kernel(
    const float* __restrict__ xhwc, const float* __restrict__ t4,
    const float* __restrict__ stats,
    const float* __restrict__ in_g, const float* __restrict__ in_b,
    const float* __restrict__ n1g, const float* __restrict__ n1b,
    const float* __restrict__ wq, const float* __restrict__ bq,
    const float* __restrict__ wkv, const float* __restrict__ bkv,
    __nv_bfloat16* __restrict__ qbase, __nv_bfloat16* __restrict__ kvbase) {
    __shared__ u64 s_wq2[512], s_wk2[512], s_wv2[512];
    __shared__ float s_bq[32], s_bkv[64], s_g[32], s_b[32], s_A[32], s_C[32];
    __shared__ __align__(16) float s_act[8][32];
    int tid = threadIdx.x;
    for (int idx = tid; idx < 512; idx += 256) {
        int i2 = idx >> 5, l = idx & 31;
        s_wq2[idx] = f2pack(wq[(2 * i2) * 32 + l], wq[(2 * i2 + 1) * 32 + l]);
        s_wk2[idx] = f2pack(wkv[(2 * i2) * 64 + l], wkv[(2 * i2 + 1) * 64 + l]);
        s_wv2[idx] = f2pack(wkv[(2 * i2) * 64 + 32 + l], wkv[(2 * i2 + 1) * 64 + 32 + l]);
    }
    if (tid < 32) {
        s_bq[tid] = bq[tid]; s_g[tid] = n1g[tid]; s_b[tid] = n1b[tid];
        float A = stats[32 + tid] * in_g[tid];
        s_A[tid] = A;
        s_C[tid] = in_b[tid] - stats[tid] * A;
    }
    if (tid < 64) s_bkv[tid] = bkv[tid];
    __syncthreads();
    int z = blockIdx.y;
    __nv_bfloat16* qo  = qbase  + (size_t)z * HWP * 32;
    __nv_bfloat16* kvo = kvbase + (size_t)z * HWP * 64;
    int lane = tid & 31, w = tid >> 5;
    int pbase = blockIdx.x * (8 * PPW) + w * PPW;
    const float QS = 0.25f * LOG2E;

#pragma unroll 1
    for (int it = 0; it < PPW; it++) {
        int p = pbase + it;
        float xv_x = xhwc[p * 32 + lane];
        float fv   = t4[p * 32 + lane] * s_A[lane] + s_C[lane];
        {
            float xv = z ? fv : xv_x;
            float mean = warp_sum(xv) * (1.f / 32.f);
            float dv = xv - mean;
            float var = warp_sum(dv * dv) * (1.f / 32.f);
            float xn = dv * rsqrtf(var + 1e-5f) * s_g[lane] + s_b[lane];
            s_act[w][lane] = xn;
            __syncwarp();
            u64 acc = 0ULL;
#pragma unroll
            for (int i2 = 0; i2 < 16; i2++) {
                u64 x2 = *(const u64*)&s_act[w][2 * i2];
                acc = f2fma(x2, s_wq2[i2 * 32 + lane], acc);
            }
            float2 ff = f2unpack(acc);
            qo[p * 32 + lane] = __float2bfloat16((ff.x + ff.y + s_bq[lane]) * QS);
            __syncwarp();
        }
        {
            float xv = z ? xv_x : fv;
            float mean = warp_sum(xv) * (1.f / 32.f);
            float dv = xv - mean;
            float var = warp_sum(dv * dv) * (1.f / 32.f);
            float xn = dv * rsqrtf(var + 1e-5f) * s_g[lane] + s_b[lane];
            s_act[w][lane] = xn;
            __syncwarp();
            u64 ak = 0ULL, av = 0ULL;
#pragma unroll
            for (int i2 = 0; i2 < 16; i2++) {
                u64 x2 = *(const u64*)&s_act[w][2 * i2];
                ak = f2fma(x2, s_wk2[i2 * 32 + lane], ak);
                av = f2fma(x2, s_wv2[i2 * 32 + lane], av);
            }
            float2 fk = f2unpack(ak), fv2 = f2unpack(av);
            kvo[p * 64 + lane]      = __float2bfloat16(fk.x + fk.y + s_bkv[lane]);
            kvo[p * 64 + 32 + lane] = __float2bfloat16(fv2.x + fv2.y + s_bkv[lane + 32]);
            __syncwarp();
        }
    }
}

// ---------------- K7: flash attention via mma.sync bf16, bf16 I/O ----------------
__global__ __launch_bounds__(256) void attn_kernel(
    const __nv_bfloat16* __restrict__ qbase, const __nv_bfloat16* __restrict__ kvbase,
    const u64* __restrict__ biasF, __nv_bfloat16* __restrict__ outbase) {
    extern __shared__ __align__(16) char smraw[];
    __nv_bfloat16* ksm = (__nv_bfloat16*)smraw;
    __nv_bfloat16* vsm = (__nv_bfloat16*)(smraw + SMEM_K_BYTES);
    int win = blockIdx.x, head = blockIdx.y, z = blockIdx.z;
    const __nv_bfloat16* q   = qbase   + (size_t)z * HWP * 32;
    const __nv_bfloat16* kv  = kvbase  + (size_t)z * HWP * 64;
    __nv_bfloat16*       out = outbase + (size_t)z * HWP * 32;
    int wy = win >> 4, wx = win & 15;
    int t = threadIdx.x;
    int warp = t >> 5, lane = t & 31;
    int gid = lane >> 2, tig = lane & 3;

    for (int j = t; j < NKEY; j += 256) {
        int jy = j / 24, jx = j - jy * 24;
        int yy = (wy << 4) - 4 + jy, xx = (wx << 4) - 4 + jx;
        uint4 k0 = make_uint4(0, 0, 0, 0), k1 = k0, v0 = k0, v1 = k0;
        if ((unsigned)yy < 256u && (unsigned)xx < 256u) {
            const __nv_bfloat16* base = kv + ((size_t)((yy << 8) + xx) << 6) + (head << 4);
            k0 = *(const uint4*)base;
            k1 = *(const uint4*)(base + 8);
            v0 = *(const uint4*)(base + 32);
            v1 = *(const uint4*)(base + 40);
        }
        *(uint4*)(ksm + j * KSTRIDE)     = k0;
        *(uint4*)(ksm + j * KSTRIDE + 8) = k1;
        u32 vw[8] = {v0.x, v0.y, v0.z, v0.w, v1.x, v1.y, v1.z, v1.w};
#pragma unroll
        for (int i = 0; i < 8; i++) {
            __nv_bfloat162 pr = *(const __nv_bfloat162*)&vw[i];
            vsm[(2 * i) * VSTRIDE + j]     = pr.x;
            vsm[(2 * i + 1) * VSTRIDE + j] = pr.y;
        }
    }

    u32 qa[2][4];
    int qwb = warp * 32;
#pragma unroll
    for (int m = 0; m < 2; m++) {
        int r0 = qwb + m * 16 + gid;
        int r1 = r0 + 8;
        int px0 = ((wy << 4) + (r0 >> 4)) * 256 + (wx << 4) + (r0 & 15);
        int px1 = ((wy << 4) + (r1 >> 4)) * 256 + (wx << 4) + (r1 & 15);
        const __nv_bfloat16* q0p = q + (size_t)px0 * 32 + (head << 4);
        const __nv_bfloat16* q1p = q + (size_t)px1 * 32 + (head << 4);
        qa[m][0] = *(const u32*)(q0p + 2 * tig);
        qa[m][1] = *(const u32*)(q1p + 2 * tig);
        qa[m][2] = *(const u32*)(q0p + 8 + 2 * tig);
        qa[m][3] = *(const u32*)(q1p + 8 + 2 * tig);
    }
    __syncthreads();

    float o[2][2][4];
#pragma unroll
    for (int m = 0; m < 2; m++)
#pragma unroll
        for (int d = 0; d < 2; d++)
#pragma unroll
            for (int i = 0; i < 4; i++) o[m][d][i] = 0.f;
    float l4[4] = {0.f, 0.f, 0.f, 0.f};

    const u64* bF = biasF + ((size_t)head << 8) * 144;

#pragma unroll 2
    for (int ch = 0; ch < 36; ch++) {
        int kb = ch * 16;
        u32 kf[2][2];
#pragma unroll
        for (int nt = 0; nt < 2; nt++) {
            const __nv_bfloat16* kr = ksm + (kb + nt * 8 + gid) * KSTRIDE + 2 * tig;
            kf[nt][0] = *(const u32*)kr;
            kf[nt][1] = *(const u32*)(kr + 8);
        }
        u32 vb[2][2];
#pragma unroll
        for (int dt = 0; dt < 2; dt++) {
            const __nv_bfloat16* vr = vsm + (dt * 8 + gid) * VSTRIDE + kb + 2 * tig;
            vb[dt][0] = *(const u32*)vr;
            vb[dt][1] = *(const u32*)(vr + 8);
        }
        u64 bw[4];
#pragma unroll
        for (int r4 = 0; r4 < 4; r4++) {
            int qrow = qwb + ((r4 >> 1) << 4) + ((r4 & 1) << 3) + gid;
            bw[r4] = bF[(qrow * 36 + ch) * 4 + tig];
        }
#pragma unroll
        for (int m = 0; m < 2; m++) {
            float c0[4] = {0.f, 0.f, 0.f, 0.f}, c1[4] = {0.f, 0.f, 0.f, 0.f};
            mma_bf16(c0, qa[m], kf[0], c0);
            mma_bf16(c1, qa[m], kf[1], c1);
            u32 bAlo = (u32)bw[m * 2],     bAhi = (u32)(bw[m * 2] >> 32);
            u32 bBlo = (u32)bw[m * 2 + 1], bBhi = (u32)(bw[m * 2 + 1] >> 32);
            float p00 = ex2f(fminf(c0[0] + __int_as_float(bAlo << 16), 80.f));
            float p01 = ex2f(fminf(c0[1] + __int_as_float((int)(bAlo & 0xffff0000u)), 80.f));
            float p02 = ex2f(fminf(c0[2] + __int_as_float(bBlo << 16), 80.f));
            float p03 = ex2f(fminf(c0[3] + __int_as_float((int)(bBlo & 0xffff0000u)), 80.f));
            float p10 = ex2f(fminf(c1[0] + __int_as_float(bAhi << 16), 80.f));
            float p11 = ex2f(fminf(c1[1] + __int_as_float((int)(bAhi & 0xffff0000u)), 80.f));
            float p12 = ex2f(fminf(c1[2] + __int_as_float(bBhi << 16), 80.f));
            float p13 = ex2f(fminf(c1[3] + __int_as_float((int)(bBhi & 0xffff0000u)), 80.f));
            l4[m * 2]     += (p00 + p01) + (p10 + p11);
            l4[m * 2 + 1] += (p02 + p03) + (p12 + p13);
            u32 pa[4];
            pa[0] = bfpack(p00, p01);
            pa[1] = bfpack(p02, p03);
            pa[2] = bfpack(p10, p11);
            pa[3] = bfpack(p12, p13);
            mma_bf16(o[m][0], pa, vb[0], o[m][0]);
            mma_bf16(o[m][1], pa, vb[1], o[m][1]);
        }
    }

#pragma unroll
    for (int r4 = 0; r4 < 4; r4++) {
        l4[r4] += __shfl_xor_sync(0xffffffffu, l4[r4], 1);
        l4[r4] += __shfl_xor_sync(0xffffffffu, l4[r4], 2);
        l4[r4] = 1.f / l4[r4];
    }

#pragma unroll
    for (int m = 0; m < 2; m++) {
        int r0 = qwb + m * 16 + gid;
        int r1 = r0 + 8;
        int px0 = ((wy << 4) + (r0 >> 4)) * 256 + (wx << 4) + (r0 & 15);
        int px1 = ((wy << 4) + (r1 >> 4)) * 256 + (wx << 4) + (r1 & 15);
        __nv_bfloat16* o0p = out + (size_t)px0 * 32 + (head << 4);
        __nv_bfloat16* o1p = out + (size_t)px1 * 32 + (head << 4);
        float i0 = l4[m * 2], i1 = l4[m * 2 + 1];
#pragma unroll
        for (int dt = 0; dt < 2; dt++) {
            *(u32*)(o0p + dt * 8 + 2 * tig) = bfpack(o[m][dt][0] * i0, o[m][dt][1] * i0);
            *(u32*)(o1p + dt * 8 + 2 * tig) = bfpack(o[m][dt][2] * i1, o[m][dt][3] * i1);
        }
    }
}

// ---------------- K8: out-proj + shortcut + LN + MLP(gelu); warp loops over PPW pixels --------
__global__ __launch_bounds__(256) void proj_mlp_kernel(
    const __nv_bfloat16* __restrict__ attbase,
    const float* __restrict__ xhwc, const float* __restrict__ t4,
    const float* __restrict__ stats,
    const float* __restrict__ in_g, const float* __restrict__ in_b,
    const float* __restrict__ wp, const float* __restrict__ bp,
    const float* __restrict__ n2g, const float* __restrict__ n2b,
    const float* __restrict__ mw1, const float* __restrict__ mb1,
    const float* __restrict__ mw2, const float* __restrict__ mb2,
    float* __restrict__ outbase) {
    __shared__ u64 s_wp2[512], s_m1a[512], s_m1b[512], s_m2[1024];
    __shared__ float s_bp[32], s_mb1[64], s_mb2[32], s_g[32], s_b[32], s_A[32], s_C[32];
    __shared__ __align__(16) float s_act[8][32];
    __shared__ __align__(16) float s_h[8][64];
    int tid = threadIdx.x;
    for (int idx = tid; idx < 512; idx += 256) {
        int i2 = idx >> 5, l = idx & 31;
        s_wp2[idx] = f2pack(wp[(2 * i2) * 32 + l], wp[(2 * i2 + 1) * 32 + l]);
        s_m1a[idx] = f2pack(mw1[(2 * i2) * 64 + l], mw1[(2 * i2 + 1) * 64 + l]);
        s_m1b[idx] = f2pack(mw1[(2 * i2) * 64 + 32 + l], mw1[(2 * i2 + 1) * 64 + 32 + l]);
    }
    for (int idx = tid; idx < 1024; idx += 256) {
        int i2 = idx >> 5, l = idx & 31;
        s_m2[idx] = f2pack(mw2[(2 * i2) * 32 + l], mw2[(2 * i2 + 1) * 32 + l]);
    }
    if (tid < 32) {
        s_bp[tid] = bp[tid]; s_mb2[tid] = mb2[tid]; s_g[tid] = n2g[tid]; s_b[tid] = n2b[tid];
        float A = stats[32 + tid] * in_g[tid];
        s_A[tid] = A;
        s_C[tid] = in_b[tid] - stats[tid] * A;
    }
    if (tid < 64) s_mb1[tid] = mb1[tid];
    __syncthreads();
    int z = blockIdx.y;
    const __nv_bfloat16* att = attbase + (size_t)z * HWP * 32;
    float* out = outbase + (size_t)z * HWP * 32;
    int lane = tid & 31, w = tid >> 5;
    int pbase = blockIdx.x * (8 * PPW) + w * PPW;

#pragma unroll 1
    for (int it = 0; it < PPW; it++) {
        int p = pbase + it;
        float scv = z ? (t4[p * 32 + lane] * s_A[lane] + s_C[lane]) : xhwc[p * 32 + lane];

        float a = __bfloat162float(att[p * 32 + lane]);
        s_act[w][lane] = a;
        __syncwarp();
        u64 acc = 0ULL;
#pragma unroll
        for (int i2 = 0; i2 < 16; i2++) {
            u64 x2 = *(const u64*)&s_act[w][2 * i2];
            acc = f2fma(x2, s_wp2[i2 * 32 + lane], acc);
        }
        float2 fy = f2unpack(acc);
        float y = fy.x + fy.y + s_bp[lane] + scv;

        float mean = warp_sum(y) * (1.f / 32.f);
        float dv = y - mean;
        float var = warp_sum(dv * dv) * (1.f / 32.f);
        float yn = dv * rsqrtf(var + 1e-5f) * s_g[lane] + s_b[lane];

        __syncwarp();
        s_act[w][lane] = yn;
        __syncwarp();
        u64 h0a = 0ULL, h1a = 0ULL;
#pragma unroll
        for (int i2 = 0; i2 < 16; i2++) {
            u64 x2 = *(const u64*)&s_act[w][2 * i2];
            h0a = f2fma(x2, s_m1a[i2 * 32 + lane], h0a);
            h1a = f2fma(x2, s_m1b[i2 * 32 + lane], h1a);
        }
        float2 f0 = f2unpack(h0a), f1 = f2unpack(h1a);
        float h0 = gelu_tanh(f0.x + f0.y + s_mb1[lane]);
        float h1 = gelu_tanh(f1.x + f1.y + s_mb1[lane + 32]);
        s_h[w][lane] = h0;
        s_h[w][32 + lane] = h1;
        __syncwarp();
        u64 r2 = 0ULL;
#pragma unroll
        for (int i2 = 0; i2 < 32; i2++) {
            u64 g2 = *(const u64*)&s_h[w][2 * i2];
            r2 = f2fma(g2, s_m2[i2 * 32 + lane], r2);
        }
        float2 fr = f2unpack(r2);
        out[p * 32 + lane] = y + fr.x + fr.y + s_mb2[lane];
        __syncwarp();
    }
}

// ---------------- K9: final sum, HWC -> CHW ----------------
__global__ void final_kernel(const float* __restrict__ obase,
                             const float* __restrict__ x, float* __restrict__ out) {
    __shared__ float sm[32][33];
    int p0 = blockIdx.x * 32;
    int tx = threadIdx.x, ty = threadIdx.y;
    const float* o1 = obase;
    const float* o2 = obase + (size_t)HWP * 32;
    for (int r = ty; r < 32; r += 8) {
        int p = p0 + r;
        sm[r][tx] = o1[p * 32 + tx] + o2[p * 32 + tx];
    }
    __syncthreads();
    for (int c = ty; c < 32; c += 8)
        out[c * HWP + p0 + tx] = sm[tx][c] + x[c * HWP + p0 + tx];
}

// ---------------- launch ----------------
extern "C" void kernel_launch(void* const* d_in, const int* in_sizes, int n_in,
                              void* d_out, int out_size) {
    const float* x    = (const float*)d_in[0];
    const float* dep  = (const float*)d_in[1];
    const int*   rpi  = (const int*)  d_in[2];
    const float* cw1  = (const float*)d_in[3];
    const float* cb1  = (const float*)d_in[4];
    const float* cw2  = (const float*)d_in[5];
    const float* cb2  = (const float*)d_in[6];
    const float* cw3  = (const float*)d_in[7];
    const float* cb3  = (const float*)d_in[8];
    const float* cw4  = (const float*)d_in[9];
    const float* cb4  = (const float*)d_in[10];
    const float* in_g = (const float*)d_in[11];
    const float* in_b = (const float*)d_in[12];
    const float* n1g  = (const float*)d_in[13];
    const float* n1b  = (const float*)d_in[14];
    const float* wq   = (const float*)d_in[15];
    const float* bq   = (const float*)d_in[16];
    const float* wkv  = (const float*)d_in[17];
    const float* bkv  = (const float*)d_in[18];
    const float* rpb  = (const float*)d_in[19];
    const float* wp   = (const float*)d_in[20];
    const float* bp   = (const float*)d_in[21];
    const float* n2g  = (const float*)d_in[22];
    const float* n2b  = (const float*)d_in[23];
    const float* mw1  = (const float*)d_in[24];
    const float* mb1  = (const float*)d_in[25];
    const float* mw2  = (const float*)d_in[26];
    const float* mb2  = (const float*)d_in[27];
    float* out = (float*)d_out;

    void *p_xhwc, *p_t2, *p_t4, *p_q, *p_kv, *p_att, *p_o, *p_bias, *p_stats, *p_part;
    cudaGetSymbolAddress(&p_xhwc, g_xhwc);
    cudaGetSymbolAddress(&p_t2, g_t2);
    cudaGetSymbolAddress(&p_t4, g_t4);
    cudaGetSymbolAddress(&p_q, g_qbf);
    cudaGetSymbolAddress(&p_kv, g_kvbf);
    cudaGetSymbolAddress(&p_att, g_attbf);
    cudaGetSymbolAddress(&p_o, g_o);
    cudaGetSymbolAddress(&p_bias, g_biasF);
    cudaGetSymbolAddress(&p_stats, g_stats);
    cudaGetSymbolAddress(&p_part, g_part);

    cudaFuncSetAttribute(attn_kernel, cudaFuncAttributeMaxDynamicSharedMemorySize, SMEM_ATTN);

    chw2hwc_kernel<<<2048, dim3(32, 8)>>>(x, (float*)p_xhwc);
    stem12_kernel<<<256, 256>>>(dep, cw1, cb1, cw2, cb2, (float*)p_t2);
    stem34_kernel<<<256, 256>>>((float*)p_t2, cw3, cb3, cw4, cb4, (float*)p_t4);
    inorm_part_kernel<<<512, 256>>>((float*)p_t4, (float*)p_part);
    inorm_final_kernel<<<1, 256>>>((float*)p_part, (float*)p_stats);
    build_biasF_kernel<<<288, 256>>>(rpi, rpb, (u64*)p_bias);

    ln_qkv_kernel<<<dim3(HWP / (8 * PPW), 2), 256>>>(
        (float*)p_xhwc, (float*)p_t4, (float*)p_stats, in_g, in_b, n1g, n1b,
        wq, bq, wkv, bkv, (__nv_bfloat16*)p_q, (__nv_bfloat16*)p_kv);
    attn_kernel<<<dim3(NWIN, 2, 2), 256, SMEM_ATTN>>>((__nv_bfloat16*)p_q,
                                                      (__nv_bfloat16*)p_kv,
                                                      (u64*)p_bias,
                                                      (__nv_bfloat16*)p_att);
    proj_mlp_kernel<<<dim3(HWP / (8 * PPW), 2), 256>>>(
        (__nv_bfloat16*)p_att, (float*)p_xhwc, (float*)p_t4, (float*)p_stats,
        in_g, in_b, wp, bp, n2g, n2b, mw1, mb1, mw2, mb2, (float*)p_o);

    final_kernel<<<2048, dim3(32, 8)>>>((float*)p_o, x, out);
}

// round 8
// speedup vs baseline: 3.0946x; 1.0258x over previous
#include <cuda_runtime.h>
#include <cuda_bf16.h>
#include <math.h>

// Problem constants: B=1, C=32, H=W=256, WS=16, OWS=24, NH=2, d=16
#define HWP   65536
#define NKEY  576
#define NQ    256
#define NWIN  256

typedef unsigned long long u64;
typedef unsigned int u32;

#define LOG2E 1.4426950408889634f

// attn smem layout (both z resident)
#define KSTRIDE 24
#define VSTRIDE 584
#define KBYTES (NKEY * KSTRIDE * 2)          // 27648
#define VBYTES (16 * VSTRIDE * 2)            // 18688
#define SMEM_ATTN (2 * KBYTES + 2 * VBYTES)  // 92672

#define PPW 8

// ---------------- scratch ----------------
__device__ float          g_xhwc [HWP * 32];
__device__ float          g_t2   [HWP * 16];
__device__ float          g_t4   [HWP * 32];
__device__ __nv_bfloat16  g_qbf  [2 * HWP * 32];
__device__ __nv_bfloat16  g_kvbf [2 * HWP * 64];
__device__ __nv_bfloat16  g_attbf[2 * HWP * 32];
__device__ float          g_o    [HWP * 32];
__device__ u64            g_biasF[2 * NQ * 36 * 4];
__device__ float          g_stats[64];
__device__ float          g_part [512 * 64];

// ---------------- helpers ----------------
__device__ __forceinline__ u64 f2pack(float lo, float hi) {
    u64 r; asm("mov.b64 %0, {%1, %2};" : "=l"(r) : "f"(lo), "f"(hi)); return r;
}
__device__ __forceinline__ float2 f2unpack(u64 v) {
    float2 f; asm("mov.b64 {%0, %1}, %2;" : "=f"(f.x), "=f"(f.y) : "l"(v)); return f;
}
__device__ __forceinline__ u64 f2fma(u64 a, u64 b, u64 c) {
    u64 d; asm("fma.rn.f32x2 %0, %1, %2, %3;" : "=l"(d) : "l"(a), "l"(b), "l"(c)); return d;
}
__device__ __forceinline__ float ex2f(float x) {
    float y; asm("ex2.approx.f32 %0, %1;" : "=f"(y) : "f"(x)); return y;
}
__device__ __forceinline__ u32 bfpack(float lo, float hi) {
    u32 d; asm("cvt.rn.bf16x2.f32 %0, %1, %2;" : "=r"(d) : "f"(hi), "f"(lo)); return d;
}
__device__ __forceinline__ float warp_sum(float v) {
#pragma unroll
    for (int o = 16; o; o >>= 1) v += __shfl_xor_sync(0xffffffffu, v, o);
    return v;
}
__device__ __forceinline__ float gelu_tanh(float x) {
    float z = 0.7978845608028654f * (x + 0.044715f * x * x * x);
    float e = ex2f(2.8853900817779268f * z);
    float t = 1.f - __fdividef(2.f, e + 1.f);
    return 0.5f * x * (1.f + t);
}
__device__ __forceinline__ void mma_bf16(float* d, const u32* a, const u32* b, const float* c) {
    asm("mma.sync.aligned.m16n8k16.row.col.f32.bf16.bf16.f32 "
        "{%0,%1,%2,%3}, {%4,%5,%6,%7}, {%8,%9}, {%10,%11,%12,%13};"
        : "=f"(d[0]), "=f"(d[1]), "=f"(d[2]), "=f"(d[3])
        : "r"(a[0]), "r"(a[1]), "r"(a[2]), "r"(a[3]),
          "r"(b[0]), "r"(b[1]),
          "f"(c[0]), "f"(c[1]), "f"(c[2]), "f"(c[3]));
}

// ---------------- K0: CHW -> HWC transpose of x ----------------
__global__ void chw2hwc_kernel(const float* __restrict__ x, float* __restrict__ xh) {
    __shared__ float sm[32][33];
    int p0 = blockIdx.x * 32;
    int tx = threadIdx.x, ty = threadIdx.y;
    for (int c = ty; c < 32; c += 8) sm[c][tx] = x[c * HWP + p0 + tx];
    __syncthreads();
    for (int r = ty; r < 32; r += 8) xh[(p0 + r) * 32 + tx] = sm[tx][r];
}

// ---------------- K1: conv1+conv2 ----------------
__global__ __launch_bounds__(256) void stem12_kernel(
    const float* __restrict__ depth,
    const float* __restrict__ cw1, const float* __restrict__ cb1,
    const float* __restrict__ cw2, const float* __restrict__ cb2,
    float* __restrict__ t2) {
    __shared__ float w1[72], b1s[8], w2[128], b2s[16];
    int tid = threadIdx.x;
    if (tid < 72)  w1[tid]  = cw1[tid];
    if (tid < 8)   b1s[tid] = cb1[tid];
    if (tid < 128) w2[tid]  = cw2[tid];
    if (tid < 16)  b2s[tid] = cb2[tid];
    __syncthreads();
    int p = blockIdx.x * 256 + tid;
    int y = p >> 8, x = p & 255;
    float d[9];
#pragma unroll
    for (int tap = 0; tap < 9; tap++) {
        int yy = y + tap / 3 - 1, xx = x + tap % 3 - 1;
        d[tap] = ((unsigned)yy < 256u && (unsigned)xx < 256u) ? depth[(yy << 8) + xx] : 0.f;
    }
    float c1[8];
#pragma unroll
    for (int o = 0; o < 8; o++) {
        float a = b1s[o];
#pragma unroll
        for (int tap = 0; tap < 9; tap++) a += d[tap] * w1[o * 9 + tap];
        c1[o] = fmaxf(a, 0.f);
    }
    float* dst = t2 + p * 16;
#pragma unroll
    for (int o2 = 0; o2 < 16; o2++) {
        float a = b2s[o2];
#pragma unroll
        for (int o = 0; o < 8; o++) a += c1[o] * w2[o2 * 8 + o];
        dst[o2] = fmaxf(a, 0.f);
    }
}

// ---------------- K2: conv3+conv4, packed f32x2 ----------------
__global__ __launch_bounds__(256) void stem34_kernel(
    const float* __restrict__ t2,
    const float* __restrict__ cw3, const float* __restrict__ cb3,
    const float* __restrict__ cw4, const float* __restrict__ cb4,
    float* __restrict__ t4) {
    __shared__ u64 w3p[1152];
    __shared__ u64 w4p[256];
    __shared__ float b3[16], b4[32];
    int tid = threadIdx.x;
    for (int i = tid; i < 1152; i += 256) {
        int oc = i / 72, r = i - oc * 72, tap = r >> 3, ic2 = r & 7;
        w3p[i] = f2pack(cw3[oc * 144 + (2 * ic2) * 9 + tap],
                        cw3[oc * 144 + (2 * ic2 + 1) * 9 + tap]);
    }
    if (tid < 256) {
        int c4 = tid >> 3, o2 = tid & 7;
        w4p[tid] = f2pack(cw4[c4 * 16 + 2 * o2], cw4[c4 * 16 + 2 * o2 + 1]);
    }
    if (tid < 16) b3[tid] = cb3[tid];
    if (tid < 32) b4[tid] = cb4[tid];
    __syncthreads();
    int p = blockIdx.x * 256 + tid;
    int y = p >> 8, x = p & 255;
    u64 acc2[16];
#pragma unroll
    for (int i = 0; i < 16; i++) acc2[i] = 0ULL;
#pragma unroll 1
    for (int tap = 0; tap < 9; tap++) {
        int yy = y + tap / 3 - 1, xx = x + tap % 3 - 1;
        if ((unsigned)yy < 256u && (unsigned)xx < 256u) {
            const float4* src = (const float4*)(t2 + (((yy << 8) + xx) << 4));
            float4 i0 = src[0], i1 = src[1], i2v = src[2], i3 = src[3];
            u64 in2[8] = {f2pack(i0.x, i0.y), f2pack(i0.z, i0.w),
                          f2pack(i1.x, i1.y), f2pack(i1.z, i1.w),
                          f2pack(i2v.x, i2v.y), f2pack(i2v.z, i2v.w),
                          f2pack(i3.x, i3.y), f2pack(i3.z, i3.w)};
            const u64* wt = &w3p[tap * 8];
#pragma unroll
            for (int oc = 0; oc < 16; oc++) {
                const u64* wr = wt + oc * 72;
#pragma unroll
                for (int k = 0; k < 8; k++) acc2[oc] = f2fma(in2[k], wr[k], acc2[oc]);
            }
        }
    }
    float c3[16];
#pragma unroll
    for (int oc = 0; oc < 16; oc++) {
        float2 f = f2unpack(acc2[oc]);
        c3[oc] = fmaxf(f.x + f.y + b3[oc], 0.f);
    }
    u64 a2[8];
#pragma unroll
    for (int o2 = 0; o2 < 8; o2++) a2[o2] = f2pack(c3[2 * o2], c3[2 * o2 + 1]);
    float* dst = t4 + (size_t)p * 32;
#pragma unroll
    for (int c4 = 0; c4 < 32; c4++) {
        u64 r = 0ULL;
#pragma unroll
        for (int o2 = 0; o2 < 8; o2++) r = f2fma(a2[o2], w4p[c4 * 8 + o2], r);
        float2 f = f2unpack(r);
        dst[c4] = f.x + f.y + b4[c4];
    }
}

// ---------------- K3a: instance-norm partial sums ----------------
__global__ __launch_bounds__(256) void inorm_part_kernel(const float* __restrict__ t4,
                                                         float* __restrict__ part) {
    int tid = threadIdx.x;
    size_t base = (size_t)blockIdx.x * 4096;
    float s[4] = {0, 0, 0, 0}, s2[4] = {0, 0, 0, 0};
    const float4* src = (const float4*)(t4 + base);
#pragma unroll
    for (int it = 0; it < 4; it++) {
        float4 v = src[it * 256 + tid];
        s[0] += v.x; s2[0] += v.x * v.x;
        s[1] += v.y; s2[1] += v.y * v.y;
        s[2] += v.z; s2[2] += v.z * v.z;
        s[3] += v.w; s2[3] += v.w * v.w;
    }
    __shared__ float sa[256][4], sb[256][4];
#pragma unroll
    for (int k = 0; k < 4; k++) { sa[tid][k] = s[k]; sb[tid][k] = s2[k]; }
    __syncthreads();
    if (tid < 32) {
        int grp = tid >> 2, k = tid & 3;
        float a = 0.f, b = 0.f;
#pragma unroll
        for (int t8 = 0; t8 < 32; t8++) {
            a += sa[t8 * 8 + grp][k];
            b += sb[t8 * 8 + grp][k];
        }
        part[blockIdx.x * 64 + tid] = a;
        part[blockIdx.x * 64 + 32 + tid] = b;
    }
}

// ---------------- K3b: instance-norm final reduce ----------------
__global__ __launch_bounds__(256) void inorm_final_kernel(const float* __restrict__ part,
                                                          float* __restrict__ stats) {
    int c = threadIdx.x & 31, g = threadIdx.x >> 5;
    double a = 0.0, b = 0.0;
    for (int blk = g; blk < 512; blk += 8) {
        a += (double)part[blk * 64 + c];
        b += (double)part[blk * 64 + 32 + c];
    }
    __shared__ double sa[8][32], sb[8][32];
    sa[g][c] = a; sb[g][c] = b;
    __syncthreads();
    if (threadIdx.x < 32) {
        double s = 0.0, s2 = 0.0;
#pragma unroll
        for (int k = 0; k < 8; k++) { s += sa[k][threadIdx.x]; s2 += sb[k][threadIdx.x]; }
        double mean = s / (double)HWP;
        double var = s2 / (double)HWP - mean * mean;
        stats[threadIdx.x] = (float)mean;
        stats[32 + threadIdx.x] = rsqrtf((float)var + 1e-5f);
    }
}

// ---------------- K5: bias fragments ----------------
__global__ void build_biasF_kernel(const int* __restrict__ rpi, const float* __restrict__ rpb,
                                   u64* __restrict__ biasF) {
    int idx = blockIdx.x * 256 + threadIdx.x;
    int tig = idx & 3;
    int t2 = idx >> 2;
    int ch = t2 % 36;
    int t3 = t2 / 36;
    int q = t3 & 255;
    int h = t3 >> 8;
    int k0 = ch * 16 + 2 * tig;
    u64 r = 0;
#pragma unroll
    for (int e = 0; e < 4; e++) {
        int k = k0 + (e >> 1) * 8 + (e & 1);
        float v = rpb[rpi[q * NKEY + k] * 2 + h] * LOG2E;
        unsigned short us = __bfloat16_as_ushort(__float2bfloat16(v));
        r |= (u64)us << (16 * e);
    }
    biasF[idx] = r;
}

// ---------------- K6: LN(x), LN(f) once; project into both OCABs' q/kv ----------------
__global__ __launch_bounds__(256) void ln_qkv_kernel(
    const float* __restrict__ xhwc, const float* __restrict__ t4,
    const float* __restrict__ stats,
    const float* __restrict__ in_g, const float* __restrict__ in_b,
    const float* __restrict__ n1g, const float* __restrict__ n1b,
    const float* __restrict__ wq, const float* __restrict__ bq,
    const float* __restrict__ wkv, const float* __restrict__ bkv,
    __nv_bfloat16* __restrict__ qbase, __nv_bfloat16* __restrict__ kvbase) {
    __shared__ u64 s_wq2[512], s_wk2[512], s_wv2[512];
    __shared__ float s_bq[32], s_bkv[64], s_g[32], s_b[32], s_A[32], s_C[32];
    __shared__ __align__(16) float s_act[8][32];
    int tid = threadIdx.x;
    for (int idx = tid; idx < 512; idx += 256) {
        int i2 = idx >> 5, l = idx & 31;
        s_wq2[idx] = f2pack(wq[(2 * i2) * 32 + l], wq[(2 * i2 + 1) * 32 + l]);
        s_wk2[idx] = f2pack(wkv[(2 * i2) * 64 + l], wkv[(2 * i2 + 1) * 64 + l]);
        s_wv2[idx] = f2pack(wkv[(2 * i2) * 64 + 32 + l], wkv[(2 * i2 + 1) * 64 + 32 + l]);
    }
    if (tid < 32) {
        s_bq[tid] = bq[tid]; s_g[tid] = n1g[tid]; s_b[tid] = n1b[tid];
        float A = stats[32 + tid] * in_g[tid];
        s_A[tid] = A;
        s_C[tid] = in_b[tid] - stats[tid] * A;
    }
    if (tid < 64) s_bkv[tid] = bkv[tid];
    __syncthreads();
    __nv_bfloat16* q0  = qbase;
    __nv_bfloat16* q1  = qbase + (size_t)HWP * 32;
    __nv_bfloat16* kv0 = kvbase;
    __nv_bfloat16* kv1 = kvbase + (size_t)HWP * 64;
    int lane = tid & 31, w = tid >> 5;
    int pbase = blockIdx.x * (8 * PPW) + w * PPW;
    const float QS = 0.25f * LOG2E;

#pragma unroll 1
    for (int it = 0; it < PPW; it++) {
        int p = pbase + it;
        float xv = xhwc[p * 32 + lane];
        float fvv = t4[p * 32 + lane] * s_A[lane] + s_C[lane];
        // LN(x)
        float mx = warp_sum(xv) * (1.f / 32.f);
        float dx = xv - mx;
        float vx = warp_sum(dx * dx) * (1.f / 32.f);
        float xn_x = dx * rsqrtf(vx + 1e-5f) * s_g[lane] + s_b[lane];
        // LN(f)
        float mf = warp_sum(fvv) * (1.f / 32.f);
        float df = fvv - mf;
        float vf = warp_sum(df * df) * (1.f / 32.f);
        float xn_f = df * rsqrtf(vf + 1e-5f) * s_g[lane] + s_b[lane];

        // project LN(x): q -> z0, k/v -> z1
        s_act[w][lane] = xn_x;
        __syncwarp();
        {
            u64 aq = 0ULL, ak = 0ULL, av = 0ULL;
#pragma unroll
            for (int i2 = 0; i2 < 16; i2++) {
                u64 x2 = *(const u64*)&s_act[w][2 * i2];
                aq = f2fma(x2, s_wq2[i2 * 32 + lane], aq);
                ak = f2fma(x2, s_wk2[i2 * 32 + lane], ak);
                av = f2fma(x2, s_wv2[i2 * 32 + lane], av);
            }
            float2 fq = f2unpack(aq), fk = f2unpack(ak), fv2 = f2unpack(av);
            q0[p * 32 + lane] = __float2bfloat16((fq.x + fq.y + s_bq[lane]) * QS);
            kv1[p * 64 + lane]      = __float2bfloat16(fk.x + fk.y + s_bkv[lane]);
            kv1[p * 64 + 32 + lane] = __float2bfloat16(fv2.x + fv2.y + s_bkv[lane + 32]);
        }
        __syncwarp();
        // project LN(f): q -> z1, k/v -> z0
        s_act[w][lane] = xn_f;
        __syncwarp();
        {
            u64 aq = 0ULL, ak = 0ULL, av = 0ULL;
#pragma unroll
            for (int i2 = 0; i2 < 16; i2++) {
                u64 x2 = *(const u64*)&s_act[w][2 * i2];
                aq = f2fma(x2, s_wq2[i2 * 32 + lane], aq);
                ak = f2fma(x2, s_wk2[i2 * 32 + lane], ak);
                av = f2fma(x2, s_wv2[i2 * 32 + lane], av);
            }
            float2 fq = f2unpack(aq), fk = f2unpack(ak), fv2 = f2unpack(av);
            q1[p * 32 + lane] = __float2bfloat16((fq.x + fq.y + s_bq[lane]) * QS);
            kv0[p * 64 + lane]      = __float2bfloat16(fk.x + fk.y + s_bkv[lane]);
            kv0[p * 64 + 32 + lane] = __float2bfloat16(fv2.x + fv2.y + s_bkv[lane + 32]);
        }
        __syncwarp();
    }
}

// ---------------- K7: flash attention, both z per block (bias loads shared) ----------------
__global__ __launch_bounds__(256) void attn_kernel(
    const __nv_bfloat16* __restrict__ qbase, const __nv_bfloat16* __restrict__ kvbase,
    const u64* __restrict__ biasF, __nv_bfloat16* __restrict__ outbase) {
    extern __shared__ __align__(16) char smraw[];
    int win = blockIdx.x, head = blockIdx.y;
    int wy = win >> 4, wx = win & 15;
    int t = threadIdx.x;
    int warp = t >> 5, lane = t & 31;
    int gid = lane >> 2, tig = lane & 3;

    // smem: [K z0][K z1][V z0][V z1]
    __nv_bfloat16* ksmz[2] = {(__nv_bfloat16*)smraw, (__nv_bfloat16*)(smraw + KBYTES)};
    __nv_bfloat16* vsmz[2] = {(__nv_bfloat16*)(smraw + 2 * KBYTES),
                              (__nv_bfloat16*)(smraw + 2 * KBYTES + VBYTES)};

    for (int j = t; j < NKEY; j += 256) {
        int jy = j / 24, jx = j - jy * 24;
        int yy = (wy << 4) - 4 + jy, xx = (wx << 4) - 4 + jx;
        bool inb = ((unsigned)yy < 256u && (unsigned)xx < 256u);
#pragma unroll
        for (int z = 0; z < 2; z++) {
            uint4 k0 = make_uint4(0, 0, 0, 0), k1 = k0, v0 = k0, v1 = k0;
            if (inb) {
                const __nv_bfloat16* base = kvbase + (size_t)z * HWP * 64 +
                                            ((size_t)((yy << 8) + xx) << 6) + (head << 4);
                k0 = *(const uint4*)base;
                k1 = *(const uint4*)(base + 8);
                v0 = *(const uint4*)(base + 32);
                v1 = *(const uint4*)(base + 40);
            }
            *(uint4*)(ksmz[z] + j * KSTRIDE)     = k0;
            *(uint4*)(ksmz[z] + j * KSTRIDE + 8) = k1;
            u32 vw[8] = {v0.x, v0.y, v0.z, v0.w, v1.x, v1.y, v1.z, v1.w};
#pragma unroll
            for (int i = 0; i < 8; i++) {
                __nv_bfloat162 pr = *(const __nv_bfloat162*)&vw[i];
                vsmz[z][(2 * i) * VSTRIDE + j]     = pr.x;
                vsmz[z][(2 * i + 1) * VSTRIDE + j] = pr.y;
            }
        }
    }

    // Q fragments for both z
    u32 qa[2][2][4];
    int qwb = warp * 32;
#pragma unroll
    for (int z = 0; z < 2; z++) {
        const __nv_bfloat16* q = qbase + (size_t)z * HWP * 32;
#pragma unroll
        for (int m = 0; m < 2; m++) {
            int r0 = qwb + m * 16 + gid;
            int r1 = r0 + 8;
            int px0 = ((wy << 4) + (r0 >> 4)) * 256 + (wx << 4) + (r0 & 15);
            int px1 = ((wy << 4) + (r1 >> 4)) * 256 + (wx << 4) + (r1 & 15);
            const __nv_bfloat16* q0p = q + (size_t)px0 * 32 + (head << 4);
            const __nv_bfloat16* q1p = q + (size_t)px1 * 32 + (head << 4);
            qa[z][m][0] = *(const u32*)(q0p + 2 * tig);
            qa[z][m][1] = *(const u32*)(q1p + 2 * tig);
            qa[z][m][2] = *(const u32*)(q0p + 8 + 2 * tig);
            qa[z][m][3] = *(const u32*)(q1p + 8 + 2 * tig);
        }
    }
    __syncthreads();

    float o[2][2][2][4];
#pragma unroll
    for (int z = 0; z < 2; z++)
#pragma unroll
        for (int m = 0; m < 2; m++)
#pragma unroll
            for (int d = 0; d < 2; d++)
#pragma unroll
                for (int i = 0; i < 4; i++) o[z][m][d][i] = 0.f;
    float l4[2][4] = {{0.f, 0.f, 0.f, 0.f}, {0.f, 0.f, 0.f, 0.f}};

    const u64* bF = biasF + ((size_t)head << 8) * 144;

#pragma unroll 1
    for (int ch = 0; ch < 36; ch++) {
        int kb = ch * 16;
        u64 bw[4];
#pragma unroll
        for (int r4 = 0; r4 < 4; r4++) {
            int qrow = qwb + ((r4 >> 1) << 4) + ((r4 & 1) << 3) + gid;
            bw[r4] = bF[(qrow * 36 + ch) * 4 + tig];
        }
#pragma unroll
        for (int z = 0; z < 2; z++) {
            u32 kf[2][2];
#pragma unroll
            for (int nt = 0; nt < 2; nt++) {
                const __nv_bfloat16* kr = ksmz[z] + (kb + nt * 8 + gid) * KSTRIDE + 2 * tig;
                kf[nt][0] = *(const u32*)kr;
                kf[nt][1] = *(const u32*)(kr + 8);
            }
            u32 vb[2][2];
#pragma unroll
            for (int dt = 0; dt < 2; dt++) {
                const __nv_bfloat16* vr = vsmz[z] + (dt * 8 + gid) * VSTRIDE + kb + 2 * tig;
                vb[dt][0] = *(const u32*)vr;
                vb[dt][1] = *(const u32*)(vr + 8);
            }
#pragma unroll
            for (int m = 0; m < 2; m++) {
                float c0[4] = {0.f, 0.f, 0.f, 0.f}, c1[4] = {0.f, 0.f, 0.f, 0.f};
                mma_bf16(c0, qa[z][m], kf[0], c0);
                mma_bf16(c1, qa[z][m], kf[1], c1);
                u32 bAlo = (u32)bw[m * 2],     bAhi = (u32)(bw[m * 2] >> 32);
                u32 bBlo = (u32)bw[m * 2 + 1], bBhi = (u32)(bw[m * 2 + 1] >> 32);
                float p00 = ex2f(fminf(c0[0] + __int_as_float(bAlo << 16), 80.f));
                float p01 = ex2f(fminf(c0[1] + __int_as_float((int)(bAlo & 0xffff0000u)), 80.f));
                float p02 = ex2f(fminf(c0[2] + __int_as_float(bBlo << 16), 80.f));
                float p03 = ex2f(fminf(c0[3] + __int_as_float((int)(bBlo & 0xffff0000u)), 80.f));
                float p10 = ex2f(fminf(c1[0] + __int_as_float(bAhi << 16), 80.f));
                float p11 = ex2f(fminf(c1[1] + __int_as_float((int)(bAhi & 0xffff0000u)), 80.f));
                float p12 = ex2f(fminf(c1[2] + __int_as_float(bBhi << 16), 80.f));
                float p13 = ex2f(fminf(c1[3] + __int_as_float((int)(bBhi & 0xffff0000u)), 80.f));
                l4[z][m * 2]     += (p00 + p01) + (p10 + p11);
                l4[z][m * 2 + 1] += (p02 + p03) + (p12 + p13);
                u32 pa[4];
                pa[0] = bfpack(p00, p01);
                pa[1] = bfpack(p02, p03);
                pa[2] = bfpack(p10, p11);
                pa[3] = bfpack(p12, p13);
                mma_bf16(o[z][m][0], pa, vb[0], o[z][m][0]);
                mma_bf16(o[z][m][1], pa, vb[1], o[z][m][1]);
            }
        }
    }

#pragma unroll
    for (int z = 0; z < 2; z++)
#pragma unroll
        for (int r4 = 0; r4 < 4; r4++) {
            l4[z][r4] += __shfl_xor_sync(0xffffffffu, l4[z][r4], 1);
            l4[z][r4] += __shfl_xor_sync(0xffffffffu, l4[z][r4], 2);
            l4[z][r4] = 1.f / l4[z][r4];
        }

#pragma unroll
    for (int z = 0; z < 2; z++) {
        __nv_bfloat16* out = outbase + (size_t)z * HWP * 32;
#pragma unroll
        for (int m = 0; m < 2; m++) {
            int r0 = qwb + m * 16 + gid;
            int r1 = r0 + 8;
            int px0 = ((wy << 4) + (r0 >> 4)) * 256 + (wx << 4) + (r0 & 15);
            int px1 = ((wy << 4) + (r1 >> 4)) * 256 + (wx << 4) + (r1 & 15);
            __nv_bfloat16* o0p = out + (size_t)px0 * 32 + (head << 4);
            __nv_bfloat16* o1p = out + (size_t)px1 * 32 + (head << 4);
            float i0 = l4[z][m * 2], i1 = l4[z][m * 2 + 1];
#pragma unroll
            for (int dt = 0; dt < 2; dt++) {
                *(u32*)(o0p + dt * 8 + 2 * tig) =
                    bfpack(o[z][m][dt][0] * i0, o[z][m][dt][1] * i0);
                *(u32*)(o1p + dt * 8 + 2 * tig) =
                    bfpack(o[z][m][dt][2] * i1, o[z][m][dt][3] * i1);
            }
        }
    }
}

// ---------------- K8: both OCAB tails per pixel; writes o = out1+out2 ----------------
__global__ __launch_bounds__(256) void proj_mlp_kernel(
    const __nv_bfloat16* __restrict__ attbase,
    const float* __restrict__ xhwc, const float* __restrict__ t4,
    const float* __restrict__ stats,
    const float* __restrict__ in_g, const float* __restrict__ in_b,
    const float* __restrict__ wp, const float* __restrict__ bp,
    const float* __restrict__ n2g, const float* __restrict__ n2b,
    const float* __restrict__ mw1, const float* __restrict__ mb1,
    const float* __restrict__ mw2, const float* __restrict__ mb2,
    float* __restrict__ o) {
    __shared__ u64 s_wp2[512], s_m1a[512], s_m1b[512], s_m2[1024];
    __shared__ float s_bp[32], s_mb1[64], s_mb2[32], s_g[32], s_b[32], s_A[32], s_C[32];
    __shared__ __align__(16) float s_act[8][32];
    __shared__ __align__(16) float s_h[8][64];
    int tid = threadIdx.x;
    for (int idx = tid; idx < 512; idx += 256) {
        int i2 = idx >> 5, l = idx & 31;
        s_wp2[idx] = f2pack(wp[(2 * i2) * 32 + l], wp[(2 * i2 + 1) * 32 + l]);
        s_m1a[idx] = f2pack(mw1[(2 * i2) * 64 + l], mw1[(2 * i2 + 1) * 64 + l]);
        s_m1b[idx] = f2pack(mw1[(2 * i2) * 64 + 32 + l], mw1[(2 * i2 + 1) * 64 + 32 + l]);
    }
    for (int idx = tid; idx < 1024; idx += 256) {
        int i2 = idx >> 5, l = idx & 31;
        s_m2[idx] = f2pack(mw2[(2 * i2) * 32 + l], mw2[(2 * i2 + 1) * 32 + l]);
    }
    if (tid < 32) {
        s_bp[tid] = bp[tid]; s_mb2[tid] = mb2[tid]; s_g[tid] = n2g[tid]; s_b[tid] = n2b[tid];
        float A = stats[32 + tid] * in_g[tid];
        s_A[tid] = A;
        s_C[tid] = in_b[tid] - stats[tid] * A;
    }
    if (tid < 64) s_mb1[tid] = mb1[tid];
    __syncthreads();
    int lane = tid & 31, w = tid >> 5;
    int pbase = blockIdx.x * (8 * PPW) + w * PPW;

#pragma unroll 1
    for (int it = 0; it < PPW; it++) {
        int p = pbase + it;
        float xv = xhwc[p * 32 + lane];
        float fvv = t4[p * 32 + lane] * s_A[lane] + s_C[lane];
        float osum = 0.f;
#pragma unroll 1
        for (int z = 0; z < 2; z++) {
            float scv = z ? fvv : xv;
            float a = __bfloat162float(attbase[(size_t)z * HWP * 32 + p * 32 + lane]);
            s_act[w][lane] = a;
            __syncwarp();
            u64 acc = 0ULL;
#pragma unroll
            for (int i2 = 0; i2 < 16; i2++) {
                u64 x2 = *(const u64*)&s_act[w][2 * i2];
                acc = f2fma(x2, s_wp2[i2 * 32 + lane], acc);
            }
            float2 fy = f2unpack(acc);
            float y = fy.x + fy.y + s_bp[lane] + scv;

            float mean = warp_sum(y) * (1.f / 32.f);
            float dv = y - mean;
            float var = warp_sum(dv * dv) * (1.f / 32.f);
            float yn = dv * rsqrtf(var + 1e-5f) * s_g[lane] + s_b[lane];

            __syncwarp();
            s_act[w][lane] = yn;
            __syncwarp();
            u64 h0a = 0ULL, h1a = 0ULL;
#pragma unroll
            for (int i2 = 0; i2 < 16; i2++) {
                u64 x2 = *(const u64*)&s_act[w][2 * i2];
                h0a = f2fma(x2, s_m1a[i2 * 32 + lane], h0a);
                h1a = f2fma(x2, s_m1b[i2 * 32 + lane], h1a);
            }
            float2 f0 = f2unpack(h0a), f1 = f2unpack(h1a);
            float h0 = gelu_tanh(f0.x + f0.y + s_mb1[lane]);
            float h1 = gelu_tanh(f1.x + f1.y + s_mb1[lane + 32]);
            s_h[w][lane] = h0;
            s_h[w][32 + lane] = h1;
            __syncwarp();
            u64 r2 = 0ULL;
#pragma unroll
            for (int i2 = 0; i2 < 32; i2++) {
                u64 g2 = *(const u64*)&s_h[w][2 * i2];
                r2 = f2fma(g2, s_m2[i2 * 32 + lane], r2);
            }
            float2 fr = f2unpack(r2);
            osum += y + fr.x + fr.y + s_mb2[lane];
            __syncwarp();
        }
        o[p * 32 + lane] = osum;
    }
}

// ---------------- K9: final sum, HWC -> CHW ----------------
__global__ void final_kernel(const float* __restrict__ o,
                             const float* __restrict__ x, float* __restrict__ out) {
    __shared__ float sm[32][33];
    int p0 = blockIdx.x * 32;
    int tx = threadIdx.x, ty = threadIdx.y;
    for (int r = ty; r < 32; r += 8) sm[r][tx] = o[(p0 + r) * 32 + tx];
    __syncthreads();
    for (int c = ty; c < 32; c += 8)
        out[c * HWP + p0 + tx] = sm[tx][c] + x[c * HWP + p0 + tx];
}

// ---------------- launch ----------------
extern "C" void kernel_launch(void* const* d_in, const int* in_sizes, int n_in,
                              void* d_out, int out_size) {
    const float* x    = (const float*)d_in[0];
    const float* dep  = (const float*)d_in[1];
    const int*   rpi  = (const int*)  d_in[2];
    const float* cw1  = (const float*)d_in[3];
    const float* cb1  = (const float*)d_in[4];
    const float* cw2  = (const float*)d_in[5];
    const float* cb2  = (const float*)d_in[6];
    const float* cw3  = (const float*)d_in[7];
    const float* cb3  = (const float*)d_in[8];
    const float* cw4  = (const float*)d_in[9];
    const float* cb4  = (const float*)d_in[10];
    const float* in_g = (const float*)d_in[11];
    const float* in_b = (const float*)d_in[12];
    const float* n1g  = (const float*)d_in[13];
    const float* n1b  = (const float*)d_in[14];
    const float* wq   = (const float*)d_in[15];
    const float* bq   = (const float*)d_in[16];
    const float* wkv  = (const float*)d_in[17];
    const float* bkv  = (const float*)d_in[18];
    const float* rpb  = (const float*)d_in[19];
    const float* wp   = (const float*)d_in[20];
    const float* bp   = (const float*)d_in[21];
    const float* n2g  = (const float*)d_in[22];
    const float* n2b  = (const float*)d_in[23];
    const float* mw1  = (const float*)d_in[24];
    const float* mb1  = (const float*)d_in[25];
    const float* mw2  = (const float*)d_in[26];
    const float* mb2  = (const float*)d_in[27];
    float* out = (float*)d_out;

    void *p_xhwc, *p_t2, *p_t4, *p_q, *p_kv, *p_att, *p_o, *p_bias, *p_stats, *p_part;
    cudaGetSymbolAddress(&p_xhwc, g_xhwc);
    cudaGetSymbolAddress(&p_t2, g_t2);
    cudaGetSymbolAddress(&p_t4, g_t4);
    cudaGetSymbolAddress(&p_q, g_qbf);
    cudaGetSymbolAddress(&p_kv, g_kvbf);
    cudaGetSymbolAddress(&p_att, g_attbf);
    cudaGetSymbolAddress(&p_o, g_o);
    cudaGetSymbolAddress(&p_bias, g_biasF);
    cudaGetSymbolAddress(&p_stats, g_stats);
    cudaGetSymbolAddress(&p_part, g_part);

    cudaFuncSetAttribute(attn_kernel, cudaFuncAttributeMaxDynamicSharedMemorySize, SMEM_ATTN);

    chw2hwc_kernel<<<2048, dim3(32, 8)>>>(x, (float*)p_xhwc);
    stem12_kernel<<<256, 256>>>(dep, cw1, cb1, cw2, cb2, (float*)p_t2);
    stem34_kernel<<<256, 256>>>((float*)p_t2, cw3, cb3, cw4, cb4, (float*)p_t4);
    inorm_part_kernel<<<512, 256>>>((float*)p_t4, (float*)p_part);
    inorm_final_kernel<<<1, 256>>>((float*)p_part, (float*)p_stats);
    build_biasF_kernel<<<288, 256>>>(rpi, rpb, (u64*)p_bias);

    ln_qkv_kernel<<<HWP / (8 * PPW), 256>>>(
        (float*)p_xhwc, (float*)p_t4, (float*)p_stats, in_g, in_b, n1g, n1b,
        wq, bq, wkv, bkv, (__nv_bfloat16*)p_q, (__nv_bfloat16*)p_kv);
    attn_kernel<<<dim3(NWIN, 2), 256, SMEM_ATTN>>>((__nv_bfloat16*)p_q,
                                                   (__nv_bfloat16*)p_kv,
                                                   (u64*)p_bias,
                                                   (__nv_bfloat16*)p_att);
    proj_mlp_kernel<<<HWP / (8 * PPW), 256>>>(
        (__nv_bfloat16*)p_att, (float*)p_xhwc, (float*)p_t4, (float*)p_stats,
        in_g, in_b, wp, bp, n2g, n2b, mw1, mb1, mw2, mb2, (float*)p_o);

    final_kernel<<<2048, dim3(32, 8)>>>((float*)p_o, x, out);
}

// round 9
// speedup vs baseline: 3.1913x; 1.0313x over previous
#include <cuda_runtime.h>
#include <cuda_bf16.h>
#include <math.h>

// Problem constants: B=1, C=32, H=W=256, WS=16, OWS=24, NH=2, d=16
#define HWP   65536
#define NKEY  576
#define NQ    256
#define NWIN  256

typedef unsigned long long u64;
typedef unsigned int u32;

#define LOG2E 1.4426950408889634f

// attn smem layout (both z resident)
#define KSTRIDE 24
#define VSTRIDE 584
#define KBYTES (NKEY * KSTRIDE * 2)          // 27648
#define VBYTES (16 * VSTRIDE * 2)            // 18688
#define SMEM_ATTN (2 * KBYTES + 2 * VBYTES)  // 92672

#define PPW 8

// ---------------- scratch ----------------
__device__ float          g_xhwc [HWP * 32];
__device__ float          g_t4   [HWP * 32];
__device__ __nv_bfloat16  g_qbf  [2 * HWP * 32];
__device__ __nv_bfloat16  g_kvbf [2 * HWP * 64];
__device__ __nv_bfloat16  g_attbf[2 * HWP * 32];
__device__ u64            g_biasF[2 * NQ * 36 * 4];
__device__ float          g_stats[64];
__device__ float          g_part [512 * 64];

// ---------------- helpers ----------------
__device__ __forceinline__ u64 f2pack(float lo, float hi) {
    u64 r; asm("mov.b64 %0, {%1, %2};" : "=l"(r) : "f"(lo), "f"(hi)); return r;
}
__device__ __forceinline__ float2 f2unpack(u64 v) {
    float2 f; asm("mov.b64 {%0, %1}, %2;" : "=f"(f.x), "=f"(f.y) : "l"(v)); return f;
}
__device__ __forceinline__ u64 f2fma(u64 a, u64 b, u64 c) {
    u64 d; asm("fma.rn.f32x2 %0, %1, %2, %3;" : "=l"(d) : "l"(a), "l"(b), "l"(c)); return d;
}
__device__ __forceinline__ float ex2f(float x) {
    float y; asm("ex2.approx.f32 %0, %1;" : "=f"(y) : "f"(x)); return y;
}
__device__ __forceinline__ u32 bfpack(float lo, float hi) {
    u32 d; asm("cvt.rn.bf16x2.f32 %0, %1, %2;" : "=r"(d) : "f"(hi), "f"(lo)); return d;
}
__device__ __forceinline__ float warp_sum(float v) {
#pragma unroll
    for (int o = 16; o; o >>= 1) v += __shfl_xor_sync(0xffffffffu, v, o);
    return v;
}
__device__ __forceinline__ float gelu_tanh(float x) {
    float z = 0.7978845608028654f * (x + 0.044715f * x * x * x);
    float e = ex2f(2.8853900817779268f * z);
    float t = 1.f - __fdividef(2.f, e + 1.f);
    return 0.5f * x * (1.f + t);
}
__device__ __forceinline__ void mma_bf16(float* d, const u32* a, const u32* b, const float* c) {
    asm("mma.sync.aligned.m16n8k16.row.col.f32.bf16.bf16.f32 "
        "{%0,%1,%2,%3}, {%4,%5,%6,%7}, {%8,%9}, {%10,%11,%12,%13};"
        : "=f"(d[0]), "=f"(d[1]), "=f"(d[2]), "=f"(d[3])
        : "r"(a[0]), "r"(a[1]), "r"(a[2]), "r"(a[3]),
          "r"(b[0]), "r"(b[1]),
          "f"(c[0]), "f"(c[1]), "f"(c[2]), "f"(c[3]));
}

// ---------------- K0: CHW -> HWC transpose of x ----------------
__global__ void chw2hwc_kernel(const float* __restrict__ x, float* __restrict__ xh) {
    __shared__ float sm[32][33];
    int p0 = blockIdx.x * 32;
    int tx = threadIdx.x, ty = threadIdx.y;
    for (int c = ty; c < 32; c += 8) sm[c][tx] = x[c * HWP + p0 + tx];
    __syncthreads();
    for (int r = ty; r < 32; r += 8) xh[(p0 + r) * 32 + tx] = sm[tx][r];
}

// ---------------- K1: fused stem: conv1+conv2 (halo in smem) + conv3+conv4 ----------------
__global__ __launch_bounds__(256) void stem_fused_kernel(
    const float* __restrict__ depth,
    const float* __restrict__ cw1, const float* __restrict__ cb1,
    const float* __restrict__ cw2, const float* __restrict__ cb2,
    const float* __restrict__ cw3, const float* __restrict__ cb3,
    const float* __restrict__ cw4, const float* __restrict__ cb4,
    float* __restrict__ t4) {
    __shared__ float w1[72], b1s[8], w2[128], b2s[16];
    __shared__ u64 w3p[1152];      // [oc][tap][ic2]
    __shared__ u64 w4p[256];       // [c4][oc2]
    __shared__ float b3[16], b4[32];
    __shared__ float t2s[324][17]; // 18x18 halo of conv2 output, pad 17
    int tid = threadIdx.x;
    if (tid < 72)  w1[tid]  = cw1[tid];
    if (tid < 8)   b1s[tid] = cb1[tid];
    if (tid < 128) w2[tid]  = cw2[tid];
    if (tid < 16)  b2s[tid] = cb2[tid];
    for (int i = tid; i < 1152; i += 256) {
        int oc = i / 72, r = i - oc * 72, tap = r >> 3, ic2 = r & 7;
        w3p[i] = f2pack(cw3[oc * 144 + (2 * ic2) * 9 + tap],
                        cw3[oc * 144 + (2 * ic2 + 1) * 9 + tap]);
    }
    if (tid < 256) {
        int c4 = tid >> 3, o2 = tid & 7;
        w4p[tid] = f2pack(cw4[c4 * 16 + 2 * o2], cw4[c4 * 16 + 2 * o2 + 1]);
    }
    if (tid < 16) b3[tid] = cb3[tid];
    if (tid < 32) b4[tid] = cb4[tid];
    __syncthreads();

    int ty0 = (blockIdx.x >> 4) << 4;
    int tx0 = (blockIdx.x & 15) << 4;

    // phase 1: conv1+conv2 on 18x18 halo
    for (int h = tid; h < 324; h += 256) {
        int hy = h / 18, hx = h - hy * 18;
        int gy = ty0 + hy - 1, gx = tx0 + hx - 1;
        float out16[16];
        if ((unsigned)gy < 256u && (unsigned)gx < 256u) {
            float d[9];
#pragma unroll
            for (int tap = 0; tap < 9; tap++) {
                int yy = gy + tap / 3 - 1, xx = gx + tap % 3 - 1;
                d[tap] = ((unsigned)yy < 256u && (unsigned)xx < 256u)
                             ? depth[(yy << 8) + xx] : 0.f;
            }
            float c1[8];
#pragma unroll
            for (int o = 0; o < 8; o++) {
                float a = b1s[o];
#pragma unroll
                for (int tap = 0; tap < 9; tap++) a += d[tap] * w1[o * 9 + tap];
                c1[o] = fmaxf(a, 0.f);
            }
#pragma unroll
            for (int o2 = 0; o2 < 16; o2++) {
                float a = b2s[o2];
#pragma unroll
                for (int o = 0; o < 8; o++) a += c1[o] * w2[o2 * 8 + o];
                out16[o2] = fmaxf(a, 0.f);
            }
        } else {
#pragma unroll
            for (int o2 = 0; o2 < 16; o2++) out16[o2] = 0.f;
        }
#pragma unroll
        for (int o2 = 0; o2 < 16; o2++) t2s[h][o2] = out16[o2];
    }
    __syncthreads();

    // phase 2: conv3+conv4 for own pixel
    int py = tid >> 4, px = tid & 15;
    u64 acc2[16];
#pragma unroll
    for (int i = 0; i < 16; i++) acc2[i] = 0ULL;
#pragma unroll 1
    for (int tap = 0; tap < 9; tap++) {
        int hh = (py + tap / 3) * 18 + (px + tap % 3);
        const float* src = &t2s[hh][0];
        u64 in2[8];
#pragma unroll
        for (int k = 0; k < 8; k++) in2[k] = f2pack(src[2 * k], src[2 * k + 1]);
        const u64* wt = &w3p[tap * 8];
#pragma unroll
        for (int oc = 0; oc < 16; oc++) {
            const u64* wr = wt + oc * 72;
#pragma unroll
            for (int k = 0; k < 8; k++) acc2[oc] = f2fma(in2[k], wr[k], acc2[oc]);
        }
    }
    float c3[16];
#pragma unroll
    for (int oc = 0; oc < 16; oc++) {
        float2 f = f2unpack(acc2[oc]);
        c3[oc] = fmaxf(f.x + f.y + b3[oc], 0.f);
    }
    u64 a2[8];
#pragma unroll
    for (int o2 = 0; o2 < 8; o2++) a2[o2] = f2pack(c3[2 * o2], c3[2 * o2 + 1]);
    int p = (ty0 + py) * 256 + tx0 + px;
    float* dst = t4 + (size_t)p * 32;
#pragma unroll
    for (int c4 = 0; c4 < 32; c4++) {
        u64 r = 0ULL;
#pragma unroll
        for (int o2 = 0; o2 < 8; o2++) r = f2fma(a2[o2], w4p[c4 * 8 + o2], r);
        float2 f = f2unpack(r);
        dst[c4] = f.x + f.y + b4[c4];
    }
}

// ---------------- K3a: instance-norm partial sums ----------------
__global__ __launch_bounds__(256) void inorm_part_kernel(const float* __restrict__ t4,
                                                         float* __restrict__ part) {
    int tid = threadIdx.x;
    size_t base = (size_t)blockIdx.x * 4096;
    float s[4] = {0, 0, 0, 0}, s2[4] = {0, 0, 0, 0};
    const float4* src = (const float4*)(t4 + base);
#pragma unroll
    for (int it = 0; it < 4; it++) {
        float4 v = src[it * 256 + tid];
        s[0] += v.x; s2[0] += v.x * v.x;
        s[1] += v.y; s2[1] += v.y * v.y;
        s[2] += v.z; s2[2] += v.z * v.z;
        s[3] += v.w; s2[3] += v.w * v.w;
    }
    __shared__ float sa[256][4], sb[256][4];
#pragma unroll
    for (int k = 0; k < 4; k++) { sa[tid][k] = s[k]; sb[tid][k] = s2[k]; }
    __syncthreads();
    if (tid < 32) {
        int grp = tid >> 2, k = tid & 3;
        float a = 0.f, b = 0.f;
#pragma unroll
        for (int t8 = 0; t8 < 32; t8++) {
            a += sa[t8 * 8 + grp][k];
            b += sb[t8 * 8 + grp][k];
        }
        part[blockIdx.x * 64 + tid] = a;
        part[blockIdx.x * 64 + 32 + tid] = b;
    }
}

// ---------------- K3b: instance-norm final reduce ----------------
__global__ __launch_bounds__(256) void inorm_final_kernel(const float* __restrict__ part,
                                                          float* __restrict__ stats) {
    int c = threadIdx.x & 31, g = threadIdx.x >> 5;
    double a = 0.0, b = 0.0;
    for (int blk = g; blk < 512; blk += 8) {
        a += (double)part[blk * 64 + c];
        b += (double)part[blk * 64 + 32 + c];
    }
    __shared__ double sa[8][32], sb[8][32];
    sa[g][c] = a; sb[g][c] = b;
    __syncthreads();
    if (threadIdx.x < 32) {
        double s = 0.0, s2 = 0.0;
#pragma unroll
        for (int k = 0; k < 8; k++) { s += sa[k][threadIdx.x]; s2 += sb[k][threadIdx.x]; }
        double mean = s / (double)HWP;
        double var = s2 / (double)HWP - mean * mean;
        stats[threadIdx.x] = (float)mean;
        stats[32 + threadIdx.x] = rsqrtf((float)var + 1e-5f);
    }
}

// ---------------- K5: bias fragments ----------------
__global__ void build_biasF_kernel(const int* __restrict__ rpi, const float* __restrict__ rpb,
                                   u64* __restrict__ biasF) {
    int idx = blockIdx.x * 256 + threadIdx.x;
    int tig = idx & 3;
    int t2 = idx >> 2;
    int ch = t2 % 36;
    int t3 = t2 / 36;
    int q = t3 & 255;
    int h = t3 >> 8;
    int k0 = ch * 16 + 2 * tig;
    u64 r = 0;
#pragma unroll
    for (int e = 0; e < 4; e++) {
        int k = k0 + (e >> 1) * 8 + (e & 1);
        float v = rpb[rpi[q * NKEY + k] * 2 + h] * LOG2E;
        unsigned short us = __bfloat16_as_ushort(__float2bfloat16(v));
        r |= (u64)us << (16 * e);
    }
    biasF[idx] = r;
}

// ---------------- K6: LN(x), LN(f) once; project into both OCABs' q/kv ----------------
__global__ __launch_bounds__(256) void ln_qkv_kernel(
    const float* __restrict__ xhwc, const float* __restrict__ t4,
    const float* __restrict__ stats,
    const float* __restrict__ in_g, const float* __restrict__ in_b,
    const float* __restrict__ n1g, const float* __restrict__ n1b,
    const float* __restrict__ wq, const float* __restrict__ bq,
    const float* __restrict__ wkv, const float* __restrict__ bkv,
    __nv_bfloat16* __restrict__ qbase, __nv_bfloat16* __restrict__ kvbase) {
    __shared__ u64 s_wq2[512], s_wk2[512], s_wv2[512];
    __shared__ float s_bq[32], s_bkv[64], s_g[32], s_b[32], s_A[32], s_C[32];
    __shared__ __align__(16) float s_act[8][32];
    int tid = threadIdx.x;
    for (int idx = tid; idx < 512; idx += 256) {
        int i2 = idx >> 5, l = idx & 31;
        s_wq2[idx] = f2pack(wq[(2 * i2) * 32 + l], wq[(2 * i2 + 1) * 32 + l]);
        s_wk2[idx] = f2pack(wkv[(2 * i2) * 64 + l], wkv[(2 * i2 + 1) * 64 + l]);
        s_wv2[idx] = f2pack(wkv[(2 * i2) * 64 + 32 + l], wkv[(2 * i2 + 1) * 64 + 32 + l]);
    }
    if (tid < 32) {
        s_bq[tid] = bq[tid]; s_g[tid] = n1g[tid]; s_b[tid] = n1b[tid];
        float A = stats[32 + tid] * in_g[tid];
        s_A[tid] = A;
        s_C[tid] = in_b[tid] - stats[tid] * A;
    }
    if (tid < 64) s_bkv[tid] = bkv[tid];
    __syncthreads();
    __nv_bfloat16* q0  = qbase;
    __nv_bfloat16* q1  = qbase + (size_t)HWP * 32;
    __nv_bfloat16* kv0 = kvbase;
    __nv_bfloat16* kv1 = kvbase + (size_t)HWP * 64;
    int lane = tid & 31, w = tid >> 5;
    int pbase = blockIdx.x * (8 * PPW) + w * PPW;
    const float QS = 0.25f * LOG2E;

#pragma unroll 1
    for (int it = 0; it < PPW; it++) {
        int p = pbase + it;
        float xv = xhwc[p * 32 + lane];
        float fvv = t4[p * 32 + lane] * s_A[lane] + s_C[lane];
        float mx = warp_sum(xv) * (1.f / 32.f);
        float dx = xv - mx;
        float vx = warp_sum(dx * dx) * (1.f / 32.f);
        float xn_x = dx * rsqrtf(vx + 1e-5f) * s_g[lane] + s_b[lane];
        float mf = warp_sum(fvv) * (1.f / 32.f);
        float df = fvv - mf;
        float vf = warp_sum(df * df) * (1.f / 32.f);
        float xn_f = df * rsqrtf(vf + 1e-5f) * s_g[lane] + s_b[lane];

        s_act[w][lane] = xn_x;
        __syncwarp();
        {
            u64 aq = 0ULL, ak = 0ULL, av = 0ULL;
#pragma unroll
            for (int i2 = 0; i2 < 16; i2++) {
                u64 x2 = *(const u64*)&s_act[w][2 * i2];
                aq = f2fma(x2, s_wq2[i2 * 32 + lane], aq);
                ak = f2fma(x2, s_wk2[i2 * 32 + lane], ak);
                av = f2fma(x2, s_wv2[i2 * 32 + lane], av);
            }
            float2 fq = f2unpack(aq), fk = f2unpack(ak), fv2 = f2unpack(av);
            q0[p * 32 + lane] = __float2bfloat16((fq.x + fq.y + s_bq[lane]) * QS);
            kv1[p * 64 + lane]      = __float2bfloat16(fk.x + fk.y + s_bkv[lane]);
            kv1[p * 64 + 32 + lane] = __float2bfloat16(fv2.x + fv2.y + s_bkv[lane + 32]);
        }
        __syncwarp();
        s_act[w][lane] = xn_f;
        __syncwarp();
        {
            u64 aq = 0ULL, ak = 0ULL, av = 0ULL;
#pragma unroll
            for (int i2 = 0; i2 < 16; i2++) {
                u64 x2 = *(const u64*)&s_act[w][2 * i2];
                aq = f2fma(x2, s_wq2[i2 * 32 + lane], aq);
                ak = f2fma(x2, s_wk2[i2 * 32 + lane], ak);
                av = f2fma(x2, s_wv2[i2 * 32 + lane], av);
            }
            float2 fq = f2unpack(aq), fk = f2unpack(ak), fv2 = f2unpack(av);
            q1[p * 32 + lane] = __float2bfloat16((fq.x + fq.y + s_bq[lane]) * QS);
            kv0[p * 64 + lane]      = __float2bfloat16(fk.x + fk.y + s_bkv[lane]);
            kv0[p * 64 + 32 + lane] = __float2bfloat16(fv2.x + fv2.y + s_bkv[lane + 32]);
        }
        __syncwarp();
    }
}

// ---------------- K7: flash attention, both z per block (bias loads shared) ----------------
__global__ __launch_bounds__(256) void attn_kernel(
    const __nv_bfloat16* __restrict__ qbase, const __nv_bfloat16* __restrict__ kvbase,
    const u64* __restrict__ biasF, __nv_bfloat16* __restrict__ outbase) {
    extern __shared__ __align__(16) char smraw[];
    int win = blockIdx.x, head = blockIdx.y;
    int wy = win >> 4, wx = win & 15;
    int t = threadIdx.x;
    int warp = t >> 5, lane = t & 31;
    int gid = lane >> 2, tig = lane & 3;

    __nv_bfloat16* ksmz[2] = {(__nv_bfloat16*)smraw, (__nv_bfloat16*)(smraw + KBYTES)};
    __nv_bfloat16* vsmz[2] = {(__nv_bfloat16*)(smraw + 2 * KBYTES),
                              (__nv_bfloat16*)(smraw + 2 * KBYTES + VBYTES)};

    for (int j = t; j < NKEY; j += 256) {
        int jy = j / 24, jx = j - jy * 24;
        int yy = (wy << 4) - 4 + jy, xx = (wx << 4) - 4 + jx;
        bool inb = ((unsigned)yy < 256u && (unsigned)xx < 256u);
#pragma unroll
        for (int z = 0; z < 2; z++) {
            uint4 k0 = make_uint4(0, 0, 0, 0), k1 = k0, v0 = k0, v1 = k0;
            if (inb) {
                const __nv_bfloat16* base = kvbase + (size_t)z * HWP * 64 +
                                            ((size_t)((yy << 8) + xx) << 6) + (head << 4);
                k0 = *(const uint4*)base;
                k1 = *(const uint4*)(base + 8);
                v0 = *(const uint4*)(base + 32);
                v1 = *(const uint4*)(base + 40);
            }
            *(uint4*)(ksmz[z] + j * KSTRIDE)     = k0;
            *(uint4*)(ksmz[z] + j * KSTRIDE + 8) = k1;
            u32 vw[8] = {v0.x, v0.y, v0.z, v0.w, v1.x, v1.y, v1.z, v1.w};
#pragma unroll
            for (int i = 0; i < 8; i++) {
                __nv_bfloat162 pr = *(const __nv_bfloat162*)&vw[i];
                vsmz[z][(2 * i) * VSTRIDE + j]     = pr.x;
                vsmz[z][(2 * i + 1) * VSTRIDE + j] = pr.y;
            }
        }
    }

    u32 qa[2][2][4];
    int qwb = warp * 32;
#pragma unroll
    for (int z = 0; z < 2; z++) {
        const __nv_bfloat16* q = qbase + (size_t)z * HWP * 32;
#pragma unroll
        for (int m = 0; m < 2; m++) {
            int r0 = qwb + m * 16 + gid;
            int r1 = r0 + 8;
            int px0 = ((wy << 4) + (r0 >> 4)) * 256 + (wx << 4) + (r0 & 15);
            int px1 = ((wy << 4) + (r1 >> 4)) * 256 + (wx << 4) + (r1 & 15);
            const __nv_bfloat16* q0p = q + (size_t)px0 * 32 + (head << 4);
            const __nv_bfloat16* q1p = q + (size_t)px1 * 32 + (head << 4);
            qa[z][m][0] = *(const u32*)(q0p + 2 * tig);
            qa[z][m][1] = *(const u32*)(q1p + 2 * tig);
            qa[z][m][2] = *(const u32*)(q0p + 8 + 2 * tig);
            qa[z][m][3] = *(const u32*)(q1p + 8 + 2 * tig);
        }
    }
    __syncthreads();

    float o[2][2][2][4];
#pragma unroll
    for (int z = 0; z < 2; z++)
#pragma unroll
        for (int m = 0; m < 2; m++)
#pragma unroll
            for (int d = 0; d < 2; d++)
#pragma unroll
                for (int i = 0; i < 4; i++) o[z][m][d][i] = 0.f;
    float l4[2][4] = {{0.f, 0.f, 0.f, 0.f}, {0.f, 0.f, 0.f, 0.f}};

    const u64* bF = biasF + ((size_t)head << 8) * 144;

#pragma unroll 1
    for (int ch = 0; ch < 36; ch++) {
        int kb = ch * 16;
        u64 bw[4];
#pragma unroll
        for (int r4 = 0; r4 < 4; r4++) {
            int qrow = qwb + ((r4 >> 1) << 4) + ((r4 & 1) << 3) + gid;
            bw[r4] = bF[(qrow * 36 + ch) * 4 + tig];
        }
#pragma unroll
        for (int z = 0; z < 2; z++) {
            u32 kf[2][2];
#pragma unroll
            for (int nt = 0; nt < 2; nt++) {
                const __nv_bfloat16* kr = ksmz[z] + (kb + nt * 8 + gid) * KSTRIDE + 2 * tig;
                kf[nt][0] = *(const u32*)kr;
                kf[nt][1] = *(const u32*)(kr + 8);
            }
            u32 vb[2][2];
#pragma unroll
            for (int dt = 0; dt < 2; dt++) {
                const __nv_bfloat16* vr = vsmz[z] + (dt * 8 + gid) * VSTRIDE + kb + 2 * tig;
                vb[dt][0] = *(const u32*)vr;
                vb[dt][1] = *(const u32*)(vr + 8);
            }
#pragma unroll
            for (int m = 0; m < 2; m++) {
                float c0[4] = {0.f, 0.f, 0.f, 0.f}, c1[4] = {0.f, 0.f, 0.f, 0.f};
                mma_bf16(c0, qa[z][m], kf[0], c0);
                mma_bf16(c1, qa[z][m], kf[1], c1);
                u32 bAlo = (u32)bw[m * 2],     bAhi = (u32)(bw[m * 2] >> 32);
                u32 bBlo = (u32)bw[m * 2 + 1], bBhi = (u32)(bw[m * 2 + 1] >> 32);
                float p00 = ex2f(fminf(c0[0] + __int_as_float(bAlo << 16), 80.f));
                float p01 = ex2f(fminf(c0[1] + __int_as_float((int)(bAlo & 0xffff0000u)), 80.f));
                float p02 = ex2f(fminf(c0[2] + __int_as_float(bBlo << 16), 80.f));
                float p03 = ex2f(fminf(c0[3] + __int_as_float((int)(bBlo & 0xffff0000u)), 80.f));
                float p10 = ex2f(fminf(c1[0] + __int_as_float(bAhi << 16), 80.f));
                float p11 = ex2f(fminf(c1[1] + __int_as_float((int)(bAhi & 0xffff0000u)), 80.f));
                float p12 = ex2f(fminf(c1[2] + __int_as_float(bBhi << 16), 80.f));
                float p13 = ex2f(fminf(c1[3] + __int_as_float((int)(bBhi & 0xffff0000u)), 80.f));
                l4[z][m * 2]     += (p00 + p01) + (p10 + p11);
                l4[z][m * 2 + 1] += (p02 + p03) + (p12 + p13);
                u32 pa[4];
                pa[0] = bfpack(p00, p01);
                pa[1] = bfpack(p02, p03);
                pa[2] = bfpack(p10, p11);
                pa[3] = bfpack(p12, p13);
                mma_bf16(o[z][m][0], pa, vb[0], o[z][m][0]);
                mma_bf16(o[z][m][1], pa, vb[1], o[z][m][1]);
            }
        }
    }

#pragma unroll
    for (int z = 0; z < 2; z++)
#pragma unroll
        for (int r4 = 0; r4 < 4; r4++) {
            l4[z][r4] += __shfl_xor_sync(0xffffffffu, l4[z][r4], 1);
            l4[z][r4] += __shfl_xor_sync(0xffffffffu, l4[z][r4], 2);
            l4[z][r4] = 1.f / l4[z][r4];
        }

#pragma unroll
    for (int z = 0; z < 2; z++) {
        __nv_bfloat16* out = outbase + (size_t)z * HWP * 32;
#pragma unroll
        for (int m = 0; m < 2; m++) {
            int r0 = qwb + m * 16 + gid;
            int r1 = r0 + 8;
            int px0 = ((wy << 4) + (r0 >> 4)) * 256 + (wx << 4) + (r0 & 15);
            int px1 = ((wy << 4) + (r1 >> 4)) * 256 + (wx << 4) + (r1 & 15);
            __nv_bfloat16* o0p = out + (size_t)px0 * 32 + (head << 4);
            __nv_bfloat16* o1p = out + (size_t)px1 * 32 + (head << 4);
            float i0 = l4[z][m * 2], i1 = l4[z][m * 2 + 1];
#pragma unroll
            for (int dt = 0; dt < 2; dt++) {
                *(u32*)(o0p + dt * 8 + 2 * tig) =
                    bfpack(o[z][m][dt][0] * i0, o[z][m][dt][1] * i0);
                *(u32*)(o1p + dt * 8 + 2 * tig) =
                    bfpack(o[z][m][dt][2] * i1, o[z][m][dt][3] * i1);
            }
        }
    }
}

// ---------------- K8: both OCAB tails + final sum + HWC->CHW, fused ----------------
__global__ __launch_bounds__(256) void proj_mlp_kernel(
    const __nv_bfloat16* __restrict__ attbase,
    const float* __restrict__ xhwc, const float* __restrict__ t4,
    const float* __restrict__ x_chw,
    const float* __restrict__ stats,
    const float* __restrict__ in_g, const float* __restrict__ in_b,
    const float* __restrict__ wp, const float* __restrict__ bp,
    const float* __restrict__ n2g, const float* __restrict__ n2b,
    const float* __restrict__ mw1, const float* __restrict__ mb1,
    const float* __restrict__ mw2, const float* __restrict__ mb2,
    float* __restrict__ out) {
    __shared__ u64 s_wp2[512], s_m1a[512], s_m1b[512], s_m2[1024];
    __shared__ float s_bp[32], s_mb1[64], s_mb2[32], s_g[32], s_b[32], s_A[32], s_C[32];
    __shared__ __align__(16) float s_act[8][32];
    __shared__ __align__(16) float s_h[8][64];
    __shared__ float s_o[64][33];
    int tid = threadIdx.x;
    for (int idx = tid; idx < 512; idx += 256) {
        int i2 = idx >> 5, l = idx & 31;
        s_wp2[idx] = f2pack(wp[(2 * i2) * 32 + l], wp[(2 * i2 + 1) * 32 + l]);
        s_m1a[idx] = f2pack(mw1[(2 * i2) * 64 + l], mw1[(2 * i2 + 1) * 64 + l]);
        s_m1b[idx] = f2pack(mw1[(2 * i2) * 64 + 32 + l], mw1[(2 * i2 + 1) * 64 + 32 + l]);
    }
    for (int idx = tid; idx < 1024; idx += 256) {
        int i2 = idx >> 5, l = idx & 31;
        s_m2[idx] = f2pack(mw2[(2 * i2) * 32 + l], mw2[(2 * i2 + 1) * 32 + l]);
    }
    if (tid < 32) {
        s_bp[tid] = bp[tid]; s_mb2[tid] = mb2[tid]; s_g[tid] = n2g[tid]; s_b[tid] = n2b[tid];
        float A = stats[32 + tid] * in_g[tid];
        s_A[tid] = A;
        s_C[tid] = in_b[tid] - stats[tid] * A;
    }
    if (tid < 64) s_mb1[tid] = mb1[tid];
    __syncthreads();
    int lane = tid & 31, w = tid >> 5;
    int p0blk = blockIdx.x * 64;
    int pbase = p0blk + w * PPW;

#pragma unroll 1
    for (int it = 0; it < PPW; it++) {
        int p = pbase + it;
        float xv = xhwc[p * 32 + lane];
        float fvv = t4[p * 32 + lane] * s_A[lane] + s_C[lane];
        float osum = 0.f;
#pragma unroll 1
        for (int z = 0; z < 2; z++) {
            float scv = z ? fvv : xv;
            float a = __bfloat162float(attbase[(size_t)z * HWP * 32 + p * 32 + lane]);
            s_act[w][lane] = a;
            __syncwarp();
            u64 acc = 0ULL;
#pragma unroll
            for (int i2 = 0; i2 < 16; i2++) {
                u64 x2 = *(const u64*)&s_act[w][2 * i2];
                acc = f2fma(x2, s_wp2[i2 * 32 + lane], acc);
            }
            float2 fy = f2unpack(acc);
            float y = fy.x + fy.y + s_bp[lane] + scv;

            float mean = warp_sum(y) * (1.f / 32.f);
            float dv = y - mean;
            float var = warp_sum(dv * dv) * (1.f / 32.f);
            float yn = dv * rsqrtf(var + 1e-5f) * s_g[lane] + s_b[lane];

            __syncwarp();
            s_act[w][lane] = yn;
            __syncwarp();
            u64 h0a = 0ULL, h1a = 0ULL;
#pragma unroll
            for (int i2 = 0; i2 < 16; i2++) {
                u64 x2 = *(const u64*)&s_act[w][2 * i2];
                h0a = f2fma(x2, s_m1a[i2 * 32 + lane], h0a);
                h1a = f2fma(x2, s_m1b[i2 * 32 + lane], h1a);
            }
            float2 f0 = f2unpack(h0a), f1 = f2unpack(h1a);
            float h0 = gelu_tanh(f0.x + f0.y + s_mb1[lane]);
            float h1 = gelu_tanh(f1.x + f1.y + s_mb1[lane + 32]);
            s_h[w][lane] = h0;
            s_h[w][32 + lane] = h1;
            __syncwarp();
            u64 r2 = 0ULL;
#pragma unroll
            for (int i2 = 0; i2 < 32; i2++) {
                u64 g2 = *(const u64*)&s_h[w][2 * i2];
                r2 = f2fma(g2, s_m2[i2 * 32 + lane], r2);
            }
            float2 fr = f2unpack(r2);
            osum += y + fr.x + fr.y + s_mb2[lane];
            __syncwarp();
        }
        s_o[w * PPW + it][lane] = osum;
    }
    __syncthreads();
    // epilogue: transpose + add x (CHW) + write out (CHW), coalesced
#pragma unroll
    for (int e = tid; e < 2048; e += 256) {
        int c = e >> 6, px = e & 63;
        int gp = p0blk + px;
        out[c * HWP + gp] = s_o[px][c] + x_chw[c * HWP + gp];
    }
}

// ---------------- launch ----------------
extern "C" void kernel_launch(void* const* d_in, const int* in_sizes, int n_in,
                              void* d_out, int out_size) {
    const float* x    = (const float*)d_in[0];
    const float* dep  = (const float*)d_in[1];
    const int*   rpi  = (const int*)  d_in[2];
    const float* cw1  = (const float*)d_in[3];
    const float* cb1  = (const float*)d_in[4];
    const float* cw2  = (const float*)d_in[5];
    const float* cb2  = (const float*)d_in[6];
    const float* cw3  = (const float*)d_in[7];
    const float* cb3  = (const float*)d_in[8];
    const float* cw4  = (const float*)d_in[9];
    const float* cb4  = (const float*)d_in[10];
    const float* in_g = (const float*)d_in[11];
    const float* in_b = (const float*)d_in[12];
    const float* n1g  = (const float*)d_in[13];
    const float* n1b  = (const float*)d_in[14];
    const float* wq   = (const float*)d_in[15];
    const float* bq   = (const float*)d_in[16];
    const float* wkv  = (const float*)d_in[17];
    const float* bkv  = (const float*)d_in[18];
    const float* rpb  = (const float*)d_in[19];
    const float* wp   = (const float*)d_in[20];
    const float* bp   = (const float*)d_in[21];
    const float* n2g  = (const float*)d_in[22];
    const float* n2b  = (const float*)d_in[23];
    const float* mw1  = (const float*)d_in[24];
    const float* mb1  = (const float*)d_in[25];
    const float* mw2  = (const float*)d_in[26];
    const float* mb2  = (const float*)d_in[27];
    float* out = (float*)d_out;

    void *p_xhwc, *p_t4, *p_q, *p_kv, *p_att, *p_bias, *p_stats, *p_part;
    cudaGetSymbolAddress(&p_xhwc, g_xhwc);
    cudaGetSymbolAddress(&p_t4, g_t4);
    cudaGetSymbolAddress(&p_q, g_qbf);
    cudaGetSymbolAddress(&p_kv, g_kvbf);
    cudaGetSymbolAddress(&p_att, g_attbf);
    cudaGetSymbolAddress(&p_bias, g_biasF);
    cudaGetSymbolAddress(&p_stats, g_stats);
    cudaGetSymbolAddress(&p_part, g_part);

    cudaFuncSetAttribute(attn_kernel, cudaFuncAttributeMaxDynamicSharedMemorySize, SMEM_ATTN);

    chw2hwc_kernel<<<2048, dim3(32, 8)>>>(x, (float*)p_xhwc);
    stem_fused_kernel<<<256, 256>>>(dep, cw1, cb1, cw2, cb2, cw3, cb3, cw4, cb4,
                                    (float*)p_t4);
    inorm_part_kernel<<<512, 256>>>((float*)p_t4, (float*)p_part);
    inorm_final_kernel<<<1, 256>>>((float*)p_part, (float*)p_stats);
    build_biasF_kernel<<<288, 256>>>(rpi, rpb, (u64*)p_bias);

    ln_qkv_kernel<<<HWP / (8 * PPW), 256>>>(
        (float*)p_xhwc, (float*)p_t4, (float*)p_stats, in_g, in_b, n1g, n1b,
        wq, bq, wkv, bkv, (__nv_bfloat16*)p_q, (__nv_bfloat16*)p_kv);
    attn_kernel<<<dim3(NWIN, 2), 256, SMEM_ATTN>>>((__nv_bfloat16*)p_q,
                                                   (__nv_bfloat16*)p_kv,
                                                   (u64*)p_bias,
                                                   (__nv_bfloat16*)p_att);
    proj_mlp_kernel<<<HWP / 64, 256>>>(
        (__nv_bfloat16*)p_att, (float*)p_xhwc, (float*)p_t4, x, (float*)p_stats,
        in_g, in_b, wp, bp, n2g, n2b, mw1, mb1, mw2, mb2, out);
}